// round 1
// baseline (speedup 1.0000x reference)
#include <cuda_runtime.h>
#include <math.h>

#define S     4096
#define CDIM  1280
#define HIDD  128
#define DID   1536
#define EPSV  1e-5f

// ---------------- scratch (static device globals; no allocations) ----------
__device__ float  g_zt  [(size_t)S * CDIM];   // LN'd tokens (S, C)
__device__ float  g_Q   [(size_t)S * HIDD];
__device__ float  g_Km  [(size_t)S * HIDD];
__device__ float  g_Vm  [(size_t)S * HIDD];
__device__ float  g_iv  [HIDD];
__device__ float  g_cidp[CDIM];
__device__ float  g_maskv[S];
__device__ float  g_attn[(size_t)S * S];      // 67 MB
__device__ float  g_av  [(size_t)S * HIDD];
__device__ float  g_att [(size_t)S * CDIM];   // attended -> af (in place)
__device__ double g_psum[S];
__device__ double g_psq [S];
__device__ float  g_mean_f;
__device__ float  g_rstd_f;

// ---------------- transpose z (C,S) -> zt (S,C) ----------------------------
__global__ void transpose_zt_kernel(const float* __restrict__ z, float* __restrict__ zt) {
    __shared__ float tile[32][33];
    int s0 = blockIdx.x * 32, c0 = blockIdx.y * 32;
    #pragma unroll
    for (int i = threadIdx.y; i < 32; i += 8)
        tile[i][threadIdx.x] = z[(size_t)(c0 + i) * S + s0 + threadIdx.x];
    __syncthreads();
    #pragma unroll
    for (int i = threadIdx.y; i < 32; i += 8)
        zt[(size_t)(s0 + i) * CDIM + c0 + threadIdx.x] = tile[threadIdx.x][i];
}

// ---------------- row LayerNorm over C (in place) ---------------------------
__global__ void ln_rows_kernel(float* __restrict__ x) {
    __shared__ float rs[256], rq[256];
    int row = blockIdx.x;
    float* p = x + (size_t)row * CDIM;
    float s = 0.f, q = 0.f;
    for (int i = threadIdx.x; i < CDIM; i += 256) { float v = p[i]; s += v; q += v * v; }
    rs[threadIdx.x] = s; rq[threadIdx.x] = q; __syncthreads();
    for (int o = 128; o > 0; o >>= 1) {
        if (threadIdx.x < o) { rs[threadIdx.x] += rs[threadIdx.x + o]; rq[threadIdx.x] += rq[threadIdx.x + o]; }
        __syncthreads();
    }
    float mean = rs[0] / CDIM;
    float var  = rq[0] / CDIM - mean * mean;
    float rstd = rsqrtf(var + EPSV);
    for (int i = threadIdx.x; i < CDIM; i += 256) p[i] = (p[i] - mean) * rstd;
}

// ---------------- iv = mlp(cid), cidp = proj(cid) ---------------------------
__global__ void dual_matvec_kernel(const float* __restrict__ w1, const float* __restrict__ b1,
                                   const float* __restrict__ w2, const float* __restrict__ b2,
                                   const float* __restrict__ x,
                                   float* __restrict__ o1, float* __restrict__ o2) {
    __shared__ float sm[128];
    int n = blockIdx.x;
    const float* w; float bv; float* o; int nn;
    if (n < HIDD) { nn = n;        w = w1 + (size_t)nn * DID; bv = b1[nn]; o = o1; }
    else          { nn = n - HIDD; w = w2 + (size_t)nn * DID; bv = b2[nn]; o = o2; }
    float s = 0.f;
    for (int k = threadIdx.x; k < DID; k += 128) s += w[k] * x[k];
    sm[threadIdx.x] = s; __syncthreads();
    for (int off = 64; off > 0; off >>= 1) {
        if (threadIdx.x < off) sm[threadIdx.x] += sm[threadIdx.x + off];
        __syncthreads();
    }
    if (threadIdx.x == 0) o[nn] = sm[0] + bv;
}

// ---------------- generic tiled GEMM: C = scale * A·op(B) + bias ------------
// A: (M,K) row-major. BT=true: B is (N,K) -> C[m,n]=sum A[m,k]B[n,k].
// BT=false: B is (K,N).
template <bool BT>
__global__ void gemm64_kernel(const float* __restrict__ A, const float* __restrict__ B,
                              const float* __restrict__ bias, float* __restrict__ C,
                              int M, int N, int K, float scale) {
    __shared__ float As[16][64];
    __shared__ float Bs[16][64];
    int m0 = blockIdx.y * 64, n0 = blockIdx.x * 64;
    int tid = threadIdx.x;
    int tx = tid & 15, ty = tid >> 4;
    float acc[4][4] = {};
    for (int k0 = 0; k0 < K; k0 += 16) {
        #pragma unroll
        for (int e = tid; e < 1024; e += 256) {
            int m = e >> 4, k = e & 15;
            As[k][m] = A[(size_t)(m0 + m) * K + k0 + k];
        }
        #pragma unroll
        for (int e = tid; e < 1024; e += 256) {
            if (BT) { int n = e >> 4, k = e & 15; Bs[k][n] = B[(size_t)(n0 + n) * K + k0 + k]; }
            else    { int n = e & 63, k = e >> 6; Bs[k][n] = B[(size_t)(k0 + k) * N + n0 + n]; }
        }
        __syncthreads();
        #pragma unroll
        for (int k = 0; k < 16; k++) {
            float a[4], b[4];
            #pragma unroll
            for (int i = 0; i < 4; i++) a[i] = As[k][ty * 4 + i];
            #pragma unroll
            for (int j = 0; j < 4; j++) b[j] = Bs[k][tx * 4 + j];
            #pragma unroll
            for (int i = 0; i < 4; i++)
                #pragma unroll
                for (int j = 0; j < 4; j++) acc[i][j] += a[i] * b[j];
        }
        __syncthreads();
    }
    #pragma unroll
    for (int i = 0; i < 4; i++) {
        int m = m0 + ty * 4 + i;
        #pragma unroll
        for (int j = 0; j < 4; j++) {
            int n = n0 + tx * 4 + j;
            float v = acc[i][j] * scale;
            if (bias) v += bias[n];
            C[(size_t)m * N + n] = v;
        }
    }
}

// ---------------- mask[k] = sigmoid(iv . K[k]) -------------------------------
__global__ void mask_kernel(const float* __restrict__ Kmat, const float* __restrict__ iv,
                            float* __restrict__ mask) {
    __shared__ float sm[128];
    int k = blockIdx.x;
    float v = iv[threadIdx.x] * Kmat[(size_t)k * HIDD + threadIdx.x];
    sm[threadIdx.x] = v; __syncthreads();
    for (int o = 64; o > 0; o >>= 1) {
        if (threadIdx.x < o) sm[threadIdx.x] += sm[threadIdx.x + o];
        __syncthreads();
    }
    if (threadIdx.x == 0) mask[k] = 1.f / (1.f + expf(-sm[0]));
}

// ---------------- masked row softmax (in place) ------------------------------
__global__ void softmax_kernel(float* __restrict__ attn, const float* __restrict__ mask) {
    __shared__ float red[256];
    int q = blockIdx.x;
    float* row = attn + (size_t)q * S;
    float mx = -1e30f;
    for (int k = threadIdx.x; k < S; k += 256) {
        float v = row[k] * mask[k];
        row[k] = v;
        mx = fmaxf(mx, v);
    }
    red[threadIdx.x] = mx; __syncthreads();
    for (int o = 128; o > 0; o >>= 1) {
        if (threadIdx.x < o) red[threadIdx.x] = fmaxf(red[threadIdx.x], red[threadIdx.x + o]);
        __syncthreads();
    }
    mx = red[0]; __syncthreads();
    float s = 0.f;
    for (int k = threadIdx.x; k < S; k += 256) {
        float e = expf(row[k] - mx);
        row[k] = e;
        s += e;
    }
    red[threadIdx.x] = s; __syncthreads();
    for (int o = 128; o > 0; o >>= 1) {
        if (threadIdx.x < o) red[threadIdx.x] += red[threadIdx.x + o];
        __syncthreads();
    }
    float inv = 1.f / red[0];
    for (int k = threadIdx.x; k < S; k += 256) row[k] *= inv;
}

// ---------------- decoupling epilogue + per-row partial stats ----------------
__global__ void epilogue_kernel(float* __restrict__ att, const float* __restrict__ cidp,
                                double* __restrict__ psum, double* __restrict__ psq) {
    __shared__ float red[256], red2[256];
    int s = blockIdx.x;
    float* row = att + (size_t)s * CDIM;
    float dot = 0.f;
    for (int c = threadIdx.x; c < CDIM; c += 256) dot += row[c] * cidp[c];
    red[threadIdx.x] = dot; __syncthreads();
    for (int o = 128; o > 0; o >>= 1) {
        if (threadIdx.x < o) red[threadIdx.x] += red[threadIdx.x + o];
        __syncthreads();
    }
    float w = 1.f / (1.f + expf(-red[0]));
    __syncthreads();
    float ls = 0.f, lq = 0.f;
    for (int c = threadIdx.x; c < CDIM; c += 256) {
        float v = row[c] - w * cidp[c];
        row[c] = v;
        ls += v; lq += v * v;
    }
    red[threadIdx.x] = ls; red2[threadIdx.x] = lq; __syncthreads();
    for (int o = 128; o > 0; o >>= 1) {
        if (threadIdx.x < o) { red[threadIdx.x] += red[threadIdx.x + o]; red2[threadIdx.x] += red2[threadIdx.x + o]; }
        __syncthreads();
    }
    if (threadIdx.x == 0) { psum[s] = (double)red[0]; psq[s] = (double)red2[0]; }
}

// ---------------- global LN stats (deterministic, single block) --------------
__global__ void stats_kernel(const double* __restrict__ psum, const double* __restrict__ psq) {
    __shared__ double rs[1024], rq[1024];
    double s = 0.0, q = 0.0;
    for (int i = threadIdx.x; i < S; i += 1024) { s += psum[i]; q += psq[i]; }
    rs[threadIdx.x] = s; rq[threadIdx.x] = q; __syncthreads();
    for (int o = 512; o > 0; o >>= 1) {
        if (threadIdx.x < o) { rs[threadIdx.x] += rs[threadIdx.x + o]; rq[threadIdx.x] += rq[threadIdx.x + o]; }
        __syncthreads();
    }
    if (threadIdx.x == 0) {
        double n = (double)S * (double)CDIM;
        double mean = rs[0] / n;
        double var  = rq[0] / n - mean * mean;
        g_mean_f = (float)mean;
        g_rstd_f = (float)rsqrt(var + 1e-5);
    }
}

// ---------------- normalize + transpose back (S,C) -> (C,S) ------------------
__global__ void out_transpose_kernel(const float* __restrict__ af, float* __restrict__ out) {
    __shared__ float tile[32][33];
    float mean = g_mean_f, rstd = g_rstd_f;
    int c0 = blockIdx.x * 32, s0 = blockIdx.y * 32;
    #pragma unroll
    for (int i = threadIdx.y; i < 32; i += 8)
        tile[i][threadIdx.x] = af[(size_t)(s0 + i) * CDIM + c0 + threadIdx.x];
    __syncthreads();
    #pragma unroll
    for (int i = threadIdx.y; i < 32; i += 8)
        out[(size_t)(c0 + i) * S + s0 + threadIdx.x] = (tile[threadIdx.x][i] - mean) * rstd;
}

// ---------------- launch ------------------------------------------------------
extern "C" void kernel_launch(void* const* d_in, const int* in_sizes, int n_in,
                              void* d_out, int out_size) {
    const float* z      = (const float*)d_in[0];
    const float* cid    = (const float*)d_in[1];
    const float* mlp_w  = (const float*)d_in[2];
    const float* mlp_b  = (const float*)d_in[3];
    const float* proj_w = (const float*)d_in[4];
    const float* proj_b = (const float*)d_in[5];
    const float* wq_w   = (const float*)d_in[6];
    const float* wq_b   = (const float*)d_in[7];
    const float* wk_w   = (const float*)d_in[8];
    const float* wk_b   = (const float*)d_in[9];
    const float* wv_w   = (const float*)d_in[10];
    const float* wv_b   = (const float*)d_in[11];
    const float* wo_w   = (const float*)d_in[12];
    const float* wo_b   = (const float*)d_in[13];
    float* out = (float*)d_out;

    float *zt, *Q, *Km, *Vm, *iv, *cidp, *maskv, *attn, *av, *att;
    double *psum, *psq;
    cudaGetSymbolAddress((void**)&zt,    g_zt);
    cudaGetSymbolAddress((void**)&Q,     g_Q);
    cudaGetSymbolAddress((void**)&Km,    g_Km);
    cudaGetSymbolAddress((void**)&Vm,    g_Vm);
    cudaGetSymbolAddress((void**)&iv,    g_iv);
    cudaGetSymbolAddress((void**)&cidp,  g_cidp);
    cudaGetSymbolAddress((void**)&maskv, g_maskv);
    cudaGetSymbolAddress((void**)&attn,  g_attn);
    cudaGetSymbolAddress((void**)&av,    g_av);
    cudaGetSymbolAddress((void**)&att,   g_att);
    cudaGetSymbolAddress((void**)&psum,  g_psum);
    cudaGetSymbolAddress((void**)&psq,   g_psq);

    dim3 t32x8(32, 8);

    // 1. z (C,S) -> zt (S,C)
    transpose_zt_kernel<<<dim3(S / 32, CDIM / 32), t32x8>>>(z, zt);
    // 2. per-token LayerNorm over C
    ln_rows_kernel<<<S, 256>>>(zt);
    // 3. iv = mlp(cid); cidp = proj(cid)
    dual_matvec_kernel<<<HIDD + CDIM, 128>>>(mlp_w, mlp_b, proj_w, proj_b, cid, iv, cidp);
    // 4. Q/K/V GEMMs  (S x C) x (HID x C)^T
    gemm64_kernel<true><<<dim3(HIDD / 64, S / 64), 256>>>(zt, wq_w, wq_b, Q,  S, HIDD, CDIM, 1.f);
    gemm64_kernel<true><<<dim3(HIDD / 64, S / 64), 256>>>(zt, wk_w, wk_b, Km, S, HIDD, CDIM, 1.f);
    gemm64_kernel<true><<<dim3(HIDD / 64, S / 64), 256>>>(zt, wv_w, wv_b, Vm, S, HIDD, CDIM, 1.f);
    // 5. attn = Q K^T / sqrt(S)
    gemm64_kernel<true><<<dim3(S / 64, S / 64), 256>>>(Q, Km, (const float*)nullptr, attn, S, S, HIDD, 1.f / 64.f);
    // 6. mask
    mask_kernel<<<S, 128>>>(Km, iv, maskv);
    // 7. masked softmax (in place)
    softmax_kernel<<<S, 256>>>(attn, maskv);
    // 8. av = A V
    gemm64_kernel<false><<<dim3(HIDD / 64, S / 64), 256>>>(attn, Vm, (const float*)nullptr, av, S, HIDD, S, 1.f);
    // 9. attended = av wo^T + wo_b
    gemm64_kernel<true><<<dim3(CDIM / 64, S / 64), 256>>>(av, wo_w, wo_b, att, S, CDIM, HIDD, 1.f);
    // 10. decoupling epilogue + partial stats
    epilogue_kernel<<<S, 256>>>(att, cidp, psum, psq);
    // 11. global LN stats
    stats_kernel<<<1, 1024>>>(psum, psq);
    // 12. normalize + transpose to (C,H,W)
    out_transpose_kernel<<<dim3(CDIM / 32, S / 32), t32x8>>>(att, out);
}

// round 2
// speedup vs baseline: 1.5135x; 1.5135x over previous
#include <cuda_runtime.h>
#include <math.h>

#define S     4096
#define CDIM  1280
#define HIDD  128
#define DID   1536
#define EPSV  1e-5f

// ---------------- scratch (static device globals; no allocations) ----------
__device__ float  g_zt  [(size_t)S * CDIM];   // LN'd tokens (S, C)
__device__ float  g_Q   [(size_t)S * HIDD];
__device__ float  g_Km  [(size_t)S * HIDD];
__device__ float  g_Vm  [(size_t)S * HIDD];
__device__ float  g_iv  [HIDD];
__device__ float  g_cidp[CDIM];
__device__ float  g_maskv[S];
__device__ float  g_attn[(size_t)S * S];      // 67 MB
__device__ float  g_av  [(size_t)S * HIDD];
__device__ float  g_avp [(size_t)4 * S * HIDD]; // split-K partials
__device__ float  g_att [(size_t)S * CDIM];   // attended -> af (in place)
__device__ double g_psum[S];
__device__ double g_psq [S];
__device__ float  g_mean_f;
__device__ float  g_rstd_f;

// ---------------- transpose z (C,S) -> zt (S,C) ----------------------------
__global__ void transpose_zt_kernel(const float* __restrict__ z, float* __restrict__ zt) {
    __shared__ float tile[32][33];
    int s0 = blockIdx.x * 32, c0 = blockIdx.y * 32;
    #pragma unroll
    for (int i = threadIdx.y; i < 32; i += 8)
        tile[i][threadIdx.x] = z[(size_t)(c0 + i) * S + s0 + threadIdx.x];
    __syncthreads();
    #pragma unroll
    for (int i = threadIdx.y; i < 32; i += 8)
        zt[(size_t)(s0 + i) * CDIM + c0 + threadIdx.x] = tile[threadIdx.x][i];
}

// ---------------- row LayerNorm over C (in place) ---------------------------
__global__ void ln_rows_kernel(float* __restrict__ x) {
    __shared__ float rs[256], rq[256];
    int row = blockIdx.x;
    float* p = x + (size_t)row * CDIM;
    float s = 0.f, q = 0.f;
    for (int i = threadIdx.x; i < CDIM; i += 256) { float v = p[i]; s += v; q += v * v; }
    rs[threadIdx.x] = s; rq[threadIdx.x] = q; __syncthreads();
    for (int o = 128; o > 0; o >>= 1) {
        if (threadIdx.x < o) { rs[threadIdx.x] += rs[threadIdx.x + o]; rq[threadIdx.x] += rq[threadIdx.x + o]; }
        __syncthreads();
    }
    float mean = rs[0] / CDIM;
    float var  = rq[0] / CDIM - mean * mean;
    float rstd = rsqrtf(var + EPSV);
    for (int i = threadIdx.x; i < CDIM; i += 256) p[i] = (p[i] - mean) * rstd;
}

// ---------------- iv = mlp(cid), cidp = proj(cid) ---------------------------
__global__ void dual_matvec_kernel(const float* __restrict__ w1, const float* __restrict__ b1,
                                   const float* __restrict__ w2, const float* __restrict__ b2,
                                   const float* __restrict__ x,
                                   float* __restrict__ o1, float* __restrict__ o2) {
    __shared__ float sm[128];
    int n = blockIdx.x;
    const float* w; float bv; float* o; int nn;
    if (n < HIDD) { nn = n;        w = w1 + (size_t)nn * DID; bv = b1[nn]; o = o1; }
    else          { nn = n - HIDD; w = w2 + (size_t)nn * DID; bv = b2[nn]; o = o2; }
    float s = 0.f;
    for (int k = threadIdx.x; k < DID; k += 128) s += w[k] * x[k];
    sm[threadIdx.x] = s; __syncthreads();
    for (int off = 64; off > 0; off >>= 1) {
        if (threadIdx.x < off) sm[threadIdx.x] += sm[threadIdx.x + off];
        __syncthreads();
    }
    if (threadIdx.x == 0) o[nn] = sm[0] + bv;
}

// ---------------- GEMM tile body (64x64, 16-deep k, 256 thr) ----------------
// BT=true: B is (N,K) row-major; BT=false: B is (K,N) row-major.
// Processes k in [kstart, kstart+kchunk); ldA=K (full), writes to Cblk (M,N).
template <bool BT>
__device__ __forceinline__ void gemm_tile_body(
        const float* __restrict__ A, const float* __restrict__ B,
        const float* __restrict__ bias, float* __restrict__ Cblk,
        int N, int K, float scale, int kstart, int kchunk,
        int m0, int n0) {
    __shared__ float As[16][64];
    __shared__ float Bs[16][64];
    int tid = threadIdx.x;
    int tx = tid & 15, ty = tid >> 4;
    float acc[4][4] = {};
    for (int kk = 0; kk < kchunk; kk += 16) {
        int k0 = kstart + kk;
        #pragma unroll
        for (int e = tid; e < 1024; e += 256) {
            int m = e >> 4, k = e & 15;
            As[k][m] = A[(size_t)(m0 + m) * K + k0 + k];
        }
        #pragma unroll
        for (int e = tid; e < 1024; e += 256) {
            if (BT) { int n = e >> 4, k = e & 15; Bs[k][n] = B[(size_t)(n0 + n) * K + k0 + k]; }
            else    { int n = e & 63, k = e >> 6; Bs[k][n] = B[(size_t)(k0 + k) * N + n0 + n]; }
        }
        __syncthreads();
        #pragma unroll
        for (int k = 0; k < 16; k++) {
            float a[4], b[4];
            #pragma unroll
            for (int i = 0; i < 4; i++) a[i] = As[k][ty * 4 + i];
            #pragma unroll
            for (int j = 0; j < 4; j++) b[j] = Bs[k][tx * 4 + j];
            #pragma unroll
            for (int i = 0; i < 4; i++)
                #pragma unroll
                for (int j = 0; j < 4; j++) acc[i][j] += a[i] * b[j];
        }
        __syncthreads();
    }
    #pragma unroll
    for (int i = 0; i < 4; i++) {
        int m = m0 + ty * 4 + i;
        #pragma unroll
        for (int j = 0; j < 4; j++) {
            int n = n0 + tx * 4 + j;
            float v = acc[i][j] * scale;
            if (bias) v += bias[n];
            Cblk[(size_t)m * N + n] = v;
        }
    }
}

// Fused QKV: blockIdx.z selects {Q,K,V} weight/bias/output. Grid (2, 64, 3).
__global__ void qkv_gemm_kernel(const float* __restrict__ A,
                                const float* __restrict__ wq, const float* __restrict__ bq,
                                const float* __restrict__ wk, const float* __restrict__ bk,
                                const float* __restrict__ wv, const float* __restrict__ bv,
                                float* __restrict__ Q, float* __restrict__ Km, float* __restrict__ Vm) {
    const float* B; const float* bias; float* C;
    if (blockIdx.z == 0)      { B = wq; bias = bq; C = Q;  }
    else if (blockIdx.z == 1) { B = wk; bias = bk; C = Km; }
    else                      { B = wv; bias = bv; C = Vm; }
    gemm_tile_body<true>(A, B, bias, C, HIDD, CDIM, 1.f, 0, CDIM,
                         blockIdx.y * 64, blockIdx.x * 64);
}

// Generic GEMM with optional split-K over blockIdx.z (writes per-z partials).
template <bool BT>
__global__ void gemm64s_kernel(const float* __restrict__ A, const float* __restrict__ B,
                               const float* __restrict__ bias, float* __restrict__ C,
                               int M, int N, int K, float scale, int kchunk) {
    float* Cblk = C + (size_t)blockIdx.z * M * N;
    gemm_tile_body<BT>(A, B, bias, Cblk, N, K, scale, blockIdx.z * kchunk, kchunk,
                       blockIdx.y * 64, blockIdx.x * 64);
}

// Reduce split-K partials: av = sum_z avp[z]
__global__ void reduce_av_kernel(const float* __restrict__ avp, float* __restrict__ av) {
    size_t i = ((size_t)blockIdx.x * 256 + threadIdx.x) * 4;
    const size_t MN = (size_t)S * HIDD;
    float4 a = *(const float4*)&avp[i];
    float4 b = *(const float4*)&avp[MN + i];
    float4 c = *(const float4*)&avp[2 * MN + i];
    float4 d = *(const float4*)&avp[3 * MN + i];
    float4 r;
    r.x = a.x + b.x + c.x + d.x;
    r.y = a.y + b.y + c.y + d.y;
    r.z = a.z + b.z + c.z + d.z;
    r.w = a.w + b.w + c.w + d.w;
    *(float4*)&av[i] = r;
}

// ---------------- mask[k] = sigmoid(iv . K[k]) -------------------------------
__global__ void mask_kernel(const float* __restrict__ Kmat, const float* __restrict__ iv,
                            float* __restrict__ mask) {
    __shared__ float sm[128];
    int k = blockIdx.x;
    float v = iv[threadIdx.x] * Kmat[(size_t)k * HIDD + threadIdx.x];
    sm[threadIdx.x] = v; __syncthreads();
    for (int o = 64; o > 0; o >>= 1) {
        if (threadIdx.x < o) sm[threadIdx.x] += sm[threadIdx.x + o];
        __syncthreads();
    }
    if (threadIdx.x == 0) mask[k] = 1.f / (1.f + expf(-sm[0]));
}

// ---------------- masked row softmax (in place) ------------------------------
__global__ void softmax_kernel(float* __restrict__ attn, const float* __restrict__ mask) {
    __shared__ float red[256];
    int q = blockIdx.x;
    float* row = attn + (size_t)q * S;
    float mx = -1e30f;
    for (int k = threadIdx.x; k < S; k += 256) {
        float v = row[k] * mask[k];
        row[k] = v;
        mx = fmaxf(mx, v);
    }
    red[threadIdx.x] = mx; __syncthreads();
    for (int o = 128; o > 0; o >>= 1) {
        if (threadIdx.x < o) red[threadIdx.x] = fmaxf(red[threadIdx.x], red[threadIdx.x + o]);
        __syncthreads();
    }
    mx = red[0]; __syncthreads();
    float s = 0.f;
    for (int k = threadIdx.x; k < S; k += 256) {
        float e = expf(row[k] - mx);
        row[k] = e;
        s += e;
    }
    red[threadIdx.x] = s; __syncthreads();
    for (int o = 128; o > 0; o >>= 1) {
        if (threadIdx.x < o) red[threadIdx.x] += red[threadIdx.x + o];
        __syncthreads();
    }
    float inv = 1.f / red[0];
    for (int k = threadIdx.x; k < S; k += 256) row[k] *= inv;
}

// ---------------- decoupling epilogue + per-row partial stats ----------------
__global__ void epilogue_kernel(float* __restrict__ att, const float* __restrict__ cidp,
                                double* __restrict__ psum, double* __restrict__ psq) {
    __shared__ float red[256], red2[256];
    int s = blockIdx.x;
    float* row = att + (size_t)s * CDIM;
    float dot = 0.f;
    for (int c = threadIdx.x; c < CDIM; c += 256) dot += row[c] * cidp[c];
    red[threadIdx.x] = dot; __syncthreads();
    for (int o = 128; o > 0; o >>= 1) {
        if (threadIdx.x < o) red[threadIdx.x] += red[threadIdx.x + o];
        __syncthreads();
    }
    float w = 1.f / (1.f + expf(-red[0]));
    __syncthreads();
    float ls = 0.f, lq = 0.f;
    for (int c = threadIdx.x; c < CDIM; c += 256) {
        float v = row[c] - w * cidp[c];
        row[c] = v;
        ls += v; lq += v * v;
    }
    red[threadIdx.x] = ls; red2[threadIdx.x] = lq; __syncthreads();
    for (int o = 128; o > 0; o >>= 1) {
        if (threadIdx.x < o) { red[threadIdx.x] += red[threadIdx.x + o]; red2[threadIdx.x] += red2[threadIdx.x + o]; }
        __syncthreads();
    }
    if (threadIdx.x == 0) { psum[s] = (double)red[0]; psq[s] = (double)red2[0]; }
}

// ---------------- global LN stats (deterministic, single block) --------------
__global__ void stats_kernel(const double* __restrict__ psum, const double* __restrict__ psq) {
    __shared__ double rs[1024], rq[1024];
    double s = 0.0, q = 0.0;
    for (int i = threadIdx.x; i < S; i += 1024) { s += psum[i]; q += psq[i]; }
    rs[threadIdx.x] = s; rq[threadIdx.x] = q; __syncthreads();
    for (int o = 512; o > 0; o >>= 1) {
        if (threadIdx.x < o) { rs[threadIdx.x] += rs[threadIdx.x + o]; rq[threadIdx.x] += rq[threadIdx.x + o]; }
        __syncthreads();
    }
    if (threadIdx.x == 0) {
        double n = (double)S * (double)CDIM;
        double mean = rs[0] / n;
        double var  = rq[0] / n - mean * mean;
        g_mean_f = (float)mean;
        g_rstd_f = (float)rsqrt(var + 1e-5);
    }
}

// ---------------- normalize + transpose back (S,C) -> (C,S) ------------------
__global__ void out_transpose_kernel(const float* __restrict__ af, float* __restrict__ out) {
    __shared__ float tile[32][33];
    float mean = g_mean_f, rstd = g_rstd_f;
    int c0 = blockIdx.x * 32, s0 = blockIdx.y * 32;
    #pragma unroll
    for (int i = threadIdx.y; i < 32; i += 8)
        tile[i][threadIdx.x] = af[(size_t)(s0 + i) * CDIM + c0 + threadIdx.x];
    __syncthreads();
    #pragma unroll
    for (int i = threadIdx.y; i < 32; i += 8)
        out[(size_t)(c0 + i) * S + s0 + threadIdx.x] = (tile[threadIdx.x][i] - mean) * rstd;
}

// ---------------- launch ------------------------------------------------------
extern "C" void kernel_launch(void* const* d_in, const int* in_sizes, int n_in,
                              void* d_out, int out_size) {
    const float* z      = (const float*)d_in[0];
    const float* cid    = (const float*)d_in[1];
    const float* mlp_w  = (const float*)d_in[2];
    const float* mlp_b  = (const float*)d_in[3];
    const float* proj_w = (const float*)d_in[4];
    const float* proj_b = (const float*)d_in[5];
    const float* wq_w   = (const float*)d_in[6];
    const float* wq_b   = (const float*)d_in[7];
    const float* wk_w   = (const float*)d_in[8];
    const float* wk_b   = (const float*)d_in[9];
    const float* wv_w   = (const float*)d_in[10];
    const float* wv_b   = (const float*)d_in[11];
    const float* wo_w   = (const float*)d_in[12];
    const float* wo_b   = (const float*)d_in[13];
    float* out = (float*)d_out;

    float *zt, *Q, *Km, *Vm, *iv, *cidp, *maskv, *attn, *av, *avp, *att;
    double *psum, *psq;
    cudaGetSymbolAddress((void**)&zt,    g_zt);
    cudaGetSymbolAddress((void**)&Q,     g_Q);
    cudaGetSymbolAddress((void**)&Km,    g_Km);
    cudaGetSymbolAddress((void**)&Vm,    g_Vm);
    cudaGetSymbolAddress((void**)&iv,    g_iv);
    cudaGetSymbolAddress((void**)&cidp,  g_cidp);
    cudaGetSymbolAddress((void**)&maskv, g_maskv);
    cudaGetSymbolAddress((void**)&attn,  g_attn);
    cudaGetSymbolAddress((void**)&av,    g_av);
    cudaGetSymbolAddress((void**)&avp,   g_avp);
    cudaGetSymbolAddress((void**)&att,   g_att);
    cudaGetSymbolAddress((void**)&psum,  g_psum);
    cudaGetSymbolAddress((void**)&psq,   g_psq);

    dim3 t32x8(32, 8);

    // 1. z (C,S) -> zt (S,C)
    transpose_zt_kernel<<<dim3(S / 32, CDIM / 32), t32x8>>>(z, zt);
    // 2. per-token LayerNorm over C
    ln_rows_kernel<<<S, 256>>>(zt);
    // 3. iv = mlp(cid); cidp = proj(cid)
    dual_matvec_kernel<<<HIDD + CDIM, 128>>>(mlp_w, mlp_b, proj_w, proj_b, cid, iv, cidp);
    // 4. fused Q/K/V GEMMs: one launch, grid (2,64,3) = 384 blocks
    qkv_gemm_kernel<<<dim3(HIDD / 64, S / 64, 3), 256>>>(zt, wq_w, wq_b, wk_w, wk_b, wv_w, wv_b,
                                                         Q, Km, Vm);
    // 5. attn = Q K^T / sqrt(S)   grid (64,64)
    gemm64s_kernel<true><<<dim3(S / 64, S / 64, 1), 256>>>(Q, Km, (const float*)nullptr, attn,
                                                           S, S, HIDD, 1.f / 64.f, HIDD);
    // 6. mask
    mask_kernel<<<S, 128>>>(Km, iv, maskv);
    // 7. masked softmax (in place)
    softmax_kernel<<<S, 256>>>(attn, maskv);
    // 8. av = A V  — split-K x4: grid (2,64,4) = 512 blocks -> partials
    gemm64s_kernel<false><<<dim3(HIDD / 64, S / 64, 4), 256>>>(attn, Vm, (const float*)nullptr, avp,
                                                               S, HIDD, S, 1.f, S / 4);
    reduce_av_kernel<<<(S * HIDD) / (256 * 4), 256>>>(avp, av);
    // 9. attended = av wo^T + wo_b   grid (20,64)
    gemm64s_kernel<true><<<dim3(CDIM / 64, S / 64, 1), 256>>>(av, wo_w, wo_b, att,
                                                              S, CDIM, HIDD, 1.f, HIDD);
    // 10. decoupling epilogue + partial stats
    epilogue_kernel<<<S, 256>>>(att, cidp, psum, psq);
    // 11. global LN stats
    stats_kernel<<<1, 1024>>>(psum, psq);
    // 12. normalize + transpose to (C,H,W)
    out_transpose_kernel<<<dim3(CDIM / 32, S / 32), t32x8>>>(att, out);
}

// round 3
// speedup vs baseline: 2.6160x; 1.7285x over previous
#include <cuda_runtime.h>
#include <math.h>

#define S     4096
#define CDIM  1280
#define HIDD  128
#define DID   1536
#define EPSV  1e-5f

// ---------------- scratch (static device globals; no allocations) ----------
__device__ float  g_zt  [(size_t)S * CDIM];   // LN'd tokens (S, C)
__device__ float  g_Q   [(size_t)S * HIDD];
__device__ float  g_Km  [(size_t)S * HIDD];
__device__ float  g_Vm  [(size_t)S * HIDD];
__device__ float  g_iv  [HIDD];
__device__ float  g_cidp[CDIM];
__device__ float  g_maskv[S];
__device__ float  g_attn[(size_t)S * S];      // 67 MB
__device__ float  g_av  [(size_t)S * HIDD];
__device__ float  g_avp [(size_t)4 * S * HIDD]; // split-K partials
__device__ float  g_att [(size_t)S * CDIM];   // attended -> af (in place)
__device__ double g_psum[S];
__device__ double g_psq [S];
__device__ float  g_mean_f;
__device__ float  g_rstd_f;

// ---------------- transpose z (C,S) -> zt (S,C) ----------------------------
__global__ void transpose_zt_kernel(const float* __restrict__ z, float* __restrict__ zt) {
    __shared__ float tile[32][33];
    int s0 = blockIdx.x * 32, c0 = blockIdx.y * 32;
    #pragma unroll
    for (int i = threadIdx.y; i < 32; i += 8)
        tile[i][threadIdx.x] = z[(size_t)(c0 + i) * S + s0 + threadIdx.x];
    __syncthreads();
    #pragma unroll
    for (int i = threadIdx.y; i < 32; i += 8)
        zt[(size_t)(s0 + i) * CDIM + c0 + threadIdx.x] = tile[threadIdx.x][i];
}

// ---------------- row LayerNorm over C (in place) ---------------------------
__global__ void ln_rows_kernel(float* __restrict__ x) {
    __shared__ float rs[256], rq[256];
    int row = blockIdx.x;
    float4* p = (float4*)(x + (size_t)row * CDIM);
    float s = 0.f, q = 0.f;
    for (int i = threadIdx.x; i < CDIM / 4; i += 256) {
        float4 v = p[i];
        s += v.x + v.y + v.z + v.w;
        q += v.x * v.x + v.y * v.y + v.z * v.z + v.w * v.w;
    }
    rs[threadIdx.x] = s; rq[threadIdx.x] = q; __syncthreads();
    for (int o = 128; o > 0; o >>= 1) {
        if (threadIdx.x < o) { rs[threadIdx.x] += rs[threadIdx.x + o]; rq[threadIdx.x] += rq[threadIdx.x + o]; }
        __syncthreads();
    }
    float mean = rs[0] / CDIM;
    float var  = rq[0] / CDIM - mean * mean;
    float rstd = rsqrtf(var + EPSV);
    for (int i = threadIdx.x; i < CDIM / 4; i += 256) {
        float4 v = p[i];
        v.x = (v.x - mean) * rstd; v.y = (v.y - mean) * rstd;
        v.z = (v.z - mean) * rstd; v.w = (v.w - mean) * rstd;
        p[i] = v;
    }
}

// ---------------- iv = mlp(cid), cidp = proj(cid) ---------------------------
__global__ void dual_matvec_kernel(const float* __restrict__ w1, const float* __restrict__ b1,
                                   const float* __restrict__ w2, const float* __restrict__ b2,
                                   const float* __restrict__ x,
                                   float* __restrict__ o1, float* __restrict__ o2) {
    __shared__ float sm[128];
    int n = blockIdx.x;
    const float* w; float bv; float* o; int nn;
    if (n < HIDD) { nn = n;        w = w1 + (size_t)nn * DID; bv = b1[nn]; o = o1; }
    else          { nn = n - HIDD; w = w2 + (size_t)nn * DID; bv = b2[nn]; o = o2; }
    float s = 0.f;
    for (int k = threadIdx.x; k < DID; k += 128) s += w[k] * x[k];
    sm[threadIdx.x] = s; __syncthreads();
    for (int off = 64; off > 0; off >>= 1) {
        if (threadIdx.x < off) sm[threadIdx.x] += sm[threadIdx.x + off];
        __syncthreads();
    }
    if (threadIdx.x == 0) o[nn] = sm[0] + bv;
}

// ---------------- GEMM body: 128x64 tile, 256 thr, 8x4/thread, k-tile 16,
//                  double-buffered smem with register prefetch ----------------
// BT=true: B is (N,K) row-major; BT=false: B is (K,N) row-major.
template <bool BT>
__device__ __forceinline__ void gemm128_body(
        const float* __restrict__ A, const float* __restrict__ B,
        const float* __restrict__ bias, float* __restrict__ C,
        int N, int K, float scale, int kstart, int kchunk,
        int m0, int n0) {
    __shared__ float As[2][16][132];
    __shared__ float Bs[2][16][68];
    const int tid = threadIdx.x;
    const int tx = tid & 15;      // n quad index
    const int ty = tid >> 4;      // m octet index

    const int ar0 = tid >> 2;     // 0..63
    const int ar1 = ar0 + 64;     // 64..127
    const int ak  = (tid & 3) * 4;
    const int bk  = tid >> 4;     // !BT: k row 0..15
    const int bn  = (tid & 15) * 4;

    float4 ra0, ra1, rb;
    float acc[8][4] = {};

    const int nt = kchunk / 16;

    // prologue: load tile 0
    {
        const int k0 = kstart;
        ra0 = *(const float4*)&A[(size_t)(m0 + ar0) * K + k0 + ak];
        ra1 = *(const float4*)&A[(size_t)(m0 + ar1) * K + k0 + ak];
        if (BT) rb = *(const float4*)&B[(size_t)(n0 + ar0) * K + k0 + ak];
        else    rb = *(const float4*)&B[(size_t)(k0 + bk) * N + n0 + bn];
    }
    // store tile 0 -> buf 0
    {
        As[0][ak + 0][ar0] = ra0.x; As[0][ak + 1][ar0] = ra0.y;
        As[0][ak + 2][ar0] = ra0.z; As[0][ak + 3][ar0] = ra0.w;
        As[0][ak + 0][ar1] = ra1.x; As[0][ak + 1][ar1] = ra1.y;
        As[0][ak + 2][ar1] = ra1.z; As[0][ak + 3][ar1] = ra1.w;
        if (BT) {
            Bs[0][ak + 0][ar0] = rb.x; Bs[0][ak + 1][ar0] = rb.y;
            Bs[0][ak + 2][ar0] = rb.z; Bs[0][ak + 3][ar0] = rb.w;
        } else {
            *(float4*)&Bs[0][bk][bn] = rb;
        }
    }
    __syncthreads();

    for (int t = 0; t < nt; t++) {
        const int cur = t & 1;
        if (t + 1 < nt) {
            const int k0 = kstart + (t + 1) * 16;
            ra0 = *(const float4*)&A[(size_t)(m0 + ar0) * K + k0 + ak];
            ra1 = *(const float4*)&A[(size_t)(m0 + ar1) * K + k0 + ak];
            if (BT) rb = *(const float4*)&B[(size_t)(n0 + ar0) * K + k0 + ak];
            else    rb = *(const float4*)&B[(size_t)(k0 + bk) * N + n0 + bn];
        }
        #pragma unroll
        for (int k = 0; k < 16; k++) {
            float4 a0 = *(const float4*)&As[cur][k][ty * 8];
            float4 a1 = *(const float4*)&As[cur][k][ty * 8 + 4];
            float4 b  = *(const float4*)&Bs[cur][k][tx * 4];
            float av[8] = {a0.x, a0.y, a0.z, a0.w, a1.x, a1.y, a1.z, a1.w};
            float bv[4] = {b.x, b.y, b.z, b.w};
            #pragma unroll
            for (int i = 0; i < 8; i++)
                #pragma unroll
                for (int j = 0; j < 4; j++)
                    acc[i][j] += av[i] * bv[j];
        }
        if (t + 1 < nt) {
            const int nb = cur ^ 1;
            As[nb][ak + 0][ar0] = ra0.x; As[nb][ak + 1][ar0] = ra0.y;
            As[nb][ak + 2][ar0] = ra0.z; As[nb][ak + 3][ar0] = ra0.w;
            As[nb][ak + 0][ar1] = ra1.x; As[nb][ak + 1][ar1] = ra1.y;
            As[nb][ak + 2][ar1] = ra1.z; As[nb][ak + 3][ar1] = ra1.w;
            if (BT) {
                Bs[nb][ak + 0][ar0] = rb.x; Bs[nb][ak + 1][ar0] = rb.y;
                Bs[nb][ak + 2][ar0] = rb.z; Bs[nb][ak + 3][ar0] = rb.w;
            } else {
                *(float4*)&Bs[nb][bk][bn] = rb;
            }
            __syncthreads();
        }
    }

    // epilogue: vectorized stores
    #pragma unroll
    for (int i = 0; i < 8; i++) {
        const int m = m0 + ty * 8 + i;
        float4 v;
        v.x = acc[i][0] * scale; v.y = acc[i][1] * scale;
        v.z = acc[i][2] * scale; v.w = acc[i][3] * scale;
        if (bias) {
            const float4 bb = *(const float4*)&bias[n0 + tx * 4];
            v.x += bb.x; v.y += bb.y; v.z += bb.z; v.w += bb.w;
        }
        *(float4*)&C[(size_t)m * N + n0 + tx * 4] = v;
    }
}

// Fused QKV: blockIdx.z selects {Q,K,V}. Grid (2, 32, 3).
__global__ __launch_bounds__(256)
void qkv_gemm_kernel(const float* __restrict__ A,
                     const float* __restrict__ wq, const float* __restrict__ bq,
                     const float* __restrict__ wk, const float* __restrict__ bk,
                     const float* __restrict__ wv, const float* __restrict__ bv,
                     float* __restrict__ Q, float* __restrict__ Km, float* __restrict__ Vm) {
    const float* B; const float* bias; float* C;
    if (blockIdx.z == 0)      { B = wq; bias = bq; C = Q;  }
    else if (blockIdx.z == 1) { B = wk; bias = bk; C = Km; }
    else                      { B = wv; bias = bv; C = Vm; }
    gemm128_body<true>(A, B, bias, C, HIDD, CDIM, 1.f, 0, CDIM,
                       blockIdx.y * 128, blockIdx.x * 64);
}

// Generic GEMM with optional split-K over blockIdx.z (per-z partial outputs).
template <bool BT>
__global__ __launch_bounds__(256)
void gemm128s_kernel(const float* __restrict__ A, const float* __restrict__ B,
                     const float* __restrict__ bias, float* __restrict__ C,
                     int M, int N, int K, float scale, int kchunk) {
    float* Cblk = C + (size_t)blockIdx.z * M * N;
    gemm128_body<BT>(A, B, bias, Cblk, N, K, scale, blockIdx.z * kchunk, kchunk,
                     blockIdx.y * 128, blockIdx.x * 64);
}

// Reduce split-K partials: av = sum_z avp[z]
__global__ void reduce_av_kernel(const float* __restrict__ avp, float* __restrict__ av) {
    size_t i = ((size_t)blockIdx.x * 256 + threadIdx.x) * 4;
    const size_t MN = (size_t)S * HIDD;
    float4 a = *(const float4*)&avp[i];
    float4 b = *(const float4*)&avp[MN + i];
    float4 c = *(const float4*)&avp[2 * MN + i];
    float4 d = *(const float4*)&avp[3 * MN + i];
    float4 r;
    r.x = a.x + b.x + c.x + d.x;
    r.y = a.y + b.y + c.y + d.y;
    r.z = a.z + b.z + c.z + d.z;
    r.w = a.w + b.w + c.w + d.w;
    *(float4*)&av[i] = r;
}

// ---------------- mask[k] = sigmoid(iv . K[k]) -------------------------------
__global__ void mask_kernel(const float* __restrict__ Kmat, const float* __restrict__ iv,
                            float* __restrict__ mask) {
    __shared__ float sm[128];
    int k = blockIdx.x;
    float v = iv[threadIdx.x] * Kmat[(size_t)k * HIDD + threadIdx.x];
    sm[threadIdx.x] = v; __syncthreads();
    for (int o = 64; o > 0; o >>= 1) {
        if (threadIdx.x < o) sm[threadIdx.x] += sm[threadIdx.x + o];
        __syncthreads();
    }
    if (threadIdx.x == 0) mask[k] = 1.f / (1.f + expf(-sm[0]));
}

// ---------------- masked row softmax (in place, float4) ----------------------
__global__ void softmax_kernel(float* __restrict__ attn, const float* __restrict__ mask) {
    __shared__ float red[256];
    int q = blockIdx.x;
    float4* row = (float4*)(attn + (size_t)q * S);
    const float4* m4 = (const float4*)mask;
    float mx = -1e30f;
    for (int k = threadIdx.x; k < S / 4; k += 256) {
        float4 v = row[k], mm = m4[k];
        v.x *= mm.x; v.y *= mm.y; v.z *= mm.z; v.w *= mm.w;
        row[k] = v;
        mx = fmaxf(mx, fmaxf(fmaxf(v.x, v.y), fmaxf(v.z, v.w)));
    }
    red[threadIdx.x] = mx; __syncthreads();
    for (int o = 128; o > 0; o >>= 1) {
        if (threadIdx.x < o) red[threadIdx.x] = fmaxf(red[threadIdx.x], red[threadIdx.x + o]);
        __syncthreads();
    }
    mx = red[0]; __syncthreads();
    float s = 0.f;
    for (int k = threadIdx.x; k < S / 4; k += 256) {
        float4 v = row[k];
        v.x = expf(v.x - mx); v.y = expf(v.y - mx);
        v.z = expf(v.z - mx); v.w = expf(v.w - mx);
        row[k] = v;
        s += v.x + v.y + v.z + v.w;
    }
    red[threadIdx.x] = s; __syncthreads();
    for (int o = 128; o > 0; o >>= 1) {
        if (threadIdx.x < o) red[threadIdx.x] += red[threadIdx.x + o];
        __syncthreads();
    }
    float inv = 1.f / red[0];
    for (int k = threadIdx.x; k < S / 4; k += 256) {
        float4 v = row[k];
        v.x *= inv; v.y *= inv; v.z *= inv; v.w *= inv;
        row[k] = v;
    }
}

// ---------------- decoupling epilogue + per-row partial stats ----------------
__global__ void epilogue_kernel(float* __restrict__ att, const float* __restrict__ cidp,
                                double* __restrict__ psum, double* __restrict__ psq) {
    __shared__ float red[256], red2[256];
    int s = blockIdx.x;
    float* row = att + (size_t)s * CDIM;
    float dot = 0.f;
    for (int c = threadIdx.x; c < CDIM; c += 256) dot += row[c] * cidp[c];
    red[threadIdx.x] = dot; __syncthreads();
    for (int o = 128; o > 0; o >>= 1) {
        if (threadIdx.x < o) red[threadIdx.x] += red[threadIdx.x + o];
        __syncthreads();
    }
    float w = 1.f / (1.f + expf(-red[0]));
    __syncthreads();
    float ls = 0.f, lq = 0.f;
    for (int c = threadIdx.x; c < CDIM; c += 256) {
        float v = row[c] - w * cidp[c];
        row[c] = v;
        ls += v; lq += v * v;
    }
    red[threadIdx.x] = ls; red2[threadIdx.x] = lq; __syncthreads();
    for (int o = 128; o > 0; o >>= 1) {
        if (threadIdx.x < o) { red[threadIdx.x] += red[threadIdx.x + o]; red2[threadIdx.x] += red2[threadIdx.x + o]; }
        __syncthreads();
    }
    if (threadIdx.x == 0) { psum[s] = (double)red[0]; psq[s] = (double)red2[0]; }
}

// ---------------- global LN stats (deterministic, single block) --------------
__global__ void stats_kernel(const double* __restrict__ psum, const double* __restrict__ psq) {
    __shared__ double rs[1024], rq[1024];
    double s = 0.0, q = 0.0;
    for (int i = threadIdx.x; i < S; i += 1024) { s += psum[i]; q += psq[i]; }
    rs[threadIdx.x] = s; rq[threadIdx.x] = q; __syncthreads();
    for (int o = 512; o > 0; o >>= 1) {
        if (threadIdx.x < o) { rs[threadIdx.x] += rs[threadIdx.x + o]; rq[threadIdx.x] += rq[threadIdx.x + o]; }
        __syncthreads();
    }
    if (threadIdx.x == 0) {
        double n = (double)S * (double)CDIM;
        double mean = rs[0] / n;
        double var  = rq[0] / n - mean * mean;
        g_mean_f = (float)mean;
        g_rstd_f = (float)rsqrt(var + 1e-5);
    }
}

// ---------------- normalize + transpose back (S,C) -> (C,S) ------------------
__global__ void out_transpose_kernel(const float* __restrict__ af, float* __restrict__ out) {
    __shared__ float tile[32][33];
    float mean = g_mean_f, rstd = g_rstd_f;
    int c0 = blockIdx.x * 32, s0 = blockIdx.y * 32;
    #pragma unroll
    for (int i = threadIdx.y; i < 32; i += 8)
        tile[i][threadIdx.x] = af[(size_t)(s0 + i) * CDIM + c0 + threadIdx.x];
    __syncthreads();
    #pragma unroll
    for (int i = threadIdx.y; i < 32; i += 8)
        out[(size_t)(c0 + i) * S + s0 + threadIdx.x] = (tile[threadIdx.x][i] - mean) * rstd;
}

// ---------------- launch ------------------------------------------------------
extern "C" void kernel_launch(void* const* d_in, const int* in_sizes, int n_in,
                              void* d_out, int out_size) {
    const float* z      = (const float*)d_in[0];
    const float* cid    = (const float*)d_in[1];
    const float* mlp_w  = (const float*)d_in[2];
    const float* mlp_b  = (const float*)d_in[3];
    const float* proj_w = (const float*)d_in[4];
    const float* proj_b = (const float*)d_in[5];
    const float* wq_w   = (const float*)d_in[6];
    const float* wq_b   = (const float*)d_in[7];
    const float* wk_w   = (const float*)d_in[8];
    const float* wk_b   = (const float*)d_in[9];
    const float* wv_w   = (const float*)d_in[10];
    const float* wv_b   = (const float*)d_in[11];
    const float* wo_w   = (const float*)d_in[12];
    const float* wo_b   = (const float*)d_in[13];
    float* out = (float*)d_out;

    float *zt, *Q, *Km, *Vm, *iv, *cidp, *maskv, *attn, *av, *avp, *att;
    double *psum, *psq;
    cudaGetSymbolAddress((void**)&zt,    g_zt);
    cudaGetSymbolAddress((void**)&Q,     g_Q);
    cudaGetSymbolAddress((void**)&Km,    g_Km);
    cudaGetSymbolAddress((void**)&Vm,    g_Vm);
    cudaGetSymbolAddress((void**)&iv,    g_iv);
    cudaGetSymbolAddress((void**)&cidp,  g_cidp);
    cudaGetSymbolAddress((void**)&maskv, g_maskv);
    cudaGetSymbolAddress((void**)&attn,  g_attn);
    cudaGetSymbolAddress((void**)&av,    g_av);
    cudaGetSymbolAddress((void**)&avp,   g_avp);
    cudaGetSymbolAddress((void**)&att,   g_att);
    cudaGetSymbolAddress((void**)&psum,  g_psum);
    cudaGetSymbolAddress((void**)&psq,   g_psq);

    dim3 t32x8(32, 8);

    // 1. z (C,S) -> zt (S,C)
    transpose_zt_kernel<<<dim3(S / 32, CDIM / 32), t32x8>>>(z, zt);
    // 2. per-token LayerNorm over C
    ln_rows_kernel<<<S, 256>>>(zt);
    // 3. iv = mlp(cid); cidp = proj(cid)
    dual_matvec_kernel<<<HIDD + CDIM, 128>>>(mlp_w, mlp_b, proj_w, proj_b, cid, iv, cidp);
    // 4. fused Q/K/V GEMMs: grid (2,32,3) = 192 blocks
    qkv_gemm_kernel<<<dim3(HIDD / 64, S / 128, 3), 256>>>(zt, wq_w, wq_b, wk_w, wk_b, wv_w, wv_b,
                                                          Q, Km, Vm);
    // 5. attn = Q K^T / sqrt(S)   grid (64,32) = 2048 blocks
    gemm128s_kernel<true><<<dim3(S / 64, S / 128, 1), 256>>>(Q, Km, (const float*)nullptr, attn,
                                                             S, S, HIDD, 1.f / 64.f, HIDD);
    // 6. mask
    mask_kernel<<<S, 128>>>(Km, iv, maskv);
    // 7. masked softmax (in place)
    softmax_kernel<<<S, 256>>>(attn, maskv);
    // 8. av = A V  — split-K x4: grid (2,32,4) = 256 blocks -> partials
    gemm128s_kernel<false><<<dim3(HIDD / 64, S / 128, 4), 256>>>(attn, Vm, (const float*)nullptr, avp,
                                                                 S, HIDD, S, 1.f, S / 4);
    reduce_av_kernel<<<(S * HIDD) / (256 * 4), 256>>>(avp, av);
    // 9. attended = av wo^T + wo_b   grid (20,32) = 640 blocks
    gemm128s_kernel<true><<<dim3(CDIM / 64, S / 128, 1), 256>>>(av, wo_w, wo_b, att,
                                                                S, CDIM, HIDD, 1.f, HIDD);
    // 10. decoupling epilogue + partial stats
    epilogue_kernel<<<S, 256>>>(att, cidp, psum, psq);
    // 11. global LN stats
    stats_kernel<<<1, 1024>>>(psum, psq);
    // 12. normalize + transpose to (C,H,W)
    out_transpose_kernel<<<dim3(CDIM / 32, S / 32), t32x8>>>(att, out);
}

// round 4
// speedup vs baseline: 3.9037x; 1.4922x over previous
#include <cuda_runtime.h>
#include <math.h>
#include <stdint.h>

#define S     4096
#define CDIM  1280
#define HIDD  128
#define DID   1536
#define EPSV  1e-5f

// ---------------- scratch (static device globals; no allocations) ----------
__device__ float  g_zt  [(size_t)S * CDIM];
__device__ float  g_Q   [(size_t)S * HIDD];
__device__ float  g_Km  [(size_t)S * HIDD];
__device__ float  g_Vm  [(size_t)S * HIDD];
__device__ float  g_iv  [HIDD];
__device__ float  g_cidp[CDIM];
__device__ float  g_maskv[S];
__device__ float  g_attn[(size_t)S * S];            // 67 MB
__device__ float  g_qkvp[(size_t)12 * S * HIDD];    // QKV split-K partials
__device__ float  g_avp [(size_t)8 * S * HIDD];     // AV split-K partials
__device__ float  g_av  [(size_t)S * HIDD];
__device__ float  g_att [(size_t)S * CDIM];
__device__ double g_psum[S];
__device__ double g_psq [S];
__device__ float  g_mean_f;
__device__ float  g_rstd_f;

// ---------------- helpers ----------------------------------------------------
__device__ __forceinline__ float to_tf32(float x) {
    float r;
    asm("cvt.rna.tf32.f32 %0, %1;" : "=f"(r) : "f"(x));
    return r;
}

__device__ __forceinline__ void mma_tf32(float* d, const float* a, const float* b) {
    asm volatile(
        "mma.sync.aligned.m16n8k8.row.col.f32.tf32.tf32.f32 "
        "{%0,%1,%2,%3}, {%4,%5,%6,%7}, {%8,%9}, {%0,%1,%2,%3};"
        : "+f"(d[0]), "+f"(d[1]), "+f"(d[2]), "+f"(d[3])
        : "r"(__float_as_uint(a[0])), "r"(__float_as_uint(a[1])),
          "r"(__float_as_uint(a[2])), "r"(__float_as_uint(a[3])),
          "r"(__float_as_uint(b[0])), "r"(__float_as_uint(b[1])));
}

// ---------------- transpose z (C,S) -> zt (S,C) ----------------------------
__global__ void transpose_zt_kernel(const float* __restrict__ z, float* __restrict__ zt) {
    __shared__ float tile[32][33];
    int s0 = blockIdx.x * 32, c0 = blockIdx.y * 32;
    #pragma unroll
    for (int i = threadIdx.y; i < 32; i += 8)
        tile[i][threadIdx.x] = z[(size_t)(c0 + i) * S + s0 + threadIdx.x];
    __syncthreads();
    #pragma unroll
    for (int i = threadIdx.y; i < 32; i += 8)
        zt[(size_t)(s0 + i) * CDIM + c0 + threadIdx.x] = tile[threadIdx.x][i];
}

// ---------------- row LayerNorm over C (in place) ---------------------------
__global__ void ln_rows_kernel(float* __restrict__ x) {
    __shared__ float rs[256], rq[256];
    int row = blockIdx.x;
    float4* p = (float4*)(x + (size_t)row * CDIM);
    float s = 0.f, q = 0.f;
    for (int i = threadIdx.x; i < CDIM / 4; i += 256) {
        float4 v = p[i];
        s += v.x + v.y + v.z + v.w;
        q += v.x * v.x + v.y * v.y + v.z * v.z + v.w * v.w;
    }
    rs[threadIdx.x] = s; rq[threadIdx.x] = q; __syncthreads();
    for (int o = 128; o > 0; o >>= 1) {
        if (threadIdx.x < o) { rs[threadIdx.x] += rs[threadIdx.x + o]; rq[threadIdx.x] += rq[threadIdx.x + o]; }
        __syncthreads();
    }
    float mean = rs[0] / CDIM;
    float var  = rq[0] / CDIM - mean * mean;
    float rstd = rsqrtf(var + EPSV);
    for (int i = threadIdx.x; i < CDIM / 4; i += 256) {
        float4 v = p[i];
        v.x = (v.x - mean) * rstd; v.y = (v.y - mean) * rstd;
        v.z = (v.z - mean) * rstd; v.w = (v.w - mean) * rstd;
        p[i] = v;
    }
}

// ---------------- iv = mlp(cid), cidp = proj(cid) ---------------------------
__global__ void dual_matvec_kernel(const float* __restrict__ w1, const float* __restrict__ b1,
                                   const float* __restrict__ w2, const float* __restrict__ b2,
                                   const float* __restrict__ x,
                                   float* __restrict__ o1, float* __restrict__ o2) {
    __shared__ float sm[128];
    int n = blockIdx.x;
    const float* w; float bv; float* o; int nn;
    if (n < HIDD) { nn = n;        w = w1 + (size_t)nn * DID; bv = b1[nn]; o = o1; }
    else          { nn = n - HIDD; w = w2 + (size_t)nn * DID; bv = b2[nn]; o = o2; }
    float s = 0.f;
    for (int k = threadIdx.x; k < DID; k += 128) s += w[k] * x[k];
    sm[threadIdx.x] = s; __syncthreads();
    for (int off = 64; off > 0; off >>= 1) {
        if (threadIdx.x < off) sm[threadIdx.x] += sm[threadIdx.x + off];
        __syncthreads();
    }
    if (threadIdx.x == 0) o[nn] = sm[0] + bv;
}

// ---------------- tf32 mma GEMM body: 128x128 tile, 256 thr, 8 warps --------
// A: (M,K) row-major. BT=true: B (N,K); BT=false: B (K,N).
// Processes nkt k-tiles of 16 starting at kstart. Output tile (m0,n0) into C (ld N).
// colmul: optional per-column multiplier applied in epilogue (after scale, before bias).
template <bool BT>
__device__ __forceinline__ void mma_gemm_body(
        const float* __restrict__ A, const float* __restrict__ B,
        const float* __restrict__ bias, const float* __restrict__ colmul,
        float* __restrict__ C,
        int N, int K, float scale, int kstart, int nkt, int m0, int n0) {
    __shared__ float As[2][16][136];   // [k][m], bank-spread pad
    __shared__ float Bs[2][16][136];   // [k][n]

    const int tid  = threadIdx.x;
    const int lane = tid & 31, wid = tid >> 5;
    const int g    = lane >> 2, tig = lane & 3;
    const int wm   = (wid >> 2) * 64;   // warp m offset (0/64)
    const int wn   = (wid & 3) * 32;    // warp n offset (0/32/64/96)

    // global-load indexing
    const int am = tid & 127;          // row (m or n for BT)
    const int ac = (tid >> 7) * 4;     // k col base: 0 or 4 (second float4 at +8)
    const int bk = tid >> 4;           // !BT: k row 0..15
    const int bc = (tid & 15) * 8;     // !BT: n col base

    float4 rA0, rA1, rB0, rB1;
    float acc[4][4][4] = {};

    // prologue load tile 0
    {
        const int k0 = kstart;
        const float* ap = A + (size_t)(m0 + am) * K + k0;
        rA0 = *(const float4*)(ap + ac);
        rA1 = *(const float4*)(ap + ac + 8);
        if (BT) {
            const float* bp = B + (size_t)(n0 + am) * K + k0;
            rB0 = *(const float4*)(bp + ac);
            rB1 = *(const float4*)(bp + ac + 8);
        } else {
            const float* bp = B + (size_t)(k0 + bk) * N + n0 + bc;
            rB0 = *(const float4*)(bp);
            rB1 = *(const float4*)(bp + 4);
        }
    }
    // store tile 0
    {
        As[0][ac + 0][am] = to_tf32(rA0.x); As[0][ac + 1][am] = to_tf32(rA0.y);
        As[0][ac + 2][am] = to_tf32(rA0.z); As[0][ac + 3][am] = to_tf32(rA0.w);
        As[0][ac + 8][am] = to_tf32(rA1.x); As[0][ac + 9][am] = to_tf32(rA1.y);
        As[0][ac +10][am] = to_tf32(rA1.z); As[0][ac +11][am] = to_tf32(rA1.w);
        if (BT) {
            Bs[0][ac + 0][am] = to_tf32(rB0.x); Bs[0][ac + 1][am] = to_tf32(rB0.y);
            Bs[0][ac + 2][am] = to_tf32(rB0.z); Bs[0][ac + 3][am] = to_tf32(rB0.w);
            Bs[0][ac + 8][am] = to_tf32(rB1.x); Bs[0][ac + 9][am] = to_tf32(rB1.y);
            Bs[0][ac +10][am] = to_tf32(rB1.z); Bs[0][ac +11][am] = to_tf32(rB1.w);
        } else {
            float4 t0, t1;
            t0.x = to_tf32(rB0.x); t0.y = to_tf32(rB0.y); t0.z = to_tf32(rB0.z); t0.w = to_tf32(rB0.w);
            t1.x = to_tf32(rB1.x); t1.y = to_tf32(rB1.y); t1.z = to_tf32(rB1.z); t1.w = to_tf32(rB1.w);
            *(float4*)&Bs[0][bk][bc]     = t0;
            *(float4*)&Bs[0][bk][bc + 4] = t1;
        }
    }
    __syncthreads();

    for (int t = 0; t < nkt; t++) {
        const int cur = t & 1;
        if (t + 1 < nkt) {
            const int k0 = kstart + (t + 1) * 16;
            const float* ap = A + (size_t)(m0 + am) * K + k0;
            rA0 = *(const float4*)(ap + ac);
            rA1 = *(const float4*)(ap + ac + 8);
            if (BT) {
                const float* bp = B + (size_t)(n0 + am) * K + k0;
                rB0 = *(const float4*)(bp + ac);
                rB1 = *(const float4*)(bp + ac + 8);
            } else {
                const float* bp = B + (size_t)(k0 + bk) * N + n0 + bc;
                rB0 = *(const float4*)(bp);
                rB1 = *(const float4*)(bp + 4);
            }
        }
        #pragma unroll
        for (int ks = 0; ks < 2; ks++) {
            const int kk = ks * 8;
            float a[4][4], b[4][2];
            #pragma unroll
            for (int mf = 0; mf < 4; mf++) {
                a[mf][0] = As[cur][kk + tig    ][wm + mf * 16 + g];
                a[mf][1] = As[cur][kk + tig    ][wm + mf * 16 + g + 8];
                a[mf][2] = As[cur][kk + tig + 4][wm + mf * 16 + g];
                a[mf][3] = As[cur][kk + tig + 4][wm + mf * 16 + g + 8];
            }
            #pragma unroll
            for (int nf = 0; nf < 4; nf++) {
                b[nf][0] = Bs[cur][kk + tig    ][wn + nf * 8 + g];
                b[nf][1] = Bs[cur][kk + tig + 4][wn + nf * 8 + g];
            }
            #pragma unroll
            for (int mf = 0; mf < 4; mf++)
                #pragma unroll
                for (int nf = 0; nf < 4; nf++)
                    mma_tf32(acc[mf][nf], a[mf], b[nf]);
        }
        if (t + 1 < nkt) {
            const int nb = cur ^ 1;
            __syncthreads();
            As[nb][ac + 0][am] = to_tf32(rA0.x); As[nb][ac + 1][am] = to_tf32(rA0.y);
            As[nb][ac + 2][am] = to_tf32(rA0.z); As[nb][ac + 3][am] = to_tf32(rA0.w);
            As[nb][ac + 8][am] = to_tf32(rA1.x); As[nb][ac + 9][am] = to_tf32(rA1.y);
            As[nb][ac +10][am] = to_tf32(rA1.z); As[nb][ac +11][am] = to_tf32(rA1.w);
            if (BT) {
                Bs[nb][ac + 0][am] = to_tf32(rB0.x); Bs[nb][ac + 1][am] = to_tf32(rB0.y);
                Bs[nb][ac + 2][am] = to_tf32(rB0.z); Bs[nb][ac + 3][am] = to_tf32(rB0.w);
                Bs[nb][ac + 8][am] = to_tf32(rB1.x); Bs[nb][ac + 9][am] = to_tf32(rB1.y);
                Bs[nb][ac +10][am] = to_tf32(rB1.z); Bs[nb][ac +11][am] = to_tf32(rB1.w);
            } else {
                float4 t0, t1;
                t0.x = to_tf32(rB0.x); t0.y = to_tf32(rB0.y); t0.z = to_tf32(rB0.z); t0.w = to_tf32(rB0.w);
                t1.x = to_tf32(rB1.x); t1.y = to_tf32(rB1.y); t1.z = to_tf32(rB1.z); t1.w = to_tf32(rB1.w);
                *(float4*)&Bs[nb][bk][bc]     = t0;
                *(float4*)&Bs[nb][bk][bc + 4] = t1;
            }
            __syncthreads();
        }
    }

    // epilogue
    #pragma unroll
    for (int mf = 0; mf < 4; mf++) {
        #pragma unroll
        for (int nf = 0; nf < 4; nf++) {
            const int r0 = m0 + wm + mf * 16 + g;
            const int c  = n0 + wn + nf * 8 + 2 * tig;
            float2 v0, v1;
            v0.x = acc[mf][nf][0] * scale; v0.y = acc[mf][nf][1] * scale;
            v1.x = acc[mf][nf][2] * scale; v1.y = acc[mf][nf][3] * scale;
            if (colmul) {
                float m0c = colmul[c], m1c = colmul[c + 1];
                v0.x *= m0c; v0.y *= m1c; v1.x *= m0c; v1.y *= m1c;
            }
            if (bias) {
                float b0 = bias[c], b1 = bias[c + 1];
                v0.x += b0; v0.y += b1; v1.x += b0; v1.y += b1;
            }
            *(float2*)&C[(size_t)r0 * N + c]       = v0;
            *(float2*)&C[(size_t)(r0 + 8) * N + c] = v1;
        }
    }
}

// Fused QKV split-K: grid (1, 32, 12); z = which*4 + split.
__global__ __launch_bounds__(256, 2)
void qkv_mma_kernel(const float* __restrict__ A,
                    const float* __restrict__ wq, const float* __restrict__ wk,
                    const float* __restrict__ wv, float* __restrict__ qkvp) {
    const int which = blockIdx.z >> 2;
    const int split = blockIdx.z & 3;
    const float* B = (which == 0) ? wq : (which == 1) ? wk : wv;
    float* out = qkvp + (size_t)blockIdx.z * S * HIDD;
    mma_gemm_body<true>(A, B, nullptr, nullptr, out, HIDD, CDIM, 1.f,
                        split * 320, 20, blockIdx.y * 128, blockIdx.x * 128);
}

// Generic mma GEMM, split-K over blockIdx.z (partials if gridDim.z>1).
template <bool BT>
__global__ __launch_bounds__(256, 2)
void gemm_mma_kernel(const float* __restrict__ A, const float* __restrict__ B,
                     const float* __restrict__ bias, const float* __restrict__ colmul,
                     float* __restrict__ C, int M, int N, int K, float scale, int kchunk) {
    float* out = C + (size_t)blockIdx.z * M * N;
    mma_gemm_body<BT>(A, B, bias, colmul, out, N, K, scale,
                      blockIdx.z * kchunk, kchunk / 16, blockIdx.y * 128, blockIdx.x * 128);
}

// Reduce QKV partials (+bias). grid (512, 3), 256 thr, float4 per thread.
__global__ void reduce_qkv_kernel(const float* __restrict__ qkvp,
                                  const float* __restrict__ bq, const float* __restrict__ bk,
                                  const float* __restrict__ bv,
                                  float* __restrict__ Q, float* __restrict__ Km,
                                  float* __restrict__ Vm) {
    const size_t MN = (size_t)S * HIDD;
    const int which = blockIdx.y;
    size_t i = ((size_t)blockIdx.x * 256 + threadIdx.x) * 4;
    const float* base = qkvp + (size_t)which * 4 * MN;
    float4 a = *(const float4*)&base[i];
    float4 b = *(const float4*)&base[MN + i];
    float4 c = *(const float4*)&base[2 * MN + i];
    float4 d = *(const float4*)&base[3 * MN + i];
    const float* bias = (which == 0) ? bq : (which == 1) ? bk : bv;
    float4 bb = *(const float4*)&bias[i & 127];
    float4 r;
    r.x = a.x + b.x + c.x + d.x + bb.x;
    r.y = a.y + b.y + c.y + d.y + bb.y;
    r.z = a.z + b.z + c.z + d.z + bb.z;
    r.w = a.w + b.w + c.w + d.w + bb.w;
    float* out = (which == 0) ? Q : (which == 1) ? Km : Vm;
    *(float4*)&out[i] = r;
}

// Reduce AV partials (8-way). grid 512, 256 thr.
__global__ void reduce_av8_kernel(const float* __restrict__ avp, float* __restrict__ av) {
    const size_t MN = (size_t)S * HIDD;
    size_t i = ((size_t)blockIdx.x * 256 + threadIdx.x) * 4;
    float4 r = *(const float4*)&avp[i];
    #pragma unroll
    for (int z = 1; z < 8; z++) {
        float4 v = *(const float4*)&avp[(size_t)z * MN + i];
        r.x += v.x; r.y += v.y; r.z += v.z; r.w += v.w;
    }
    *(float4*)&av[i] = r;
}

// ---------------- mask[k] = sigmoid(iv . K[k]) -------------------------------
__global__ void mask_kernel(const float* __restrict__ Kmat, const float* __restrict__ iv,
                            float* __restrict__ mask) {
    __shared__ float sm[128];
    int k = blockIdx.x;
    float v = iv[threadIdx.x] * Kmat[(size_t)k * HIDD + threadIdx.x];
    sm[threadIdx.x] = v; __syncthreads();
    for (int o = 64; o > 0; o >>= 1) {
        if (threadIdx.x < o) sm[threadIdx.x] += sm[threadIdx.x + o];
        __syncthreads();
    }
    if (threadIdx.x == 0) mask[k] = 1.f / (1.f + expf(-sm[0]));
}

// ---------------- row softmax (mask pre-applied in GEMM epilogue) ------------
__global__ void softmax_kernel(float* __restrict__ attn) {
    __shared__ float red[256];
    int q = blockIdx.x;
    float4* row = (float4*)(attn + (size_t)q * S);
    float mx = -1e30f;
    for (int k = threadIdx.x; k < S / 4; k += 256) {
        float4 v = row[k];
        mx = fmaxf(mx, fmaxf(fmaxf(v.x, v.y), fmaxf(v.z, v.w)));
    }
    red[threadIdx.x] = mx; __syncthreads();
    for (int o = 128; o > 0; o >>= 1) {
        if (threadIdx.x < o) red[threadIdx.x] = fmaxf(red[threadIdx.x], red[threadIdx.x + o]);
        __syncthreads();
    }
    mx = red[0]; __syncthreads();
    float s = 0.f;
    for (int k = threadIdx.x; k < S / 4; k += 256) {
        float4 v = row[k];
        v.x = expf(v.x - mx); v.y = expf(v.y - mx);
        v.z = expf(v.z - mx); v.w = expf(v.w - mx);
        row[k] = v;
        s += v.x + v.y + v.z + v.w;
    }
    red[threadIdx.x] = s; __syncthreads();
    for (int o = 128; o > 0; o >>= 1) {
        if (threadIdx.x < o) red[threadIdx.x] += red[threadIdx.x + o];
        __syncthreads();
    }
    float inv = 1.f / red[0];
    for (int k = threadIdx.x; k < S / 4; k += 256) {
        float4 v = row[k];
        v.x *= inv; v.y *= inv; v.z *= inv; v.w *= inv;
        row[k] = v;
    }
}

// ---------------- decoupling epilogue + per-row partial stats ----------------
__global__ void epilogue_kernel(float* __restrict__ att, const float* __restrict__ cidp,
                                double* __restrict__ psum, double* __restrict__ psq) {
    __shared__ float red[256], red2[256];
    int s = blockIdx.x;
    float* row = att + (size_t)s * CDIM;
    float dot = 0.f;
    for (int c = threadIdx.x; c < CDIM; c += 256) dot += row[c] * cidp[c];
    red[threadIdx.x] = dot; __syncthreads();
    for (int o = 128; o > 0; o >>= 1) {
        if (threadIdx.x < o) red[threadIdx.x] += red[threadIdx.x + o];
        __syncthreads();
    }
    float w = 1.f / (1.f + expf(-red[0]));
    __syncthreads();
    float ls = 0.f, lq = 0.f;
    for (int c = threadIdx.x; c < CDIM; c += 256) {
        float v = row[c] - w * cidp[c];
        row[c] = v;
        ls += v; lq += v * v;
    }
    red[threadIdx.x] = ls; red2[threadIdx.x] = lq; __syncthreads();
    for (int o = 128; o > 0; o >>= 1) {
        if (threadIdx.x < o) { red[threadIdx.x] += red[threadIdx.x + o]; red2[threadIdx.x] += red2[threadIdx.x + o]; }
        __syncthreads();
    }
    if (threadIdx.x == 0) { psum[s] = (double)red[0]; psq[s] = (double)red2[0]; }
}

// ---------------- global LN stats (deterministic, single block) --------------
__global__ void stats_kernel(const double* __restrict__ psum, const double* __restrict__ psq) {
    __shared__ double rs[1024], rq[1024];
    double s = 0.0, q = 0.0;
    for (int i = threadIdx.x; i < S; i += 1024) { s += psum[i]; q += psq[i]; }
    rs[threadIdx.x] = s; rq[threadIdx.x] = q; __syncthreads();
    for (int o = 512; o > 0; o >>= 1) {
        if (threadIdx.x < o) { rs[threadIdx.x] += rs[threadIdx.x + o]; rq[threadIdx.x] += rq[threadIdx.x + o]; }
        __syncthreads();
    }
    if (threadIdx.x == 0) {
        double n = (double)S * (double)CDIM;
        double mean = rs[0] / n;
        double var  = rq[0] / n - mean * mean;
        g_mean_f = (float)mean;
        g_rstd_f = (float)rsqrt(var + 1e-5);
    }
}

// ---------------- normalize + transpose back (S,C) -> (C,S) ------------------
__global__ void out_transpose_kernel(const float* __restrict__ af, float* __restrict__ out) {
    __shared__ float tile[32][33];
    float mean = g_mean_f, rstd = g_rstd_f;
    int c0 = blockIdx.x * 32, s0 = blockIdx.y * 32;
    #pragma unroll
    for (int i = threadIdx.y; i < 32; i += 8)
        tile[i][threadIdx.x] = af[(size_t)(s0 + i) * CDIM + c0 + threadIdx.x];
    __syncthreads();
    #pragma unroll
    for (int i = threadIdx.y; i < 32; i += 8)
        out[(size_t)(c0 + i) * S + s0 + threadIdx.x] = (tile[threadIdx.x][i] - mean) * rstd;
}

// ---------------- launch ------------------------------------------------------
extern "C" void kernel_launch(void* const* d_in, const int* in_sizes, int n_in,
                              void* d_out, int out_size) {
    const float* z      = (const float*)d_in[0];
    const float* cid    = (const float*)d_in[1];
    const float* mlp_w  = (const float*)d_in[2];
    const float* mlp_b  = (const float*)d_in[3];
    const float* proj_w = (const float*)d_in[4];
    const float* proj_b = (const float*)d_in[5];
    const float* wq_w   = (const float*)d_in[6];
    const float* wq_b   = (const float*)d_in[7];
    const float* wk_w   = (const float*)d_in[8];
    const float* wk_b   = (const float*)d_in[9];
    const float* wv_w   = (const float*)d_in[10];
    const float* wv_b   = (const float*)d_in[11];
    const float* wo_w   = (const float*)d_in[12];
    const float* wo_b   = (const float*)d_in[13];
    float* out = (float*)d_out;

    float *zt, *Q, *Km, *Vm, *iv, *cidp, *maskv, *attn, *qkvp, *avp, *av, *att;
    double *psum, *psq;
    cudaGetSymbolAddress((void**)&zt,    g_zt);
    cudaGetSymbolAddress((void**)&Q,     g_Q);
    cudaGetSymbolAddress((void**)&Km,    g_Km);
    cudaGetSymbolAddress((void**)&Vm,    g_Vm);
    cudaGetSymbolAddress((void**)&iv,    g_iv);
    cudaGetSymbolAddress((void**)&cidp,  g_cidp);
    cudaGetSymbolAddress((void**)&maskv, g_maskv);
    cudaGetSymbolAddress((void**)&attn,  g_attn);
    cudaGetSymbolAddress((void**)&qkvp,  g_qkvp);
    cudaGetSymbolAddress((void**)&avp,   g_avp);
    cudaGetSymbolAddress((void**)&av,    g_av);
    cudaGetSymbolAddress((void**)&att,   g_att);
    cudaGetSymbolAddress((void**)&psum,  g_psum);
    cudaGetSymbolAddress((void**)&psq,   g_psq);

    dim3 t32x8(32, 8);

    // 1. z (C,S) -> zt (S,C)
    transpose_zt_kernel<<<dim3(S / 32, CDIM / 32), t32x8>>>(z, zt);
    // 2. per-token LayerNorm over C
    ln_rows_kernel<<<S, 256>>>(zt);
    // 3. iv = mlp(cid); cidp = proj(cid)
    dual_matvec_kernel<<<HIDD + CDIM, 128>>>(mlp_w, mlp_b, proj_w, proj_b, cid, iv, cidp);
    // 4. QKV tf32 mma, split-K x4: grid (1,32,12)
    qkv_mma_kernel<<<dim3(1, S / 128, 12), 256>>>(zt, wq_w, wk_w, wv_w, qkvp);
    reduce_qkv_kernel<<<dim3(512, 3), 256>>>(qkvp, wq_b, wk_b, wv_b, Q, Km, Vm);
    // 5. mask (needs Km)
    mask_kernel<<<S, 128>>>(Km, iv, maskv);
    // 6. attn = (Q K^T / 64) * mask[col]  — mask fused into epilogue. grid (32,32)
    gemm_mma_kernel<true><<<dim3(S / 128, S / 128, 1), 256>>>(
        Q, Km, nullptr, maskv, attn, S, S, HIDD, 1.f / 64.f, HIDD);
    // 7. row softmax (pass 1 read-only)
    softmax_kernel<<<S, 256>>>(attn);
    // 8. av = A V — tf32 mma split-K x8: grid (1,32,8)
    gemm_mma_kernel<false><<<dim3(1, S / 128, 8), 256>>>(
        attn, Vm, nullptr, nullptr, avp, S, HIDD, S, 1.f, S / 8);
    reduce_av8_kernel<<<512, 256>>>(avp, av);
    // 9. attended = av wo^T + wo_b: grid (10,32)
    gemm_mma_kernel<true><<<dim3(CDIM / 128, S / 128, 1), 256>>>(
        av, wo_w, wo_b, nullptr, att, S, CDIM, HIDD, 1.f, HIDD);
    // 10. decoupling epilogue + partial stats
    epilogue_kernel<<<S, 256>>>(att, cidp, psum, psq);
    // 11. global LN stats
    stats_kernel<<<1, 1024>>>(psum, psq);
    // 12. normalize + transpose to (C,H,W)
    out_transpose_kernel<<<dim3(CDIM / 32, S / 32), t32x8>>>(att, out);
}

// round 5
// speedup vs baseline: 5.1584x; 1.3214x over previous
#include <cuda_runtime.h>
#include <math.h>
#include <stdint.h>

#define S     4096
#define CDIM  1280
#define HIDD  128
#define DID   1536
#define EPSV  1e-5f

// ---------------- scratch (static device globals; no allocations) ----------
__device__ float  g_zt  [(size_t)S * CDIM];
__device__ float  g_Q   [(size_t)S * HIDD];
__device__ float  g_Km  [(size_t)S * HIDD];
__device__ float  g_Vm  [(size_t)S * HIDD];
__device__ float  g_iv  [HIDD];
__device__ float  g_cidp[CDIM];
__device__ float  g_maskv[S];
__device__ float  g_attn[(size_t)S * S];
__device__ float  g_qkvp[(size_t)12 * S * HIDD];
__device__ float  g_avp [(size_t)8 * S * HIDD];
__device__ float  g_av  [(size_t)S * HIDD];
__device__ float  g_att [(size_t)S * CDIM];
__device__ double g_psum[S];
__device__ double g_psq [S];
__device__ float  g_mean_f;
__device__ float  g_rstd_f;

// ---------------- helpers ----------------------------------------------------
__device__ __forceinline__ void cp16(void* dst, const void* src) {
    uint32_t d = (uint32_t)__cvta_generic_to_shared(dst);
    asm volatile("cp.async.cg.shared.global [%0], [%1], 16;\n" :: "r"(d), "l"(src));
}
#define CP_COMMIT() asm volatile("cp.async.commit_group;\n" ::: "memory")
#define CP_WAIT1()  asm volatile("cp.async.wait_group 1;\n" ::: "memory")

__device__ __forceinline__ void mma_tf32(float* d, const float* a, const float* b) {
    asm volatile(
        "mma.sync.aligned.m16n8k8.row.col.f32.tf32.tf32.f32 "
        "{%0,%1,%2,%3}, {%4,%5,%6,%7}, {%8,%9}, {%0,%1,%2,%3};"
        : "+f"(d[0]), "+f"(d[1]), "+f"(d[2]), "+f"(d[3])
        : "r"(__float_as_uint(a[0])), "r"(__float_as_uint(a[1])),
          "r"(__float_as_uint(a[2])), "r"(__float_as_uint(a[3])),
          "r"(__float_as_uint(b[0])), "r"(__float_as_uint(b[1])));
}

// ---------------- transpose z (C,S) -> zt (S,C) ----------------------------
__global__ void transpose_zt_kernel(const float* __restrict__ z, float* __restrict__ zt) {
    __shared__ float tile[32][33];
    int s0 = blockIdx.x * 32, c0 = blockIdx.y * 32;
    #pragma unroll
    for (int i = threadIdx.y; i < 32; i += 8)
        tile[i][threadIdx.x] = z[(size_t)(c0 + i) * S + s0 + threadIdx.x];
    __syncthreads();
    #pragma unroll
    for (int i = threadIdx.y; i < 32; i += 8)
        zt[(size_t)(s0 + i) * CDIM + c0 + threadIdx.x] = tile[threadIdx.x][i];
}

// ---------------- row LayerNorm over C (in place) ---------------------------
__global__ void ln_rows_kernel(float* __restrict__ x) {
    __shared__ float rs[256], rq[256];
    int row = blockIdx.x;
    float4* p = (float4*)(x + (size_t)row * CDIM);
    float s = 0.f, q = 0.f;
    for (int i = threadIdx.x; i < CDIM / 4; i += 256) {
        float4 v = p[i];
        s += v.x + v.y + v.z + v.w;
        q += v.x * v.x + v.y * v.y + v.z * v.z + v.w * v.w;
    }
    rs[threadIdx.x] = s; rq[threadIdx.x] = q; __syncthreads();
    for (int o = 128; o > 0; o >>= 1) {
        if (threadIdx.x < o) { rs[threadIdx.x] += rs[threadIdx.x + o]; rq[threadIdx.x] += rq[threadIdx.x + o]; }
        __syncthreads();
    }
    float mean = rs[0] / CDIM;
    float var  = rq[0] / CDIM - mean * mean;
    float rstd = rsqrtf(var + EPSV);
    for (int i = threadIdx.x; i < CDIM / 4; i += 256) {
        float4 v = p[i];
        v.x = (v.x - mean) * rstd; v.y = (v.y - mean) * rstd;
        v.z = (v.z - mean) * rstd; v.w = (v.w - mean) * rstd;
        p[i] = v;
    }
}

// ---------------- iv = mlp(cid), cidp = proj(cid) ---------------------------
__global__ void dual_matvec_kernel(const float* __restrict__ w1, const float* __restrict__ b1,
                                   const float* __restrict__ w2, const float* __restrict__ b2,
                                   const float* __restrict__ x,
                                   float* __restrict__ o1, float* __restrict__ o2) {
    __shared__ float sm[128];
    int n = blockIdx.x;
    const float* w; float bv; float* o; int nn;
    if (n < HIDD) { nn = n;        w = w1 + (size_t)nn * DID; bv = b1[nn]; o = o1; }
    else          { nn = n - HIDD; w = w2 + (size_t)nn * DID; bv = b2[nn]; o = o2; }
    float s = 0.f;
    for (int k = threadIdx.x; k < DID; k += 128) s += w[k] * x[k];
    sm[threadIdx.x] = s; __syncthreads();
    for (int off = 64; off > 0; off >>= 1) {
        if (threadIdx.x < off) sm[threadIdx.x] += sm[threadIdx.x + off];
        __syncthreads();
    }
    if (threadIdx.x == 0) o[nn] = sm[0] + bv;
}

// ---------------- tf32 mma GEMM engine v2 ------------------------------------
// 128x128 CTA tile, 256 thr, 8 warps (2x4), warp 64x32, k-tile 16,
// 2-stage cp.async pipeline, conflict-free smem layouts.
// A: (M,K) row-major. BT=true: B (N,K); BT=false: B (K,N).
template <bool BT>
__device__ __forceinline__ void mma_gemm_body(
        const float* __restrict__ A, const float* __restrict__ B,
        const float* __restrict__ bias, const float* __restrict__ colmul,
        float* __restrict__ C,
        int N, int K, float scale, int kstart, int nkt, int m0, int n0) {
    // A (and BT-B): [row][k16 + 4 pad] stride 20. !BT B: [k][n + 8 pad] stride 136.
    constexpr int BSZ = BT ? (128 * 20) : (16 * 136);
    __shared__ float As[2][128][20];
    __shared__ float Bs[2][BSZ];

    const int tid  = threadIdx.x;
    const int lane = tid & 31, wid = tid >> 5;
    const int g    = lane >> 2, tig = lane & 3;
    const int wm   = (wid >> 2) * 64;
    const int wn   = (wid & 3) * 32;

    float acc[4][4][4] = {};

    // ---- fill one stage via cp.async (2 x 16B chunks per thread per operand)
    auto fill = [&](int s, int k0) {
        #pragma unroll
        for (int i = 0; i < 2; i++) {
            int ci = tid * 2 + i;
            int r = ci >> 2, c4 = (ci & 3) * 4;
            cp16(&As[s][r][c4], A + (size_t)(m0 + r) * K + k0 + c4);
        }
        if (BT) {
            #pragma unroll
            for (int i = 0; i < 2; i++) {
                int ci = tid * 2 + i;
                int r = ci >> 2, c4 = (ci & 3) * 4;
                cp16(&Bs[s][r * 20 + c4], B + (size_t)(n0 + r) * K + k0 + c4);
            }
        } else {
            #pragma unroll
            for (int i = 0; i < 2; i++) {
                int ci = tid * 2 + i;
                int kr = ci >> 5, nc = (ci & 31) * 4;
                cp16(&Bs[s][kr * 136 + nc], B + (size_t)(k0 + kr) * N + n0 + nc);
            }
        }
    };

    fill(0, kstart);
    CP_COMMIT();

    for (int t = 0; t < nkt; t++) {
        const int st = t & 1;
        if (t + 1 < nkt) fill(st ^ 1, kstart + (t + 1) * 16);
        CP_COMMIT();
        CP_WAIT1();
        __syncthreads();

        #pragma unroll
        for (int ks = 0; ks < 2; ks++) {
            const int kk = ks * 8;
            float a[4][4], b[4][2];
            #pragma unroll
            for (int mf = 0; mf < 4; mf++) {
                a[mf][0] = As[st][wm + mf * 16 + g    ][kk + tig];
                a[mf][1] = As[st][wm + mf * 16 + g + 8][kk + tig];
                a[mf][2] = As[st][wm + mf * 16 + g    ][kk + tig + 4];
                a[mf][3] = As[st][wm + mf * 16 + g + 8][kk + tig + 4];
            }
            #pragma unroll
            for (int nf = 0; nf < 4; nf++) {
                if (BT) {
                    b[nf][0] = Bs[st][(wn + nf * 8 + g) * 20 + kk + tig];
                    b[nf][1] = Bs[st][(wn + nf * 8 + g) * 20 + kk + tig + 4];
                } else {
                    b[nf][0] = Bs[st][(kk + tig)     * 136 + wn + nf * 8 + g];
                    b[nf][1] = Bs[st][(kk + tig + 4) * 136 + wn + nf * 8 + g];
                }
            }
            #pragma unroll
            for (int mf = 0; mf < 4; mf++)
                #pragma unroll
                for (int nf = 0; nf < 4; nf++)
                    mma_tf32(acc[mf][nf], a[mf], b[nf]);
        }
        __syncthreads();   // compute done before next iter refills this buffer
    }

    // epilogue
    #pragma unroll
    for (int mf = 0; mf < 4; mf++) {
        #pragma unroll
        for (int nf = 0; nf < 4; nf++) {
            const int r0 = m0 + wm + mf * 16 + g;
            const int c  = n0 + wn + nf * 8 + 2 * tig;
            float2 v0, v1;
            v0.x = acc[mf][nf][0] * scale; v0.y = acc[mf][nf][1] * scale;
            v1.x = acc[mf][nf][2] * scale; v1.y = acc[mf][nf][3] * scale;
            if (colmul) {
                float m0c = colmul[c], m1c = colmul[c + 1];
                v0.x *= m0c; v0.y *= m1c; v1.x *= m0c; v1.y *= m1c;
            }
            if (bias) {
                float b0 = bias[c], b1 = bias[c + 1];
                v0.x += b0; v0.y += b1; v1.x += b0; v1.y += b1;
            }
            *(float2*)&C[(size_t)r0 * N + c]       = v0;
            *(float2*)&C[(size_t)(r0 + 8) * N + c] = v1;
        }
    }
}

// Fused QKV split-K: grid (1, 32, 12); z = which*4 + split.
__global__ __launch_bounds__(256, 2)
void qkv_mma_kernel(const float* __restrict__ A,
                    const float* __restrict__ wq, const float* __restrict__ wk,
                    const float* __restrict__ wv, float* __restrict__ qkvp) {
    const int which = blockIdx.z >> 2;
    const int split = blockIdx.z & 3;
    const float* B = (which == 0) ? wq : (which == 1) ? wk : wv;
    float* out = qkvp + (size_t)blockIdx.z * S * HIDD;
    mma_gemm_body<true>(A, B, nullptr, nullptr, out, HIDD, CDIM, 1.f,
                        split * 320, 20, blockIdx.y * 128, blockIdx.x * 128);
}

// Generic mma GEMM, split-K over blockIdx.z (partials if gridDim.z>1).
template <bool BT>
__global__ __launch_bounds__(256, 2)
void gemm_mma_kernel(const float* __restrict__ A, const float* __restrict__ B,
                     const float* __restrict__ bias, const float* __restrict__ colmul,
                     float* __restrict__ C, int M, int N, int K, float scale, int kchunk) {
    float* out = C + (size_t)blockIdx.z * M * N;
    mma_gemm_body<BT>(A, B, bias, colmul, out, N, K, scale,
                      blockIdx.z * kchunk, kchunk / 16, blockIdx.y * 128, blockIdx.x * 128);
}

// Reduce QKV partials (+bias). grid (512, 3), 256 thr.
__global__ void reduce_qkv_kernel(const float* __restrict__ qkvp,
                                  const float* __restrict__ bq, const float* __restrict__ bk,
                                  const float* __restrict__ bv,
                                  float* __restrict__ Q, float* __restrict__ Km,
                                  float* __restrict__ Vm) {
    const size_t MN = (size_t)S * HIDD;
    const int which = blockIdx.y;
    size_t i = ((size_t)blockIdx.x * 256 + threadIdx.x) * 4;
    const float* base = qkvp + (size_t)which * 4 * MN;
    float4 a = *(const float4*)&base[i];
    float4 b = *(const float4*)&base[MN + i];
    float4 c = *(const float4*)&base[2 * MN + i];
    float4 d = *(const float4*)&base[3 * MN + i];
    const float* bias = (which == 0) ? bq : (which == 1) ? bk : bv;
    float4 bb = *(const float4*)&bias[i & 127];
    float4 r;
    r.x = a.x + b.x + c.x + d.x + bb.x;
    r.y = a.y + b.y + c.y + d.y + bb.y;
    r.z = a.z + b.z + c.z + d.z + bb.z;
    r.w = a.w + b.w + c.w + d.w + bb.w;
    float* out = (which == 0) ? Q : (which == 1) ? Km : Vm;
    *(float4*)&out[i] = r;
}

// Reduce AV partials (8-way). grid 512, 256 thr.
__global__ void reduce_av8_kernel(const float* __restrict__ avp, float* __restrict__ av) {
    const size_t MN = (size_t)S * HIDD;
    size_t i = ((size_t)blockIdx.x * 256 + threadIdx.x) * 4;
    float4 r = *(const float4*)&avp[i];
    #pragma unroll
    for (int z = 1; z < 8; z++) {
        float4 v = *(const float4*)&avp[(size_t)z * MN + i];
        r.x += v.x; r.y += v.y; r.z += v.z; r.w += v.w;
    }
    *(float4*)&av[i] = r;
}

// ---------------- mask[k] = sigmoid(iv . K[k]) -------------------------------
__global__ void mask_kernel(const float* __restrict__ Kmat, const float* __restrict__ iv,
                            float* __restrict__ mask) {
    __shared__ float sm[128];
    int k = blockIdx.x;
    float v = iv[threadIdx.x] * Kmat[(size_t)k * HIDD + threadIdx.x];
    sm[threadIdx.x] = v; __syncthreads();
    for (int o = 64; o > 0; o >>= 1) {
        if (threadIdx.x < o) sm[threadIdx.x] += sm[threadIdx.x + o];
        __syncthreads();
    }
    if (threadIdx.x == 0) mask[k] = 1.f / (1.f + expf(-sm[0]));
}

// ---------------- row softmax (mask pre-applied in GEMM epilogue) ------------
__global__ void softmax_kernel(float* __restrict__ attn) {
    __shared__ float red[256];
    int q = blockIdx.x;
    float4* row = (float4*)(attn + (size_t)q * S);
    float mx = -1e30f;
    for (int k = threadIdx.x; k < S / 4; k += 256) {
        float4 v = row[k];
        mx = fmaxf(mx, fmaxf(fmaxf(v.x, v.y), fmaxf(v.z, v.w)));
    }
    red[threadIdx.x] = mx; __syncthreads();
    for (int o = 128; o > 0; o >>= 1) {
        if (threadIdx.x < o) red[threadIdx.x] = fmaxf(red[threadIdx.x], red[threadIdx.x + o]);
        __syncthreads();
    }
    mx = red[0]; __syncthreads();
    float s = 0.f;
    for (int k = threadIdx.x; k < S / 4; k += 256) {
        float4 v = row[k];
        v.x = __expf(v.x - mx); v.y = __expf(v.y - mx);
        v.z = __expf(v.z - mx); v.w = __expf(v.w - mx);
        row[k] = v;
        s += v.x + v.y + v.z + v.w;
    }
    red[threadIdx.x] = s; __syncthreads();
    for (int o = 128; o > 0; o >>= 1) {
        if (threadIdx.x < o) red[threadIdx.x] += red[threadIdx.x + o];
        __syncthreads();
    }
    float inv = 1.f / red[0];
    for (int k = threadIdx.x; k < S / 4; k += 256) {
        float4 v = row[k];
        v.x *= inv; v.y *= inv; v.z *= inv; v.w *= inv;
        row[k] = v;
    }
}

// ---------------- decoupling epilogue + per-row partial stats ----------------
__global__ void epilogue_kernel(float* __restrict__ att, const float* __restrict__ cidp,
                                double* __restrict__ psum, double* __restrict__ psq) {
    __shared__ float red[256], red2[256];
    int s = blockIdx.x;
    float* row = att + (size_t)s * CDIM;
    float dot = 0.f;
    for (int c = threadIdx.x; c < CDIM; c += 256) dot += row[c] * cidp[c];
    red[threadIdx.x] = dot; __syncthreads();
    for (int o = 128; o > 0; o >>= 1) {
        if (threadIdx.x < o) red[threadIdx.x] += red[threadIdx.x + o];
        __syncthreads();
    }
    float w = 1.f / (1.f + expf(-red[0]));
    __syncthreads();
    float ls = 0.f, lq = 0.f;
    for (int c = threadIdx.x; c < CDIM; c += 256) {
        float v = row[c] - w * cidp[c];
        row[c] = v;
        ls += v; lq += v * v;
    }
    red[threadIdx.x] = ls; red2[threadIdx.x] = lq; __syncthreads();
    for (int o = 128; o > 0; o >>= 1) {
        if (threadIdx.x < o) { red[threadIdx.x] += red[threadIdx.x + o]; red2[threadIdx.x] += red2[threadIdx.x + o]; }
        __syncthreads();
    }
    if (threadIdx.x == 0) { psum[s] = (double)red[0]; psq[s] = (double)red2[0]; }
}

// ---------------- global LN stats (deterministic, single block) --------------
__global__ void stats_kernel(const double* __restrict__ psum, const double* __restrict__ psq) {
    __shared__ double rs[1024], rq[1024];
    double s = 0.0, q = 0.0;
    for (int i = threadIdx.x; i < S; i += 1024) { s += psum[i]; q += psq[i]; }
    rs[threadIdx.x] = s; rq[threadIdx.x] = q; __syncthreads();
    for (int o = 512; o > 0; o >>= 1) {
        if (threadIdx.x < o) { rs[threadIdx.x] += rs[threadIdx.x + o]; rq[threadIdx.x] += rq[threadIdx.x + o]; }
        __syncthreads();
    }
    if (threadIdx.x == 0) {
        double n = (double)S * (double)CDIM;
        double mean = rs[0] / n;
        double var  = rq[0] / n - mean * mean;
        g_mean_f = (float)mean;
        g_rstd_f = (float)rsqrt(var + 1e-5);
    }
}

// ---------------- normalize + transpose back (S,C) -> (C,S) ------------------
__global__ void out_transpose_kernel(const float* __restrict__ af, float* __restrict__ out) {
    __shared__ float tile[32][33];
    float mean = g_mean_f, rstd = g_rstd_f;
    int c0 = blockIdx.x * 32, s0 = blockIdx.y * 32;
    #pragma unroll
    for (int i = threadIdx.y; i < 32; i += 8)
        tile[i][threadIdx.x] = af[(size_t)(s0 + i) * CDIM + c0 + threadIdx.x];
    __syncthreads();
    #pragma unroll
    for (int i = threadIdx.y; i < 32; i += 8)
        out[(size_t)(c0 + i) * S + s0 + threadIdx.x] = (tile[threadIdx.x][i] - mean) * rstd;
}

// ---------------- launch ------------------------------------------------------
extern "C" void kernel_launch(void* const* d_in, const int* in_sizes, int n_in,
                              void* d_out, int out_size) {
    const float* z      = (const float*)d_in[0];
    const float* cid    = (const float*)d_in[1];
    const float* mlp_w  = (const float*)d_in[2];
    const float* mlp_b  = (const float*)d_in[3];
    const float* proj_w = (const float*)d_in[4];
    const float* proj_b = (const float*)d_in[5];
    const float* wq_w   = (const float*)d_in[6];
    const float* wq_b   = (const float*)d_in[7];
    const float* wk_w   = (const float*)d_in[8];
    const float* wk_b   = (const float*)d_in[9];
    const float* wv_w   = (const float*)d_in[10];
    const float* wv_b   = (const float*)d_in[11];
    const float* wo_w   = (const float*)d_in[12];
    const float* wo_b   = (const float*)d_in[13];
    float* out = (float*)d_out;

    float *zt, *Q, *Km, *Vm, *iv, *cidp, *maskv, *attn, *qkvp, *avp, *av, *att;
    double *psum, *psq;
    cudaGetSymbolAddress((void**)&zt,    g_zt);
    cudaGetSymbolAddress((void**)&Q,     g_Q);
    cudaGetSymbolAddress((void**)&Km,    g_Km);
    cudaGetSymbolAddress((void**)&Vm,    g_Vm);
    cudaGetSymbolAddress((void**)&iv,    g_iv);
    cudaGetSymbolAddress((void**)&cidp,  g_cidp);
    cudaGetSymbolAddress((void**)&maskv, g_maskv);
    cudaGetSymbolAddress((void**)&attn,  g_attn);
    cudaGetSymbolAddress((void**)&qkvp,  g_qkvp);
    cudaGetSymbolAddress((void**)&avp,   g_avp);
    cudaGetSymbolAddress((void**)&av,    g_av);
    cudaGetSymbolAddress((void**)&att,   g_att);
    cudaGetSymbolAddress((void**)&psum,  g_psum);
    cudaGetSymbolAddress((void**)&psq,   g_psq);

    dim3 t32x8(32, 8);

    // 1. z (C,S) -> zt (S,C)
    transpose_zt_kernel<<<dim3(S / 32, CDIM / 32), t32x8>>>(z, zt);
    // 2. per-token LayerNorm over C
    ln_rows_kernel<<<S, 256>>>(zt);
    // 3. iv = mlp(cid); cidp = proj(cid)
    dual_matvec_kernel<<<HIDD + CDIM, 128>>>(mlp_w, mlp_b, proj_w, proj_b, cid, iv, cidp);
    // 4. QKV tf32 mma, split-K x4: grid (1,32,12)
    qkv_mma_kernel<<<dim3(1, S / 128, 12), 256>>>(zt, wq_w, wk_w, wv_w, qkvp);
    reduce_qkv_kernel<<<dim3(512, 3), 256>>>(qkvp, wq_b, wk_b, wv_b, Q, Km, Vm);
    // 5. mask (needs Km)
    mask_kernel<<<S, 128>>>(Km, iv, maskv);
    // 6. attn = (Q K^T / 64) * mask[col]  — mask fused into epilogue. grid (32,32)
    gemm_mma_kernel<true><<<dim3(S / 128, S / 128, 1), 256>>>(
        Q, Km, nullptr, maskv, attn, S, S, HIDD, 1.f / 64.f, HIDD);
    // 7. row softmax
    softmax_kernel<<<S, 256>>>(attn);
    // 8. av = A V — tf32 mma split-K x8: grid (1,32,8)
    gemm_mma_kernel<false><<<dim3(1, S / 128, 8), 256>>>(
        attn, Vm, nullptr, nullptr, avp, S, HIDD, S, 1.f, S / 8);
    reduce_av8_kernel<<<512, 256>>>(avp, av);
    // 9. attended = av wo^T + wo_b: grid (10,32)
    gemm_mma_kernel<true><<<dim3(CDIM / 128, S / 128, 1), 256>>>(
        av, wo_w, wo_b, nullptr, att, S, CDIM, HIDD, 1.f, HIDD);
    // 10. decoupling epilogue + partial stats
    epilogue_kernel<<<S, 256>>>(att, cidp, psum, psq);
    // 11. global LN stats
    stats_kernel<<<1, 1024>>>(psum, psq);
    // 12. normalize + transpose to (C,H,W)
    out_transpose_kernel<<<dim3(CDIM / 32, S / 32), t32x8>>>(att, out);
}

// round 7
// speedup vs baseline: 5.6028x; 1.0862x over previous
#include <cuda_runtime.h>
#include <math.h>
#include <stdint.h>

#define S     4096
#define CDIM  1280
#define HIDD  128
#define DID   1536
#define EPSV  1e-5f

// ---------------- scratch (static device globals; no allocations) ----------
__device__ float  g_zt  [(size_t)S * CDIM];
__device__ float  g_Q   [(size_t)S * HIDD];
__device__ float  g_Km  [(size_t)S * HIDD];
__device__ float  g_Vm  [(size_t)S * HIDD];
__device__ float  g_iv  [HIDD];
__device__ float  g_cidp[CDIM];
__device__ float  g_maskv[S];
__device__ float  g_qkvp[(size_t)12 * S * HIDD];
__device__ float  g_Opart[(size_t)2 * S * HIDD];
__device__ float  g_mpart[2 * S];
__device__ float  g_lpart[2 * S];
__device__ float  g_av  [(size_t)S * HIDD];
__device__ float  g_att [(size_t)S * CDIM];
__device__ double g_psum[S];
__device__ double g_psq [S];
__device__ float  g_mean_f;
__device__ float  g_rstd_f;

// ---------------- helpers ----------------------------------------------------
__device__ __forceinline__ void cp16(void* dst, const void* src) {
    uint32_t d = (uint32_t)__cvta_generic_to_shared(dst);
    asm volatile("cp.async.cg.shared.global [%0], [%1], 16;\n" :: "r"(d), "l"(src));
}
#define CP_COMMIT() asm volatile("cp.async.commit_group;\n" ::: "memory")
#define CP_WAIT1()  asm volatile("cp.async.wait_group 1;\n" ::: "memory")

__device__ __forceinline__ void mma_tf32(float* d, const float* a, const float* b) {
    asm volatile(
        "mma.sync.aligned.m16n8k8.row.col.f32.tf32.tf32.f32 "
        "{%0,%1,%2,%3}, {%4,%5,%6,%7}, {%8,%9}, {%0,%1,%2,%3};"
        : "+f"(d[0]), "+f"(d[1]), "+f"(d[2]), "+f"(d[3])
        : "r"(__float_as_uint(a[0])), "r"(__float_as_uint(a[1])),
          "r"(__float_as_uint(a[2])), "r"(__float_as_uint(a[3])),
          "r"(__float_as_uint(b[0])), "r"(__float_as_uint(b[1])));
}

// ---------------- transpose z (C,S) -> zt (S,C) ----------------------------
__global__ void transpose_zt_kernel(const float* __restrict__ z, float* __restrict__ zt) {
    __shared__ float tile[32][33];
    int s0 = blockIdx.x * 32, c0 = blockIdx.y * 32;
    #pragma unroll
    for (int i = threadIdx.y; i < 32; i += 8)
        tile[i][threadIdx.x] = z[(size_t)(c0 + i) * S + s0 + threadIdx.x];
    __syncthreads();
    #pragma unroll
    for (int i = threadIdx.y; i < 32; i += 8)
        zt[(size_t)(s0 + i) * CDIM + c0 + threadIdx.x] = tile[threadIdx.x][i];
}

// ---------------- row LayerNorm over C (in place) ---------------------------
__global__ void ln_rows_kernel(float* __restrict__ x) {
    __shared__ float rs[256], rq[256];
    int row = blockIdx.x;
    float4* p = (float4*)(x + (size_t)row * CDIM);
    float s = 0.f, q = 0.f;
    for (int i = threadIdx.x; i < CDIM / 4; i += 256) {
        float4 v = p[i];
        s += v.x + v.y + v.z + v.w;
        q += v.x * v.x + v.y * v.y + v.z * v.z + v.w * v.w;
    }
    rs[threadIdx.x] = s; rq[threadIdx.x] = q; __syncthreads();
    for (int o = 128; o > 0; o >>= 1) {
        if (threadIdx.x < o) { rs[threadIdx.x] += rs[threadIdx.x + o]; rq[threadIdx.x] += rq[threadIdx.x + o]; }
        __syncthreads();
    }
    float mean = rs[0] / CDIM;
    float var  = rq[0] / CDIM - mean * mean;
    float rstd = rsqrtf(var + EPSV);
    for (int i = threadIdx.x; i < CDIM / 4; i += 256) {
        float4 v = p[i];
        v.x = (v.x - mean) * rstd; v.y = (v.y - mean) * rstd;
        v.z = (v.z - mean) * rstd; v.w = (v.w - mean) * rstd;
        p[i] = v;
    }
}

// ---------------- iv = mlp(cid), cidp = proj(cid) ---------------------------
__global__ void dual_matvec_kernel(const float* __restrict__ w1, const float* __restrict__ b1,
                                   const float* __restrict__ w2, const float* __restrict__ b2,
                                   const float* __restrict__ x,
                                   float* __restrict__ o1, float* __restrict__ o2) {
    __shared__ float sm[128];
    int n = blockIdx.x;
    const float* w; float bv; float* o; int nn;
    if (n < HIDD) { nn = n;        w = w1 + (size_t)nn * DID; bv = b1[nn]; o = o1; }
    else          { nn = n - HIDD; w = w2 + (size_t)nn * DID; bv = b2[nn]; o = o2; }
    float s = 0.f;
    for (int k = threadIdx.x; k < DID; k += 128) s += w[k] * x[k];
    sm[threadIdx.x] = s; __syncthreads();
    for (int off = 64; off > 0; off >>= 1) {
        if (threadIdx.x < off) sm[threadIdx.x] += sm[threadIdx.x + off];
        __syncthreads();
    }
    if (threadIdx.x == 0) o[nn] = sm[0] + bv;
}

// ---------------- tf32 mma GEMM engine (128x128, cp.async 2-stage) ----------
template <bool BT>
__device__ __forceinline__ void mma_gemm_body(
        const float* __restrict__ A, const float* __restrict__ B,
        const float* __restrict__ bias, const float* __restrict__ colmul,
        float* __restrict__ C,
        int N, int K, float scale, int kstart, int nkt, int m0, int n0) {
    constexpr int BSZ = BT ? (128 * 20) : (16 * 136);
    __shared__ float As[2][128][20];
    __shared__ float Bs[2][BSZ];

    const int tid  = threadIdx.x;
    const int lane = tid & 31, wid = tid >> 5;
    const int g    = lane >> 2, tig = lane & 3;
    const int wm   = (wid >> 2) * 64;
    const int wn   = (wid & 3) * 32;

    float acc[4][4][4] = {};

    auto fill = [&](int s, int k0) {
        #pragma unroll
        for (int i = 0; i < 2; i++) {
            int ci = tid * 2 + i;
            int r = ci >> 2, c4 = (ci & 3) * 4;
            cp16(&As[s][r][c4], A + (size_t)(m0 + r) * K + k0 + c4);
        }
        if (BT) {
            #pragma unroll
            for (int i = 0; i < 2; i++) {
                int ci = tid * 2 + i;
                int r = ci >> 2, c4 = (ci & 3) * 4;
                cp16(&Bs[s][r * 20 + c4], B + (size_t)(n0 + r) * K + k0 + c4);
            }
        } else {
            #pragma unroll
            for (int i = 0; i < 2; i++) {
                int ci = tid * 2 + i;
                int kr = ci >> 5, nc = (ci & 31) * 4;
                cp16(&Bs[s][kr * 136 + nc], B + (size_t)(k0 + kr) * N + n0 + nc);
            }
        }
    };

    fill(0, kstart);
    CP_COMMIT();

    for (int t = 0; t < nkt; t++) {
        const int st = t & 1;
        if (t + 1 < nkt) fill(st ^ 1, kstart + (t + 1) * 16);
        CP_COMMIT();
        CP_WAIT1();
        __syncthreads();

        #pragma unroll
        for (int ks = 0; ks < 2; ks++) {
            const int kk = ks * 8;
            float a[4][4], b[4][2];
            #pragma unroll
            for (int mf = 0; mf < 4; mf++) {
                a[mf][0] = As[st][wm + mf * 16 + g    ][kk + tig];
                a[mf][1] = As[st][wm + mf * 16 + g + 8][kk + tig];
                a[mf][2] = As[st][wm + mf * 16 + g    ][kk + tig + 4];
                a[mf][3] = As[st][wm + mf * 16 + g + 8][kk + tig + 4];
            }
            #pragma unroll
            for (int nf = 0; nf < 4; nf++) {
                if (BT) {
                    b[nf][0] = Bs[st][(wn + nf * 8 + g) * 20 + kk + tig];
                    b[nf][1] = Bs[st][(wn + nf * 8 + g) * 20 + kk + tig + 4];
                } else {
                    b[nf][0] = Bs[st][(kk + tig)     * 136 + wn + nf * 8 + g];
                    b[nf][1] = Bs[st][(kk + tig + 4) * 136 + wn + nf * 8 + g];
                }
            }
            #pragma unroll
            for (int mf = 0; mf < 4; mf++)
                #pragma unroll
                for (int nf = 0; nf < 4; nf++)
                    mma_tf32(acc[mf][nf], a[mf], b[nf]);
        }
        __syncthreads();
    }

    #pragma unroll
    for (int mf = 0; mf < 4; mf++) {
        #pragma unroll
        for (int nf = 0; nf < 4; nf++) {
            const int r0 = m0 + wm + mf * 16 + g;
            const int c  = n0 + wn + nf * 8 + 2 * tig;
            float2 v0, v1;
            v0.x = acc[mf][nf][0] * scale; v0.y = acc[mf][nf][1] * scale;
            v1.x = acc[mf][nf][2] * scale; v1.y = acc[mf][nf][3] * scale;
            if (colmul) {
                float m0c = colmul[c], m1c = colmul[c + 1];
                v0.x *= m0c; v0.y *= m1c; v1.x *= m0c; v1.y *= m1c;
            }
            if (bias) {
                float b0 = bias[c], b1 = bias[c + 1];
                v0.x += b0; v0.y += b1; v1.x += b0; v1.y += b1;
            }
            *(float2*)&C[(size_t)r0 * N + c]       = v0;
            *(float2*)&C[(size_t)(r0 + 8) * N + c] = v1;
        }
    }
}

// Fused QKV split-K: grid (1, 32, 12); z = which*4 + split.
__global__ __launch_bounds__(256, 2)
void qkv_mma_kernel(const float* __restrict__ A,
                    const float* __restrict__ wq, const float* __restrict__ wk,
                    const float* __restrict__ wv, float* __restrict__ qkvp) {
    const int which = blockIdx.z >> 2;
    const int split = blockIdx.z & 3;
    const float* B = (which == 0) ? wq : (which == 1) ? wk : wv;
    float* out = qkvp + (size_t)blockIdx.z * S * HIDD;
    mma_gemm_body<true>(A, B, nullptr, nullptr, out, HIDD, CDIM, 1.f,
                        split * 320, 20, blockIdx.y * 128, blockIdx.x * 128);
}

__global__ __launch_bounds__(256, 2)
void gemm_mma_kernel(const float* __restrict__ A, const float* __restrict__ B,
                     const float* __restrict__ bias, float* __restrict__ C,
                     int M, int N, int K, float scale, int kchunk) {
    mma_gemm_body<true>(A, B, bias, nullptr, C, N, K, scale,
                        blockIdx.z * kchunk, kchunk / 16, blockIdx.y * 128, blockIdx.x * 128);
}

// Reduce QKV partials (+bias). grid (512, 3), 256 thr.
__global__ void reduce_qkv_kernel(const float* __restrict__ qkvp,
                                  const float* __restrict__ bq, const float* __restrict__ bk,
                                  const float* __restrict__ bv,
                                  float* __restrict__ Q, float* __restrict__ Km,
                                  float* __restrict__ Vm) {
    const size_t MN = (size_t)S * HIDD;
    const int which = blockIdx.y;
    size_t i = ((size_t)blockIdx.x * 256 + threadIdx.x) * 4;
    const float* base = qkvp + (size_t)which * 4 * MN;
    float4 a = *(const float4*)&base[i];
    float4 b = *(const float4*)&base[MN + i];
    float4 c = *(const float4*)&base[2 * MN + i];
    float4 d = *(const float4*)&base[3 * MN + i];
    const float* bias = (which == 0) ? bq : (which == 1) ? bk : bv;
    float4 bb = *(const float4*)&bias[i & 127];
    float4 r;
    r.x = a.x + b.x + c.x + d.x + bb.x;
    r.y = a.y + b.y + c.y + d.y + bb.y;
    r.z = a.z + b.z + c.z + d.z + bb.z;
    r.w = a.w + b.w + c.w + d.w + bb.w;
    float* out = (which == 0) ? Q : (which == 1) ? Km : Vm;
    *(float4*)&out[i] = r;
}

// ---------------- mask[k] = sigmoid(iv . K[k]) -------------------------------
__global__ void mask_kernel(const float* __restrict__ Kmat, const float* __restrict__ iv,
                            float* __restrict__ mask) {
    __shared__ float sm[128];
    int k = blockIdx.x;
    float v = iv[threadIdx.x] * Kmat[(size_t)k * HIDD + threadIdx.x];
    sm[threadIdx.x] = v; __syncthreads();
    for (int o = 64; o > 0; o >>= 1) {
        if (threadIdx.x < o) sm[threadIdx.x] += sm[threadIdx.x + o];
        __syncthreads();
    }
    if (threadIdx.x == 0) mask[k] = 1.f / (1.f + expf(-sm[0]));
}

// ---------------- flash attention: QK^T*mask -> online softmax -> P.V --------
// Grid (S/64, 2). Each CTA: 64 q-rows, one KV half (2048 keys in 32 tiles of 64).
// Outputs unnormalized O partials + per-row (m, l) for cross-split combine.
#define FLASH_SMEM_FLOATS 47616
__global__ void __launch_bounds__(256, 1)
flash_kernel(const float* __restrict__ Q, const float* __restrict__ K,
             const float* __restrict__ V, const float* __restrict__ maskv,
             float* __restrict__ Opart, float* __restrict__ mpart,
             float* __restrict__ lpart) {
    extern __shared__ float smf[];
    float* Qs  = smf;            // 64 x 132
    float* KsB = smf + 8448;     // 2 x 64 x 132
    float* VsB = smf + 25344;    // 2 x 64 x 136
    float* Ps  = smf + 42752;    // 64 x 68
    float* msk = smf + 47104;    // 2 x 64
    float* maxb= smf + 47232;    // 2 x 64
    float* sumb= smf + 47360;    // 2 x 64
    float* m_sm= smf + 47488;    // 64
    float* l_sm= smf + 47552;    // 64

    const int tid  = threadIdx.x;
    const int lane = tid & 31, w = tid >> 5;
    const int g    = lane >> 2, tig = lane & 3;
    const int wm   = (w & 3) * 16;
    const int wns  = (w >> 2) * 32;    // scores n-block
    const int wno  = (w >> 2) * 64;    // O n-block
    const int wgrp = w >> 2;

    const int qbase  = blockIdx.x * 64;
    const int split  = blockIdx.y;
    const int kstart = split * (S / 2);
    const int NT     = (S / 2) / 64;   // 32

    if (tid < 64) { m_sm[tid] = -1e30f; l_sm[tid] = 0.f; }

    // tile = 64 rows x 128 floats = 2048 x 16B chunks; 8 chunks per thread.
    auto fillKV = [&](int st, int kb) {
        #pragma unroll
        for (int i = 0; i < 8; i++) {
            int ci = i * 256 + tid;          // 0..2047
            int r = ci >> 5, ch = (ci & 31) * 4;
            cp16(KsB + st * 8448 + r * 132 + ch, K + (size_t)(kb + r) * HIDD + ch);
            cp16(VsB + st * 8704 + r * 136 + ch, V + (size_t)(kb + r) * HIDD + ch);
        }
        if (tid < 16) cp16(msk + st * 64 + tid * 4, maskv + kb + tid * 4);
    };

    // prologue: Q + stage 0
    #pragma unroll
    for (int i = 0; i < 8; i++) {
        int ci = i * 256 + tid;
        int r = ci >> 5, ch = (ci & 31) * 4;
        cp16(Qs + r * 132 + ch, Q + (size_t)(qbase + r) * HIDD + ch);
    }
    fillKV(0, kstart);
    CP_COMMIT();

    float o_acc[8][4] = {};
    const int row0 = wm + g, row1 = wm + g + 8;

    for (int t = 0; t < NT; t++) {
        const int st = t & 1;
        if (t + 1 < NT) fillKV(st ^ 1, kstart + (t + 1) * 64);
        CP_COMMIT();
        CP_WAIT1();
        __syncthreads();

        const float* Ks  = KsB + st * 8448;
        const float* Vst = VsB + st * 8704;
        const float* mk  = msk + st * 64;

        // --- scores = Q . K^T ---
        float s_acc[4][4] = {};
        #pragma unroll
        for (int ks = 0; ks < 16; ks++) {
            const int kk = ks * 8;
            float a[4];
            a[0] = Qs[row0 * 132 + kk + tig];
            a[1] = Qs[row1 * 132 + kk + tig];
            a[2] = Qs[row0 * 132 + kk + tig + 4];
            a[3] = Qs[row1 * 132 + kk + tig + 4];
            #pragma unroll
            for (int nf = 0; nf < 4; nf++) {
                const int kr = wns + nf * 8 + g;
                float b[2];
                b[0] = Ks[kr * 132 + kk + tig];
                b[1] = Ks[kr * 132 + kk + tig + 4];
                mma_tf32(s_acc[nf], a, b);
            }
        }

        // --- scale + mask, row max ---
        float rmax0 = -1e30f, rmax1 = -1e30f;
        #pragma unroll
        for (int nf = 0; nf < 4; nf++) {
            const int cc = wns + nf * 8 + 2 * tig;
            const float mk0 = mk[cc] * 0.015625f, mk1 = mk[cc + 1] * 0.015625f;
            s_acc[nf][0] *= mk0; s_acc[nf][1] *= mk1;
            s_acc[nf][2] *= mk0; s_acc[nf][3] *= mk1;
            rmax0 = fmaxf(rmax0, fmaxf(s_acc[nf][0], s_acc[nf][1]));
            rmax1 = fmaxf(rmax1, fmaxf(s_acc[nf][2], s_acc[nf][3]));
        }
        #pragma unroll
        for (int o = 1; o <= 2; o <<= 1) {
            rmax0 = fmaxf(rmax0, __shfl_xor_sync(0xffffffffu, rmax0, o));
            rmax1 = fmaxf(rmax1, __shfl_xor_sync(0xffffffffu, rmax1, o));
        }
        if (tig == 0) { maxb[wgrp * 64 + row0] = rmax0; maxb[wgrp * 64 + row1] = rmax1; }
        __syncthreads();

        // --- online softmax update ---
        const float mp0 = m_sm[row0], mp1 = m_sm[row1];
        const float mn0 = fmaxf(mp0, fmaxf(maxb[row0], maxb[64 + row0]));
        const float mn1 = fmaxf(mp1, fmaxf(maxb[row1], maxb[64 + row1]));
        const float c0f = __expf(mp0 - mn0), c1f = __expf(mp1 - mn1);

        float ps0 = 0.f, ps1 = 0.f;
        #pragma unroll
        for (int nf = 0; nf < 4; nf++) {
            const float p0 = __expf(s_acc[nf][0] - mn0);
            const float p1 = __expf(s_acc[nf][1] - mn0);
            const float p2 = __expf(s_acc[nf][2] - mn1);
            const float p3 = __expf(s_acc[nf][3] - mn1);
            ps0 += p0 + p1; ps1 += p2 + p3;
            const int cc = wns + nf * 8 + 2 * tig;
            *(float2*)&Ps[row0 * 68 + cc] = make_float2(p0, p1);
            *(float2*)&Ps[row1 * 68 + cc] = make_float2(p2, p3);
        }
        #pragma unroll
        for (int o = 1; o <= 2; o <<= 1) {
            ps0 += __shfl_xor_sync(0xffffffffu, ps0, o);
            ps1 += __shfl_xor_sync(0xffffffffu, ps1, o);
        }
        if (tig == 0) { sumb[wgrp * 64 + row0] = ps0; sumb[wgrp * 64 + row1] = ps1; }

        #pragma unroll
        for (int nf = 0; nf < 8; nf++) {
            o_acc[nf][0] *= c0f; o_acc[nf][1] *= c0f;
            o_acc[nf][2] *= c1f; o_acc[nf][3] *= c1f;
        }
        __syncthreads();

        if (w < 4 && tig == 0) {
            l_sm[row0] = l_sm[row0] * c0f + sumb[row0] + sumb[64 + row0];
            m_sm[row0] = mn0;
            l_sm[row1] = l_sm[row1] * c1f + sumb[row1] + sumb[64 + row1];
            m_sm[row1] = mn1;
        }

        // --- O += P . V ---
        #pragma unroll
        for (int ks = 0; ks < 8; ks++) {
            const int kk = ks * 8;
            float a[4];
            a[0] = Ps[row0 * 68 + kk + tig];
            a[1] = Ps[row1 * 68 + kk + tig];
            a[2] = Ps[row0 * 68 + kk + tig + 4];
            a[3] = Ps[row1 * 68 + kk + tig + 4];
            #pragma unroll
            for (int nf = 0; nf < 8; nf++) {
                const int cn = wno + nf * 8 + g;
                float b[2];
                b[0] = Vst[(kk + tig)     * 136 + cn];
                b[1] = Vst[(kk + tig + 4) * 136 + cn];
                mma_tf32(o_acc[nf], a, b);
            }
        }
        __syncthreads();
    }

    // epilogue: unnormalized partials
    float* Ob = Opart + ((size_t)split * S + qbase) * HIDD;
    #pragma unroll
    for (int nf = 0; nf < 8; nf++) {
        const int cc = wno + nf * 8 + 2 * tig;
        *(float2*)&Ob[(size_t)row0 * HIDD + cc] = make_float2(o_acc[nf][0], o_acc[nf][1]);
        *(float2*)&Ob[(size_t)row1 * HIDD + cc] = make_float2(o_acc[nf][2], o_acc[nf][3]);
    }
    if (w < 4 && tig == 0) {
        mpart[split * S + qbase + row0] = m_sm[row0];
        lpart[split * S + qbase + row0] = l_sm[row0];
        mpart[split * S + qbase + row1] = m_sm[row1];
        lpart[split * S + qbase + row1] = l_sm[row1];
    }
}

// ---------------- combine the 2 KV-split partials ----------------------------
__global__ void combine_kernel(const float* __restrict__ Opart,
                               const float* __restrict__ mpart,
                               const float* __restrict__ lpart,
                               float* __restrict__ av) {
    const int row = blockIdx.x, col = threadIdx.x;
    const float m0 = mpart[row], m1 = mpart[S + row];
    const float M = fmaxf(m0, m1);
    const float e0 = __expf(m0 - M), e1 = __expf(m1 - M);
    const float denom = e0 * lpart[row] + e1 * lpart[S + row];
    const float v = e0 * Opart[(size_t)row * HIDD + col]
                  + e1 * Opart[((size_t)S + row) * HIDD + col];
    av[(size_t)row * HIDD + col] = v / denom;
}

// ---------------- decoupling epilogue + per-row partial stats ----------------
__global__ void epilogue_kernel(float* __restrict__ att, const float* __restrict__ cidp,
                                double* __restrict__ psum, double* __restrict__ psq) {
    __shared__ float red[256], red2[256];
    int s = blockIdx.x;
    float* row = att + (size_t)s * CDIM;
    float dot = 0.f;
    for (int c = threadIdx.x; c < CDIM; c += 256) dot += row[c] * cidp[c];
    red[threadIdx.x] = dot; __syncthreads();
    for (int o = 128; o > 0; o >>= 1) {
        if (threadIdx.x < o) red[threadIdx.x] += red[threadIdx.x + o];
        __syncthreads();
    }
    float w = 1.f / (1.f + expf(-red[0]));
    __syncthreads();
    float ls = 0.f, lq = 0.f;
    for (int c = threadIdx.x; c < CDIM; c += 256) {
        float v = row[c] - w * cidp[c];
        row[c] = v;
        ls += v; lq += v * v;
    }
    red[threadIdx.x] = ls; red2[threadIdx.x] = lq; __syncthreads();
    for (int o = 128; o > 0; o >>= 1) {
        if (threadIdx.x < o) { red[threadIdx.x] += red[threadIdx.x + o]; red2[threadIdx.x] += red2[threadIdx.x + o]; }
        __syncthreads();
    }
    if (threadIdx.x == 0) { psum[s] = (double)red[0]; psq[s] = (double)red2[0]; }
}

// ---------------- global LN stats (deterministic, single block) --------------
__global__ void stats_kernel(const double* __restrict__ psum, const double* __restrict__ psq) {
    __shared__ double rs[1024], rq[1024];
    double s = 0.0, q = 0.0;
    for (int i = threadIdx.x; i < S; i += 1024) { s += psum[i]; q += psq[i]; }
    rs[threadIdx.x] = s; rq[threadIdx.x] = q; __syncthreads();
    for (int o = 512; o > 0; o >>= 1) {
        if (threadIdx.x < o) { rs[threadIdx.x] += rs[threadIdx.x + o]; rq[threadIdx.x] += rq[threadIdx.x + o]; }
        __syncthreads();
    }
    if (threadIdx.x == 0) {
        double n = (double)S * (double)CDIM;
        double mean = rs[0] / n;
        double var  = rq[0] / n - mean * mean;
        g_mean_f = (float)mean;
        g_rstd_f = (float)rsqrt(var + 1e-5);
    }
}

// ---------------- normalize + transpose back (S,C) -> (C,S) ------------------
__global__ void out_transpose_kernel(const float* __restrict__ af, float* __restrict__ out) {
    __shared__ float tile[32][33];
    float mean = g_mean_f, rstd = g_rstd_f;
    int c0 = blockIdx.x * 32, s0 = blockIdx.y * 32;
    #pragma unroll
    for (int i = threadIdx.y; i < 32; i += 8)
        tile[i][threadIdx.x] = af[(size_t)(s0 + i) * CDIM + c0 + threadIdx.x];
    __syncthreads();
    #pragma unroll
    for (int i = threadIdx.y; i < 32; i += 8)
        out[(size_t)(c0 + i) * S + s0 + threadIdx.x] = (tile[threadIdx.x][i] - mean) * rstd;
}

// ---------------- launch ------------------------------------------------------
extern "C" void kernel_launch(void* const* d_in, const int* in_sizes, int n_in,
                              void* d_out, int out_size) {
    const float* z      = (const float*)d_in[0];
    const float* cid    = (const float*)d_in[1];
    const float* mlp_w  = (const float*)d_in[2];
    const float* mlp_b  = (const float*)d_in[3];
    const float* proj_w = (const float*)d_in[4];
    const float* proj_b = (const float*)d_in[5];
    const float* wq_w   = (const float*)d_in[6];
    const float* wq_b   = (const float*)d_in[7];
    const float* wk_w   = (const float*)d_in[8];
    const float* wk_b   = (const float*)d_in[9];
    const float* wv_w   = (const float*)d_in[10];
    const float* wv_b   = (const float*)d_in[11];
    const float* wo_w   = (const float*)d_in[12];
    const float* wo_b   = (const float*)d_in[13];
    float* out = (float*)d_out;

    float *zt, *Q, *Km, *Vm, *iv, *cidp, *maskv, *qkvp, *Opart, *mpart, *lpart, *av, *att;
    double *psum, *psq;
    cudaGetSymbolAddress((void**)&zt,    g_zt);
    cudaGetSymbolAddress((void**)&Q,     g_Q);
    cudaGetSymbolAddress((void**)&Km,    g_Km);
    cudaGetSymbolAddress((void**)&Vm,    g_Vm);
    cudaGetSymbolAddress((void**)&iv,    g_iv);
    cudaGetSymbolAddress((void**)&cidp,  g_cidp);
    cudaGetSymbolAddress((void**)&maskv, g_maskv);
    cudaGetSymbolAddress((void**)&qkvp,  g_qkvp);
    cudaGetSymbolAddress((void**)&Opart, g_Opart);
    cudaGetSymbolAddress((void**)&mpart, g_mpart);
    cudaGetSymbolAddress((void**)&lpart, g_lpart);
    cudaGetSymbolAddress((void**)&av,    g_av);
    cudaGetSymbolAddress((void**)&att,   g_att);
    cudaGetSymbolAddress((void**)&psum,  g_psum);
    cudaGetSymbolAddress((void**)&psq,   g_psq);

    static int s_attr_set = 0;
    if (!s_attr_set) {
        cudaFuncSetAttribute(flash_kernel, cudaFuncAttributeMaxDynamicSharedMemorySize,
                             FLASH_SMEM_FLOATS * 4);
        s_attr_set = 1;
    }

    dim3 t32x8(32, 8);

    // 1. z (C,S) -> zt (S,C)
    transpose_zt_kernel<<<dim3(S / 32, CDIM / 32), t32x8>>>(z, zt);
    // 2. per-token LayerNorm over C
    ln_rows_kernel<<<S, 256>>>(zt);
    // 3. iv = mlp(cid); cidp = proj(cid)
    dual_matvec_kernel<<<HIDD + CDIM, 128>>>(mlp_w, mlp_b, proj_w, proj_b, cid, iv, cidp);
    // 4. QKV tf32 mma, split-K x4: grid (1,32,12)
    qkv_mma_kernel<<<dim3(1, S / 128, 12), 256>>>(zt, wq_w, wk_w, wv_w, qkvp);
    reduce_qkv_kernel<<<dim3(512, 3), 256>>>(qkvp, wq_b, wk_b, wv_b, Q, Km, Vm);
    // 5. mask
    mask_kernel<<<S, 128>>>(Km, iv, maskv);
    // 6. flash attention (fused QK^T * mask -> softmax -> P.V), 2 KV splits
    flash_kernel<<<dim3(S / 64, 2), 256, FLASH_SMEM_FLOATS * 4>>>(
        Q, Km, Vm, maskv, Opart, mpart, lpart);
    // 7. combine splits -> av
    combine_kernel<<<S, HIDD>>>(Opart, mpart, lpart, av);
    // 8. attended = av wo^T + wo_b: grid (10,32)
    gemm_mma_kernel<<<dim3(CDIM / 128, S / 128, 1), 256>>>(
        av, wo_w, wo_b, att, S, CDIM, HIDD, 1.f, HIDD);
    // 9. decoupling epilogue + partial stats
    epilogue_kernel<<<S, 256>>>(att, cidp, psum, psq);
    // 10. global LN stats
    stats_kernel<<<1, 1024>>>(psum, psq);
    // 11. normalize + transpose to (C,H,W)
    out_transpose_kernel<<<dim3(CDIM / 32, S / 32), t32x8>>>(att, out);
}

// round 8
// speedup vs baseline: 7.3469x; 1.3113x over previous
#include <cuda_runtime.h>
#include <cuda_bf16.h>
#include <math.h>
#include <stdint.h>

#define S     4096
#define CDIM  1280
#define HIDD  128
#define DID   1536
#define EPSV  1e-5f

// ---------------- scratch (static device globals; no allocations) ----------
__device__ float          g_zt  [(size_t)S * CDIM];      // fp32 transposed z
__device__ __nv_bfloat16  g_ztb [(size_t)S * CDIM];      // LN'd tokens, bf16
__device__ __nv_bfloat16  g_wqb [(size_t)HIDD * CDIM];
__device__ __nv_bfloat16  g_wkb [(size_t)HIDD * CDIM];
__device__ __nv_bfloat16  g_wvb [(size_t)HIDD * CDIM];
__device__ __nv_bfloat16  g_wob [(size_t)CDIM * HIDD];
__device__ float          g_Km  [(size_t)S * HIDD];      // fp32 K (for mask)
__device__ __nv_bfloat16  g_Qb  [(size_t)S * HIDD];
__device__ __nv_bfloat16  g_Kb  [(size_t)S * HIDD];
__device__ __nv_bfloat16  g_Vb  [(size_t)S * HIDD];
__device__ __nv_bfloat16  g_Vtb [(size_t)HIDD * S];
__device__ float          g_iv  [HIDD];
__device__ float          g_cidp[CDIM];
__device__ float          g_maskv[S];
__device__ float          g_qkvp[(size_t)12 * S * HIDD];
__device__ float          g_Opart[(size_t)4 * S * HIDD];
__device__ float          g_mpart[4 * S];
__device__ float          g_lpart[4 * S];
__device__ __nv_bfloat16  g_avb [(size_t)S * HIDD];
__device__ float          g_att [(size_t)S * CDIM];
__device__ double         g_psum[S];
__device__ double         g_psq [S];
__device__ float          g_mean_f;
__device__ float          g_rstd_f;

// ---------------- helpers ----------------------------------------------------
__device__ __forceinline__ void cp16(void* dst, const void* src) {
    uint32_t d = (uint32_t)__cvta_generic_to_shared(dst);
    asm volatile("cp.async.cg.shared.global [%0], [%1], 16;\n" :: "r"(d), "l"(src));
}
#define CP_COMMIT() asm volatile("cp.async.commit_group;\n" ::: "memory")
#define CP_WAIT1()  asm volatile("cp.async.wait_group 1;\n" ::: "memory")

__device__ __forceinline__ void mma_bf16(float* d,
        uint32_t a0, uint32_t a1, uint32_t a2, uint32_t a3,
        uint32_t b0, uint32_t b1) {
    asm volatile(
        "mma.sync.aligned.m16n8k16.row.col.f32.bf16.bf16.f32 "
        "{%0,%1,%2,%3}, {%4,%5,%6,%7}, {%8,%9}, {%0,%1,%2,%3};"
        : "+f"(d[0]), "+f"(d[1]), "+f"(d[2]), "+f"(d[3])
        : "r"(a0), "r"(a1), "r"(a2), "r"(a3), "r"(b0), "r"(b1));
}

__device__ __forceinline__ uint32_t pack_bf16(float x, float y) {
    __nv_bfloat162 t = __floats2bfloat162_rn(x, y);
    return *reinterpret_cast<uint32_t*>(&t);
}

// ---------------- transpose z (C,S) -> zt (S,C) ----------------------------
__global__ void transpose_zt_kernel(const float* __restrict__ z, float* __restrict__ zt) {
    __shared__ float tile[32][33];
    int s0 = blockIdx.x * 32, c0 = blockIdx.y * 32;
    #pragma unroll
    for (int i = threadIdx.y; i < 32; i += 8)
        tile[i][threadIdx.x] = z[(size_t)(c0 + i) * S + s0 + threadIdx.x];
    __syncthreads();
    #pragma unroll
    for (int i = threadIdx.y; i < 32; i += 8)
        zt[(size_t)(s0 + i) * CDIM + c0 + threadIdx.x] = tile[threadIdx.x][i];
}

// ---------------- row LayerNorm over C -> bf16 out ---------------------------
__global__ void ln_rows_kernel(const float* __restrict__ x, __nv_bfloat16* __restrict__ xb) {
    __shared__ float rs[256], rq[256];
    int row = blockIdx.x;
    const float4* p = (const float4*)(x + (size_t)row * CDIM);
    float s = 0.f, q = 0.f;
    for (int i = threadIdx.x; i < CDIM / 4; i += 256) {
        float4 v = p[i];
        s += v.x + v.y + v.z + v.w;
        q += v.x * v.x + v.y * v.y + v.z * v.z + v.w * v.w;
    }
    rs[threadIdx.x] = s; rq[threadIdx.x] = q; __syncthreads();
    for (int o = 128; o > 0; o >>= 1) {
        if (threadIdx.x < o) { rs[threadIdx.x] += rs[threadIdx.x + o]; rq[threadIdx.x] += rq[threadIdx.x + o]; }
        __syncthreads();
    }
    float mean = rs[0] / CDIM;
    float var  = rq[0] / CDIM - mean * mean;
    float rstd = rsqrtf(var + EPSV);
    uint32_t* ob = (uint32_t*)(xb + (size_t)row * CDIM);
    for (int i = threadIdx.x; i < CDIM / 4; i += 256) {
        float4 v = p[i];
        ob[i * 2]     = pack_bf16((v.x - mean) * rstd, (v.y - mean) * rstd);
        ob[i * 2 + 1] = pack_bf16((v.z - mean) * rstd, (v.w - mean) * rstd);
    }
}

// ---------------- convert weights to bf16 ------------------------------------
__global__ void convw_kernel(const float* __restrict__ wq, const float* __restrict__ wk,
                             const float* __restrict__ wv, const float* __restrict__ wo,
                             __nv_bfloat16* qb, __nv_bfloat16* kb,
                             __nv_bfloat16* vb, __nv_bfloat16* ob) {
    int i = blockIdx.x * 1024 + threadIdx.x;   // 160 blocks x 1024 = 163840
    const float* src; __nv_bfloat16* dst;
    if (blockIdx.y == 0)      { src = wq; dst = qb; }
    else if (blockIdx.y == 1) { src = wk; dst = kb; }
    else if (blockIdx.y == 2) { src = wv; dst = vb; }
    else                      { src = wo; dst = ob; }
    dst[i] = __float2bfloat16(src[i]);
}

// ---------------- iv = mlp(cid), cidp = proj(cid) ---------------------------
__global__ void dual_matvec_kernel(const float* __restrict__ w1, const float* __restrict__ b1,
                                   const float* __restrict__ w2, const float* __restrict__ b2,
                                   const float* __restrict__ x,
                                   float* __restrict__ o1, float* __restrict__ o2) {
    __shared__ float sm[128];
    int n = blockIdx.x;
    const float* w; float bv; float* o; int nn;
    if (n < HIDD) { nn = n;        w = w1 + (size_t)nn * DID; bv = b1[nn]; o = o1; }
    else          { nn = n - HIDD; w = w2 + (size_t)nn * DID; bv = b2[nn]; o = o2; }
    float s = 0.f;
    for (int k = threadIdx.x; k < DID; k += 128) s += w[k] * x[k];
    sm[threadIdx.x] = s; __syncthreads();
    for (int off = 64; off > 0; off >>= 1) {
        if (threadIdx.x < off) sm[threadIdx.x] += sm[threadIdx.x + off];
        __syncthreads();
    }
    if (threadIdx.x == 0) o[nn] = sm[0] + bv;
}

// ---------------- bf16 mma GEMM engine (128x128, BT, cp.async 2-stage) -------
// A: (M,K) bf16 row-major; B: (N,K) bf16 row-major. fp32 accumulate/output.
__device__ __forceinline__ void bf16_gemm_body(
        const __nv_bfloat16* __restrict__ A, const __nv_bfloat16* __restrict__ B,
        const float* __restrict__ bias, float* __restrict__ C,
        int N, int K, int kstart, int nkt, int m0, int n0) {
    __shared__ uint32_t As[2][128][12];   // [row][k-pair], 8 data + 4 pad
    __shared__ uint32_t Bs[2][128][12];

    const int tid  = threadIdx.x;
    const int lane = tid & 31, wid = tid >> 5;
    const int g    = lane >> 2, tig = lane & 3;
    const int wm   = (wid >> 2) * 64;
    const int wn   = (wid & 3) * 32;

    const int fr = tid >> 1, fc = (tid & 1);   // fill: row, 16B-chunk (8 bf16)

    float acc[4][4][4] = {};

    auto fill = [&](int s, int k0) {
        cp16(&As[s][fr][fc * 4], A + (size_t)(m0 + fr) * K + k0 + fc * 8);
        cp16(&Bs[s][fr][fc * 4], B + (size_t)(n0 + fr) * K + k0 + fc * 8);
    };

    fill(0, kstart);
    CP_COMMIT();

    for (int t = 0; t < nkt; t++) {
        const int st = t & 1;
        if (t + 1 < nkt) fill(st ^ 1, kstart + (t + 1) * 16);
        CP_COMMIT();
        CP_WAIT1();
        __syncthreads();

        uint32_t a[4][4], b[4][2];
        #pragma unroll
        for (int mf = 0; mf < 4; mf++) {
            a[mf][0] = As[st][wm + mf * 16 + g    ][tig];
            a[mf][1] = As[st][wm + mf * 16 + g + 8][tig];
            a[mf][2] = As[st][wm + mf * 16 + g    ][tig + 4];
            a[mf][3] = As[st][wm + mf * 16 + g + 8][tig + 4];
        }
        #pragma unroll
        for (int nf = 0; nf < 4; nf++) {
            b[nf][0] = Bs[st][wn + nf * 8 + g][tig];
            b[nf][1] = Bs[st][wn + nf * 8 + g][tig + 4];
        }
        #pragma unroll
        for (int mf = 0; mf < 4; mf++)
            #pragma unroll
            for (int nf = 0; nf < 4; nf++)
                mma_bf16(acc[mf][nf], a[mf][0], a[mf][1], a[mf][2], a[mf][3],
                         b[nf][0], b[nf][1]);
        __syncthreads();
    }

    #pragma unroll
    for (int mf = 0; mf < 4; mf++) {
        #pragma unroll
        for (int nf = 0; nf < 4; nf++) {
            const int r0 = m0 + wm + mf * 16 + g;
            const int c  = n0 + wn + nf * 8 + 2 * tig;
            float2 v0 = make_float2(acc[mf][nf][0], acc[mf][nf][1]);
            float2 v1 = make_float2(acc[mf][nf][2], acc[mf][nf][3]);
            if (bias) {
                float b0 = bias[c], b1 = bias[c + 1];
                v0.x += b0; v0.y += b1; v1.x += b0; v1.y += b1;
            }
            *(float2*)&C[(size_t)r0 * N + c]       = v0;
            *(float2*)&C[(size_t)(r0 + 8) * N + c] = v1;
        }
    }
}

// Fused QKV split-K: grid (1, 32, 12); z = which*4 + split.
__global__ __launch_bounds__(256, 2)
void qkv_mma_kernel(const __nv_bfloat16* __restrict__ A,
                    const __nv_bfloat16* __restrict__ wq, const __nv_bfloat16* __restrict__ wk,
                    const __nv_bfloat16* __restrict__ wv, float* __restrict__ qkvp) {
    const int which = blockIdx.z >> 2;
    const int split = blockIdx.z & 3;
    const __nv_bfloat16* B = (which == 0) ? wq : (which == 1) ? wk : wv;
    float* out = qkvp + (size_t)blockIdx.z * S * HIDD;
    bf16_gemm_body(A, B, nullptr, out, HIDD, CDIM, split * 320, 20,
                   blockIdx.y * 128, blockIdx.x * 128);
}

// WO GEMM: grid (10, 32).
__global__ __launch_bounds__(256, 2)
void wo_mma_kernel(const __nv_bfloat16* __restrict__ A, const __nv_bfloat16* __restrict__ B,
                   const float* __restrict__ bias, float* __restrict__ C) {
    bf16_gemm_body(A, B, bias, C, CDIM, HIDD, 0, 8, blockIdx.y * 128, blockIdx.x * 128);
}

// Reduce QKV partials (+bias) -> bf16 Q/K/V (+ fp32 K). grid (512, 3), 256 thr.
__global__ void reduce_qkv_kernel(const float* __restrict__ qkvp,
                                  const float* __restrict__ bq, const float* __restrict__ bk,
                                  const float* __restrict__ bv,
                                  __nv_bfloat16* __restrict__ Qb, __nv_bfloat16* __restrict__ Kb,
                                  float* __restrict__ Kf, __nv_bfloat16* __restrict__ Vb) {
    const size_t MN = (size_t)S * HIDD;
    const int which = blockIdx.y;
    size_t i = ((size_t)blockIdx.x * 256 + threadIdx.x) * 4;
    const float* base = qkvp + (size_t)which * 4 * MN;
    float4 a = *(const float4*)&base[i];
    float4 b = *(const float4*)&base[MN + i];
    float4 c = *(const float4*)&base[2 * MN + i];
    float4 d = *(const float4*)&base[3 * MN + i];
    const float* bias = (which == 0) ? bq : (which == 1) ? bk : bv;
    float4 bb = *(const float4*)&bias[i & 127];
    float4 r;
    r.x = a.x + b.x + c.x + d.x + bb.x;
    r.y = a.y + b.y + c.y + d.y + bb.y;
    r.z = a.z + b.z + c.z + d.z + bb.z;
    r.w = a.w + b.w + c.w + d.w + bb.w;
    uint2 packed;
    packed.x = pack_bf16(r.x, r.y);
    packed.y = pack_bf16(r.z, r.w);
    if (which == 0)      { *(uint2*)&Qb[i] = packed; }
    else if (which == 1) { *(uint2*)&Kb[i] = packed; *(float4*)&Kf[i] = r; }
    else                 { *(uint2*)&Vb[i] = packed; }
}

// ---------------- V transpose (S,HID) -> (HID,S) bf16 ------------------------
__global__ void vtrans_kernel(const __nv_bfloat16* __restrict__ Vb,
                              __nv_bfloat16* __restrict__ Vtb) {
    __shared__ __nv_bfloat16 tile[32][34];
    int s0 = blockIdx.x * 32, d0 = blockIdx.y * 32;
    #pragma unroll
    for (int i = threadIdx.y; i < 32; i += 8)
        tile[i][threadIdx.x] = Vb[(size_t)(s0 + i) * HIDD + d0 + threadIdx.x];
    __syncthreads();
    #pragma unroll
    for (int i = threadIdx.y; i < 32; i += 8)
        Vtb[(size_t)(d0 + i) * S + s0 + threadIdx.x] = tile[threadIdx.x][i];
}

// ---------------- mask[k] = sigmoid(iv . K[k])  (fp32 K) ---------------------
__global__ void mask_kernel(const float* __restrict__ Kmat, const float* __restrict__ iv,
                            float* __restrict__ mask) {
    __shared__ float sm[128];
    int k = blockIdx.x;
    float v = iv[threadIdx.x] * Kmat[(size_t)k * HIDD + threadIdx.x];
    sm[threadIdx.x] = v; __syncthreads();
    for (int o = 64; o > 0; o >>= 1) {
        if (threadIdx.x < o) sm[threadIdx.x] += sm[threadIdx.x + o];
        __syncthreads();
    }
    if (threadIdx.x == 0) mask[k] = 1.f / (1.f + expf(-sm[0]));
}

// ---------------- flash attention, bf16 mma ----------------------------------
// Grid (S/64, 4). Each CTA: 64 q-rows, one KV quarter (1024 keys, 16 tiles of 64).
// smem (u32 units): Qs[64][68], KsB 2x[64][68], VTsB 2x[128][36], Ps[64][36],
//                   msk 2x64f, maxb 2x64f, sumb 2x64f, m 64f, l 64f
#define FLASH_SMEM_BYTES (25088 * 4)
__global__ void __launch_bounds__(256, 2)
flash_kernel(const __nv_bfloat16* __restrict__ Qb, const __nv_bfloat16* __restrict__ Kb,
             const __nv_bfloat16* __restrict__ Vtb, const float* __restrict__ maskv,
             float* __restrict__ Opart, float* __restrict__ mpart,
             float* __restrict__ lpart) {
    extern __shared__ uint32_t smu[];
    uint32_t* Qs   = smu;               // 64*68   = 4352
    uint32_t* KsB  = smu + 4352;        // 2*4352  = 8704
    uint32_t* VTsB = smu + 13056;       // 2*4608  = 9216
    uint32_t* Ps   = smu + 22272;       // 64*36   = 2304
    float* msk  = (float*)(smu + 24576);
    float* maxb = (float*)(smu + 24704);
    float* sumb = (float*)(smu + 24832);
    float* m_sm = (float*)(smu + 24960);
    float* l_sm = (float*)(smu + 25024);

    const int tid  = threadIdx.x;
    const int lane = tid & 31, w = tid >> 5;
    const int g    = lane >> 2, tig = lane & 3;
    const int wm   = (w & 3) * 16;
    const int wns  = (w >> 2) * 32;
    const int wno  = (w >> 2) * 64;
    const int wgrp = w >> 2;

    const int qbase  = blockIdx.x * 64;
    const int split  = blockIdx.y;
    const int kstart = split * (S / 4);
    const int NT     = (S / 4) / 64;    // 16

    if (tid < 64) { m_sm[tid] = -1e30f; l_sm[tid] = 0.f; }

    // K tile: 64 keys x 128 d bf16 (16 chunks/row); VT tile: 128 d x 64 keys (8 chunks/row)
    auto fillKV = [&](int st, int kb) {
        #pragma unroll
        for (int i = 0; i < 4; i++) {
            int ci = i * 256 + tid;                       // 0..1023
            int kr = ci >> 4, kch = (ci & 15);
            cp16(KsB + st * 4352 + kr * 68 + kch * 4,
                 Kb + (size_t)(kb + kr) * HIDD + kch * 8);
            int vr = ci >> 3, vch = (ci & 7);
            cp16(VTsB + st * 4608 + vr * 36 + vch * 4,
                 Vtb + (size_t)vr * S + kb + vch * 8);
        }
        if (tid < 16) cp16(msk + st * 64 + tid * 4, maskv + kb + tid * 4);
    };

    // prologue: Q + stage 0
    #pragma unroll
    for (int i = 0; i < 4; i++) {
        int ci = i * 256 + tid;
        int r = ci >> 4, ch = (ci & 15);
        cp16(Qs + r * 68 + ch * 4, Qb + (size_t)(qbase + r) * HIDD + ch * 8);
    }
    fillKV(0, kstart);
    CP_COMMIT();

    float o_acc[8][4] = {};
    const int row0 = wm + g, row1 = wm + g + 8;

    for (int t = 0; t < NT; t++) {
        const int st = t & 1;
        if (t + 1 < NT) fillKV(st ^ 1, kstart + (t + 1) * 64);
        CP_COMMIT();
        CP_WAIT1();
        __syncthreads();

        const uint32_t* Ks  = KsB + st * 4352;
        const uint32_t* VTs = VTsB + st * 4608;
        const float* mk = msk + st * 64;

        // --- scores = Q . K^T  (8 ktiles of 16) ---
        float s_acc[4][4] = {};
        #pragma unroll
        for (int kt = 0; kt < 8; kt++) {
            const int kb8 = kt * 8;
            uint32_t a0 = Qs[row0 * 68 + kb8 + tig];
            uint32_t a1 = Qs[row1 * 68 + kb8 + tig];
            uint32_t a2 = Qs[row0 * 68 + kb8 + tig + 4];
            uint32_t a3 = Qs[row1 * 68 + kb8 + tig + 4];
            #pragma unroll
            for (int nf = 0; nf < 4; nf++) {
                const int kr = wns + nf * 8 + g;
                uint32_t b0 = Ks[kr * 68 + kb8 + tig];
                uint32_t b1 = Ks[kr * 68 + kb8 + tig + 4];
                mma_bf16(s_acc[nf], a0, a1, a2, a3, b0, b1);
            }
        }

        // --- scale + mask, row max ---
        float rmax0 = -1e30f, rmax1 = -1e30f;
        #pragma unroll
        for (int nf = 0; nf < 4; nf++) {
            const int cc = wns + nf * 8 + 2 * tig;
            const float mk0 = mk[cc] * 0.015625f, mk1 = mk[cc + 1] * 0.015625f;
            s_acc[nf][0] *= mk0; s_acc[nf][1] *= mk1;
            s_acc[nf][2] *= mk0; s_acc[nf][3] *= mk1;
            rmax0 = fmaxf(rmax0, fmaxf(s_acc[nf][0], s_acc[nf][1]));
            rmax1 = fmaxf(rmax1, fmaxf(s_acc[nf][2], s_acc[nf][3]));
        }
        #pragma unroll
        for (int o = 1; o <= 2; o <<= 1) {
            rmax0 = fmaxf(rmax0, __shfl_xor_sync(0xffffffffu, rmax0, o));
            rmax1 = fmaxf(rmax1, __shfl_xor_sync(0xffffffffu, rmax1, o));
        }
        if (tig == 0) { maxb[wgrp * 64 + row0] = rmax0; maxb[wgrp * 64 + row1] = rmax1; }
        __syncthreads();

        // --- online softmax update ---
        const float mp0 = m_sm[row0], mp1 = m_sm[row1];
        const float mn0 = fmaxf(mp0, fmaxf(maxb[row0], maxb[64 + row0]));
        const float mn1 = fmaxf(mp1, fmaxf(maxb[row1], maxb[64 + row1]));
        const float c0f = __expf(mp0 - mn0), c1f = __expf(mp1 - mn1);

        float ps0 = 0.f, ps1 = 0.f;
        #pragma unroll
        for (int nf = 0; nf < 4; nf++) {
            const float p0 = __expf(s_acc[nf][0] - mn0);
            const float p1 = __expf(s_acc[nf][1] - mn0);
            const float p2 = __expf(s_acc[nf][2] - mn1);
            const float p3 = __expf(s_acc[nf][3] - mn1);
            ps0 += p0 + p1; ps1 += p2 + p3;
            const int pc = (wns >> 1) + nf * 4 + tig;    // u32 column
            Ps[row0 * 36 + pc] = pack_bf16(p0, p1);
            Ps[row1 * 36 + pc] = pack_bf16(p2, p3);
        }
        #pragma unroll
        for (int o = 1; o <= 2; o <<= 1) {
            ps0 += __shfl_xor_sync(0xffffffffu, ps0, o);
            ps1 += __shfl_xor_sync(0xffffffffu, ps1, o);
        }
        if (tig == 0) { sumb[wgrp * 64 + row0] = ps0; sumb[wgrp * 64 + row1] = ps1; }

        #pragma unroll
        for (int nf = 0; nf < 8; nf++) {
            o_acc[nf][0] *= c0f; o_acc[nf][1] *= c0f;
            o_acc[nf][2] *= c1f; o_acc[nf][3] *= c1f;
        }
        __syncthreads();

        if (w < 4 && tig == 0) {
            l_sm[row0] = l_sm[row0] * c0f + sumb[row0] + sumb[64 + row0];
            m_sm[row0] = mn0;
            l_sm[row1] = l_sm[row1] * c1f + sumb[row1] + sumb[64 + row1];
            m_sm[row1] = mn1;
        }

        // --- O += P . V  (4 ktiles of 16 keys) ---
        #pragma unroll
        for (int kt = 0; kt < 4; kt++) {
            const int kb8 = kt * 8;
            uint32_t a0 = Ps[row0 * 36 + kb8 + tig];
            uint32_t a1 = Ps[row1 * 36 + kb8 + tig];
            uint32_t a2 = Ps[row0 * 36 + kb8 + tig + 4];
            uint32_t a3 = Ps[row1 * 36 + kb8 + tig + 4];
            #pragma unroll
            for (int nf = 0; nf < 8; nf++) {
                const int cn = wno + nf * 8 + g;
                uint32_t b0 = VTs[cn * 36 + kb8 + tig];
                uint32_t b1 = VTs[cn * 36 + kb8 + tig + 4];
                mma_bf16(o_acc[nf], a0, a1, a2, a3, b0, b1);
            }
        }
        __syncthreads();
    }

    // epilogue: unnormalized partials
    float* Ob = Opart + ((size_t)split * S + qbase) * HIDD;
    #pragma unroll
    for (int nf = 0; nf < 8; nf++) {
        const int cc = wno + nf * 8 + 2 * tig;
        *(float2*)&Ob[(size_t)row0 * HIDD + cc] = make_float2(o_acc[nf][0], o_acc[nf][1]);
        *(float2*)&Ob[(size_t)row1 * HIDD + cc] = make_float2(o_acc[nf][2], o_acc[nf][3]);
    }
    if (w < 4 && tig == 0) {
        mpart[split * S + qbase + row0] = m_sm[row0];
        lpart[split * S + qbase + row0] = l_sm[row0];
        mpart[split * S + qbase + row1] = m_sm[row1];
        lpart[split * S + qbase + row1] = l_sm[row1];
    }
}

// ---------------- combine the 4 KV-split partials -> bf16 av -----------------
__global__ void combine_kernel(const float* __restrict__ Opart,
                               const float* __restrict__ mpart,
                               const float* __restrict__ lpart,
                               __nv_bfloat16* __restrict__ avb) {
    const int row = blockIdx.x, col = threadIdx.x;
    float M = -1e30f;
    #pragma unroll
    for (int z = 0; z < 4; z++) M = fmaxf(M, mpart[z * S + row]);
    float denom = 0.f, v = 0.f;
    #pragma unroll
    for (int z = 0; z < 4; z++) {
        const float e = __expf(mpart[z * S + row] - M);
        denom += e * lpart[z * S + row];
        v     += e * Opart[((size_t)z * S + row) * HIDD + col];
    }
    avb[(size_t)row * HIDD + col] = __float2bfloat16(v / denom);
}

// ---------------- decoupling epilogue + per-row partial stats ----------------
__global__ void epilogue_kernel(float* __restrict__ att, const float* __restrict__ cidp,
                                double* __restrict__ psum, double* __restrict__ psq) {
    __shared__ float red[256], red2[256];
    int s = blockIdx.x;
    float* row = att + (size_t)s * CDIM;
    float dot = 0.f;
    for (int c = threadIdx.x; c < CDIM; c += 256) dot += row[c] * cidp[c];
    red[threadIdx.x] = dot; __syncthreads();
    for (int o = 128; o > 0; o >>= 1) {
        if (threadIdx.x < o) red[threadIdx.x] += red[threadIdx.x + o];
        __syncthreads();
    }
    float w = 1.f / (1.f + expf(-red[0]));
    __syncthreads();
    float ls = 0.f, lq = 0.f;
    for (int c = threadIdx.x; c < CDIM; c += 256) {
        float v = row[c] - w * cidp[c];
        row[c] = v;
        ls += v; lq += v * v;
    }
    red[threadIdx.x] = ls; red2[threadIdx.x] = lq; __syncthreads();
    for (int o = 128; o > 0; o >>= 1) {
        if (threadIdx.x < o) { red[threadIdx.x] += red[threadIdx.x + o]; red2[threadIdx.x] += red2[threadIdx.x + o]; }
        __syncthreads();
    }
    if (threadIdx.x == 0) { psum[s] = (double)red[0]; psq[s] = (double)red2[0]; }
}

// ---------------- global LN stats (deterministic, single block) --------------
__global__ void stats_kernel(const double* __restrict__ psum, const double* __restrict__ psq) {
    __shared__ double rs[1024], rq[1024];
    double s = 0.0, q = 0.0;
    for (int i = threadIdx.x; i < S; i += 1024) { s += psum[i]; q += psq[i]; }
    rs[threadIdx.x] = s; rq[threadIdx.x] = q; __syncthreads();
    for (int o = 512; o > 0; o >>= 1) {
        if (threadIdx.x < o) { rs[threadIdx.x] += rs[threadIdx.x + o]; rq[threadIdx.x] += rq[threadIdx.x + o]; }
        __syncthreads();
    }
    if (threadIdx.x == 0) {
        double n = (double)S * (double)CDIM;
        double mean = rs[0] / n;
        double var  = rq[0] / n - mean * mean;
        g_mean_f = (float)mean;
        g_rstd_f = (float)rsqrt(var + 1e-5);
    }
}

// ---------------- normalize + transpose back (S,C) -> (C,S) ------------------
__global__ void out_transpose_kernel(const float* __restrict__ af, float* __restrict__ out) {
    __shared__ float tile[32][33];
    float mean = g_mean_f, rstd = g_rstd_f;
    int c0 = blockIdx.x * 32, s0 = blockIdx.y * 32;
    #pragma unroll
    for (int i = threadIdx.y; i < 32; i += 8)
        tile[i][threadIdx.x] = af[(size_t)(s0 + i) * CDIM + c0 + threadIdx.x];
    __syncthreads();
    #pragma unroll
    for (int i = threadIdx.y; i < 32; i += 8)
        out[(size_t)(c0 + i) * S + s0 + threadIdx.x] = (tile[threadIdx.x][i] - mean) * rstd;
}

// ---------------- launch ------------------------------------------------------
extern "C" void kernel_launch(void* const* d_in, const int* in_sizes, int n_in,
                              void* d_out, int out_size) {
    const float* z      = (const float*)d_in[0];
    const float* cid    = (const float*)d_in[1];
    const float* mlp_w  = (const float*)d_in[2];
    const float* mlp_b  = (const float*)d_in[3];
    const float* proj_w = (const float*)d_in[4];
    const float* proj_b = (const float*)d_in[5];
    const float* wq_w   = (const float*)d_in[6];
    const float* wq_b   = (const float*)d_in[7];
    const float* wk_w   = (const float*)d_in[8];
    const float* wk_b   = (const float*)d_in[9];
    const float* wv_w   = (const float*)d_in[10];
    const float* wv_b   = (const float*)d_in[11];
    const float* wo_w   = (const float*)d_in[12];
    const float* wo_b   = (const float*)d_in[13];
    float* out = (float*)d_out;

    float *zt, *Kf, *iv, *cidp, *maskv, *qkvp, *Opart, *mpart, *lpart, *att;
    __nv_bfloat16 *ztb, *wqb, *wkb, *wvb, *wob, *Qb, *Kb, *Vb, *Vtb, *avb;
    double *psum, *psq;
    cudaGetSymbolAddress((void**)&zt,    g_zt);
    cudaGetSymbolAddress((void**)&ztb,   g_ztb);
    cudaGetSymbolAddress((void**)&wqb,   g_wqb);
    cudaGetSymbolAddress((void**)&wkb,   g_wkb);
    cudaGetSymbolAddress((void**)&wvb,   g_wvb);
    cudaGetSymbolAddress((void**)&wob,   g_wob);
    cudaGetSymbolAddress((void**)&Kf,    g_Km);
    cudaGetSymbolAddress((void**)&Qb,    g_Qb);
    cudaGetSymbolAddress((void**)&Kb,    g_Kb);
    cudaGetSymbolAddress((void**)&Vb,    g_Vb);
    cudaGetSymbolAddress((void**)&Vtb,   g_Vtb);
    cudaGetSymbolAddress((void**)&iv,    g_iv);
    cudaGetSymbolAddress((void**)&cidp,  g_cidp);
    cudaGetSymbolAddress((void**)&maskv, g_maskv);
    cudaGetSymbolAddress((void**)&qkvp,  g_qkvp);
    cudaGetSymbolAddress((void**)&Opart, g_Opart);
    cudaGetSymbolAddress((void**)&mpart, g_mpart);
    cudaGetSymbolAddress((void**)&lpart, g_lpart);
    cudaGetSymbolAddress((void**)&avb,   g_avb);
    cudaGetSymbolAddress((void**)&att,   g_att);
    cudaGetSymbolAddress((void**)&psum,  g_psum);
    cudaGetSymbolAddress((void**)&psq,   g_psq);

    static int s_attr_set = 0;
    if (!s_attr_set) {
        cudaFuncSetAttribute(flash_kernel, cudaFuncAttributeMaxDynamicSharedMemorySize,
                             FLASH_SMEM_BYTES);
        s_attr_set = 1;
    }

    dim3 t32x8(32, 8);

    // 1. z (C,S) -> zt (S,C) fp32
    transpose_zt_kernel<<<dim3(S / 32, CDIM / 32), t32x8>>>(z, zt);
    // 2. per-token LayerNorm over C -> bf16 tokens
    ln_rows_kernel<<<S, 256>>>(zt, ztb);
    // 3. weights -> bf16
    convw_kernel<<<dim3(160, 4), 1024>>>(wq_w, wk_w, wv_w, wo_w, wqb, wkb, wvb, wob);
    // 4. iv = mlp(cid); cidp = proj(cid)
    dual_matvec_kernel<<<HIDD + CDIM, 128>>>(mlp_w, mlp_b, proj_w, proj_b, cid, iv, cidp);
    // 5. QKV bf16 mma, split-K x4: grid (1,32,12)
    qkv_mma_kernel<<<dim3(1, S / 128, 12), 256>>>(ztb, wqb, wkb, wvb, qkvp);
    reduce_qkv_kernel<<<dim3(512, 3), 256>>>(qkvp, wq_b, wk_b, wv_b, Qb, Kb, Kf, Vb);
    // 6. V transpose (for PV mma B operand)
    vtrans_kernel<<<dim3(S / 32, HIDD / 32), t32x8>>>(Vb, Vtb);
    // 7. mask (fp32 K)
    mask_kernel<<<S, 128>>>(Kf, iv, maskv);
    // 8. flash attention, 4 KV splits: grid (64,4) = 256 CTAs, 2 CTAs/SM
    flash_kernel<<<dim3(S / 64, 4), 256, FLASH_SMEM_BYTES>>>(
        Qb, Kb, Vtb, maskv, Opart, mpart, lpart);
    // 9. combine splits -> bf16 av
    combine_kernel<<<S, HIDD>>>(Opart, mpart, lpart, avb);
    // 10. attended = av wo^T + wo_b: grid (10,32)
    wo_mma_kernel<<<dim3(CDIM / 128, S / 128), 256>>>(avb, wob, wo_b, att);
    // 11. decoupling epilogue + partial stats
    epilogue_kernel<<<S, 256>>>(att, cidp, psum, psq);
    // 12. global LN stats
    stats_kernel<<<1, 1024>>>(psum, psq);
    // 13. normalize + transpose to (C,H,W)
    out_transpose_kernel<<<dim3(CDIM / 32, S / 32), t32x8>>>(att, out);
}

// round 9
// speedup vs baseline: 7.9184x; 1.0778x over previous
#include <cuda_runtime.h>
#include <cuda_bf16.h>
#include <math.h>
#include <stdint.h>

#define S     4096
#define CDIM  1280
#define HIDD  128
#define DID   1536
#define EPSV  1e-5f

// ---------------- scratch (static device globals; no allocations) ----------
__device__ float          g_zt  [(size_t)S * CDIM];
__device__ __nv_bfloat16  g_ztb [(size_t)S * CDIM];
__device__ __nv_bfloat16  g_wqb [(size_t)HIDD * CDIM];
__device__ __nv_bfloat16  g_wkb [(size_t)HIDD * CDIM];
__device__ __nv_bfloat16  g_wvb [(size_t)HIDD * CDIM];
__device__ __nv_bfloat16  g_wob [(size_t)CDIM * HIDD];
__device__ float          g_Km  [(size_t)S * HIDD];
__device__ __nv_bfloat16  g_Qb  [(size_t)S * HIDD];
__device__ __nv_bfloat16  g_Kb  [(size_t)S * HIDD];
__device__ __nv_bfloat16  g_Vb  [(size_t)S * HIDD];
__device__ __nv_bfloat16  g_Vtb [(size_t)HIDD * S];
__device__ float          g_iv  [HIDD];
__device__ float          g_cidp[CDIM];
__device__ float          g_maskv[S];
__device__ float          g_qkvp[(size_t)12 * S * HIDD];
__device__ float          g_Opart[(size_t)4 * S * HIDD];
__device__ float          g_mpart[4 * S];
__device__ float          g_lpart[4 * S];
__device__ __nv_bfloat16  g_avb [(size_t)S * HIDD];
__device__ float          g_att [(size_t)S * CDIM];
__device__ double         g_psum[S];
__device__ double         g_psq [S];
__device__ float          g_mean_f;
__device__ float          g_rstd_f;

// ---------------- helpers ----------------------------------------------------
__device__ __forceinline__ void cp16(void* dst, const void* src) {
    uint32_t d = (uint32_t)__cvta_generic_to_shared(dst);
    asm volatile("cp.async.cg.shared.global [%0], [%1], 16;\n" :: "r"(d), "l"(src));
}
#define CP_COMMIT() asm volatile("cp.async.commit_group;\n" ::: "memory")
#define CP_WAIT1()  asm volatile("cp.async.wait_group 1;\n" ::: "memory")

__device__ __forceinline__ uint32_t saddr(const void* p) {
    return (uint32_t)__cvta_generic_to_shared(p);
}

__device__ __forceinline__ void ldsm_x4(uint32_t& r0, uint32_t& r1, uint32_t& r2,
                                        uint32_t& r3, uint32_t a) {
    asm volatile("ldmatrix.sync.aligned.m8n8.x4.shared.b16 {%0,%1,%2,%3}, [%4];"
                 : "=r"(r0), "=r"(r1), "=r"(r2), "=r"(r3) : "r"(a));
}

__device__ __forceinline__ void mma_bf16(float* d,
        uint32_t a0, uint32_t a1, uint32_t a2, uint32_t a3,
        uint32_t b0, uint32_t b1) {
    asm volatile(
        "mma.sync.aligned.m16n8k16.row.col.f32.bf16.bf16.f32 "
        "{%0,%1,%2,%3}, {%4,%5,%6,%7}, {%8,%9}, {%0,%1,%2,%3};"
        : "+f"(d[0]), "+f"(d[1]), "+f"(d[2]), "+f"(d[3])
        : "r"(a0), "r"(a1), "r"(a2), "r"(a3), "r"(b0), "r"(b1));
}

__device__ __forceinline__ uint32_t pack_bf16(float x, float y) {
    __nv_bfloat162 t = __floats2bfloat162_rn(x, y);
    return *reinterpret_cast<uint32_t*>(&t);
}

// ---------------- transpose z (C,S) -> zt (S,C) ----------------------------
__global__ void transpose_zt_kernel(const float* __restrict__ z, float* __restrict__ zt) {
    __shared__ float tile[32][33];
    int s0 = blockIdx.x * 32, c0 = blockIdx.y * 32;
    #pragma unroll
    for (int i = threadIdx.y; i < 32; i += 8)
        tile[i][threadIdx.x] = z[(size_t)(c0 + i) * S + s0 + threadIdx.x];
    __syncthreads();
    #pragma unroll
    for (int i = threadIdx.y; i < 32; i += 8)
        zt[(size_t)(s0 + i) * CDIM + c0 + threadIdx.x] = tile[threadIdx.x][i];
}

// ---------------- row LayerNorm over C -> bf16 out ---------------------------
__global__ void ln_rows_kernel(const float* __restrict__ x, __nv_bfloat16* __restrict__ xb) {
    __shared__ float rs[256], rq[256];
    int row = blockIdx.x;
    const float4* p = (const float4*)(x + (size_t)row * CDIM);
    float s = 0.f, q = 0.f;
    for (int i = threadIdx.x; i < CDIM / 4; i += 256) {
        float4 v = p[i];
        s += v.x + v.y + v.z + v.w;
        q += v.x * v.x + v.y * v.y + v.z * v.z + v.w * v.w;
    }
    rs[threadIdx.x] = s; rq[threadIdx.x] = q; __syncthreads();
    for (int o = 128; o > 0; o >>= 1) {
        if (threadIdx.x < o) { rs[threadIdx.x] += rs[threadIdx.x + o]; rq[threadIdx.x] += rq[threadIdx.x + o]; }
        __syncthreads();
    }
    float mean = rs[0] / CDIM;
    float var  = rq[0] / CDIM - mean * mean;
    float rstd = rsqrtf(var + EPSV);
    uint32_t* ob = (uint32_t*)(xb + (size_t)row * CDIM);
    for (int i = threadIdx.x; i < CDIM / 4; i += 256) {
        float4 v = p[i];
        ob[i * 2]     = pack_bf16((v.x - mean) * rstd, (v.y - mean) * rstd);
        ob[i * 2 + 1] = pack_bf16((v.z - mean) * rstd, (v.w - mean) * rstd);
    }
}

// ---------------- convert weights to bf16 ------------------------------------
__global__ void convw_kernel(const float* __restrict__ wq, const float* __restrict__ wk,
                             const float* __restrict__ wv, const float* __restrict__ wo,
                             __nv_bfloat16* qb, __nv_bfloat16* kb,
                             __nv_bfloat16* vb, __nv_bfloat16* ob) {
    int i = blockIdx.x * 1024 + threadIdx.x;
    const float* src; __nv_bfloat16* dst;
    if (blockIdx.y == 0)      { src = wq; dst = qb; }
    else if (blockIdx.y == 1) { src = wk; dst = kb; }
    else if (blockIdx.y == 2) { src = wv; dst = vb; }
    else                      { src = wo; dst = ob; }
    dst[i] = __float2bfloat16(src[i]);
}

// ---------------- iv = mlp(cid), cidp = proj(cid) ---------------------------
__global__ void dual_matvec_kernel(const float* __restrict__ w1, const float* __restrict__ b1,
                                   const float* __restrict__ w2, const float* __restrict__ b2,
                                   const float* __restrict__ x,
                                   float* __restrict__ o1, float* __restrict__ o2) {
    __shared__ float sm[128];
    int n = blockIdx.x;
    const float* w; float bv; float* o; int nn;
    if (n < HIDD) { nn = n;        w = w1 + (size_t)nn * DID; bv = b1[nn]; o = o1; }
    else          { nn = n - HIDD; w = w2 + (size_t)nn * DID; bv = b2[nn]; o = o2; }
    float s = 0.f;
    for (int k = threadIdx.x; k < DID; k += 128) s += w[k] * x[k];
    sm[threadIdx.x] = s; __syncthreads();
    for (int off = 64; off > 0; off >>= 1) {
        if (threadIdx.x < off) sm[threadIdx.x] += sm[threadIdx.x + off];
        __syncthreads();
    }
    if (threadIdx.x == 0) o[nn] = sm[0] + bv;
}

// ---------------- bf16 mma GEMM engine (128x128, BT, ldmatrix) ---------------
__device__ __forceinline__ void bf16_gemm_body(
        const __nv_bfloat16* __restrict__ A, const __nv_bfloat16* __restrict__ B,
        const float* __restrict__ bias, float* __restrict__ C,
        int N, int K, int kstart, int nkt, int m0, int n0) {
    __shared__ uint32_t As[2][128][12];   // [row][k-pair], 8 data + 4 pad
    __shared__ uint32_t Bs[2][128][12];

    const int tid  = threadIdx.x;
    const int lane = tid & 31, wid = tid >> 5;
    const int g    = lane >> 2, tig = lane & 3;
    const int wm   = (wid >> 2) * 64;
    const int wn   = (wid & 3) * 32;

    // ldmatrix lane geometry
    const int l7    = lane & 7;
    const int lrow8 = (lane >> 3) & 1;
    const int lcol4 = (lane >> 4) * 4;
    const int quad  = lane >> 3;
    const int brow  = (quad >= 2) ? 8 : 0;
    const int bcol  = (quad & 1) * 4;

    const int fr = tid >> 1, fc = (tid & 1);

    float acc[4][4][4] = {};

    auto fill = [&](int s, int k0) {
        cp16(&As[s][fr][fc * 4], A + (size_t)(m0 + fr) * K + k0 + fc * 8);
        cp16(&Bs[s][fr][fc * 4], B + (size_t)(n0 + fr) * K + k0 + fc * 8);
    };

    fill(0, kstart);
    CP_COMMIT();

    for (int t = 0; t < nkt; t++) {
        const int st = t & 1;
        if (t + 1 < nkt) fill(st ^ 1, kstart + (t + 1) * 16);
        CP_COMMIT();
        CP_WAIT1();
        __syncthreads();

        uint32_t a[4][4], b[4][2];
        #pragma unroll
        for (int mf = 0; mf < 4; mf++)
            ldsm_x4(a[mf][0], a[mf][1], a[mf][2], a[mf][3],
                    saddr(&As[st][wm + mf * 16 + l7 + 8 * lrow8][lcol4]));
        ldsm_x4(b[0][0], b[0][1], b[1][0], b[1][1],
                saddr(&Bs[st][wn + brow + l7][bcol]));
        ldsm_x4(b[2][0], b[2][1], b[3][0], b[3][1],
                saddr(&Bs[st][wn + 16 + brow + l7][bcol]));
        #pragma unroll
        for (int mf = 0; mf < 4; mf++)
            #pragma unroll
            for (int nf = 0; nf < 4; nf++)
                mma_bf16(acc[mf][nf], a[mf][0], a[mf][1], a[mf][2], a[mf][3],
                         b[nf][0], b[nf][1]);
        __syncthreads();
    }

    #pragma unroll
    for (int mf = 0; mf < 4; mf++) {
        #pragma unroll
        for (int nf = 0; nf < 4; nf++) {
            const int r0 = m0 + wm + mf * 16 + g;
            const int c  = n0 + wn + nf * 8 + 2 * tig;
            float2 v0 = make_float2(acc[mf][nf][0], acc[mf][nf][1]);
            float2 v1 = make_float2(acc[mf][nf][2], acc[mf][nf][3]);
            if (bias) {
                float b0 = bias[c], b1 = bias[c + 1];
                v0.x += b0; v0.y += b1; v1.x += b0; v1.y += b1;
            }
            *(float2*)&C[(size_t)r0 * N + c]       = v0;
            *(float2*)&C[(size_t)(r0 + 8) * N + c] = v1;
        }
    }
}

// Fused QKV split-K: grid (1, 32, 12); z = which*4 + split.
__global__ __launch_bounds__(256, 2)
void qkv_mma_kernel(const __nv_bfloat16* __restrict__ A,
                    const __nv_bfloat16* __restrict__ wq, const __nv_bfloat16* __restrict__ wk,
                    const __nv_bfloat16* __restrict__ wv, float* __restrict__ qkvp) {
    const int which = blockIdx.z >> 2;
    const int split = blockIdx.z & 3;
    const __nv_bfloat16* B = (which == 0) ? wq : (which == 1) ? wk : wv;
    float* out = qkvp + (size_t)blockIdx.z * S * HIDD;
    bf16_gemm_body(A, B, nullptr, out, HIDD, CDIM, split * 320, 20,
                   blockIdx.y * 128, blockIdx.x * 128);
}

// WO GEMM: grid (10, 32).
__global__ __launch_bounds__(256, 2)
void wo_mma_kernel(const __nv_bfloat16* __restrict__ A, const __nv_bfloat16* __restrict__ B,
                   const float* __restrict__ bias, float* __restrict__ C) {
    bf16_gemm_body(A, B, bias, C, CDIM, HIDD, 0, 8, blockIdx.y * 128, blockIdx.x * 128);
}

// Reduce QKV partials (+bias) -> bf16 Q/K/V (+ fp32 K). grid (512, 3), 256 thr.
__global__ void reduce_qkv_kernel(const float* __restrict__ qkvp,
                                  const float* __restrict__ bq, const float* __restrict__ bk,
                                  const float* __restrict__ bv,
                                  __nv_bfloat16* __restrict__ Qb, __nv_bfloat16* __restrict__ Kb,
                                  float* __restrict__ Kf, __nv_bfloat16* __restrict__ Vb) {
    const size_t MN = (size_t)S * HIDD;
    const int which = blockIdx.y;
    size_t i = ((size_t)blockIdx.x * 256 + threadIdx.x) * 4;
    const float* base = qkvp + (size_t)which * 4 * MN;
    float4 a = *(const float4*)&base[i];
    float4 b = *(const float4*)&base[MN + i];
    float4 c = *(const float4*)&base[2 * MN + i];
    float4 d = *(const float4*)&base[3 * MN + i];
    const float* bias = (which == 0) ? bq : (which == 1) ? bk : bv;
    float4 bb = *(const float4*)&bias[i & 127];
    float4 r;
    r.x = a.x + b.x + c.x + d.x + bb.x;
    r.y = a.y + b.y + c.y + d.y + bb.y;
    r.z = a.z + b.z + c.z + d.z + bb.z;
    r.w = a.w + b.w + c.w + d.w + bb.w;
    uint2 packed;
    packed.x = pack_bf16(r.x, r.y);
    packed.y = pack_bf16(r.z, r.w);
    if (which == 0)      { *(uint2*)&Qb[i] = packed; }
    else if (which == 1) { *(uint2*)&Kb[i] = packed; *(float4*)&Kf[i] = r; }
    else                 { *(uint2*)&Vb[i] = packed; }
}

// ---------------- V transpose (S,HID) -> (HID,S) bf16 ------------------------
__global__ void vtrans_kernel(const __nv_bfloat16* __restrict__ Vb,
                              __nv_bfloat16* __restrict__ Vtb) {
    __shared__ __nv_bfloat16 tile[32][34];
    int s0 = blockIdx.x * 32, d0 = blockIdx.y * 32;
    #pragma unroll
    for (int i = threadIdx.y; i < 32; i += 8)
        tile[i][threadIdx.x] = Vb[(size_t)(s0 + i) * HIDD + d0 + threadIdx.x];
    __syncthreads();
    #pragma unroll
    for (int i = threadIdx.y; i < 32; i += 8)
        Vtb[(size_t)(d0 + i) * S + s0 + threadIdx.x] = tile[threadIdx.x][i];
}

// ---------------- mask[k] = sigmoid(iv . K[k])  (fp32 K) ---------------------
__global__ void mask_kernel(const float* __restrict__ Kmat, const float* __restrict__ iv,
                            float* __restrict__ mask) {
    __shared__ float sm[128];
    int k = blockIdx.x;
    float v = iv[threadIdx.x] * Kmat[(size_t)k * HIDD + threadIdx.x];
    sm[threadIdx.x] = v; __syncthreads();
    for (int o = 64; o > 0; o >>= 1) {
        if (threadIdx.x < o) sm[threadIdx.x] += sm[threadIdx.x + o];
        __syncthreads();
    }
    if (threadIdx.x == 0) mask[k] = 1.f / (1.f + expf(-sm[0]));
}

// ---------------- flash attention, bf16 mma + ldmatrix -----------------------
// Grid (S/64, 4). Each CTA: 64 q-rows, one KV quarter (1024 keys, 16 tiles of 64).
#define FLASH_SMEM_BYTES (25088 * 4)
__global__ void __launch_bounds__(256, 2)
flash_kernel(const __nv_bfloat16* __restrict__ Qb, const __nv_bfloat16* __restrict__ Kb,
             const __nv_bfloat16* __restrict__ Vtb, const float* __restrict__ maskv,
             float* __restrict__ Opart, float* __restrict__ mpart,
             float* __restrict__ lpart) {
    extern __shared__ uint32_t smu[];
    uint32_t* Qs   = smu;               // 64*68   = 4352
    uint32_t* KsB  = smu + 4352;        // 2*4352  = 8704
    uint32_t* VTsB = smu + 13056;       // 2*4608  = 9216
    uint32_t* Ps   = smu + 22272;       // 64*36   = 2304
    float* msk  = (float*)(smu + 24576);
    float* maxb = (float*)(smu + 24704);
    float* sumb = (float*)(smu + 24832);
    float* m_sm = (float*)(smu + 24960);
    float* l_sm = (float*)(smu + 25024);

    const int tid  = threadIdx.x;
    const int lane = tid & 31, w = tid >> 5;
    const int g    = lane >> 2, tig = lane & 3;
    const int wm   = (w & 3) * 16;
    const int wns  = (w >> 2) * 32;
    const int wno  = (w >> 2) * 64;
    const int wgrp = w >> 2;

    // ldmatrix lane geometry
    const int l7    = lane & 7;
    const int lrow8 = (lane >> 3) & 1;
    const int lcol4 = (lane >> 4) * 4;
    const int quad  = lane >> 3;
    const int brow  = (quad >= 2) ? 8 : 0;
    const int bcol  = (quad & 1) * 4;

    const int qbase  = blockIdx.x * 64;
    const int split  = blockIdx.y;
    const int kstart = split * (S / 4);
    const int NT     = (S / 4) / 64;    // 16

    if (tid < 64) { m_sm[tid] = -1e30f; l_sm[tid] = 0.f; }

    auto fillKV = [&](int st, int kb) {
        #pragma unroll
        for (int i = 0; i < 4; i++) {
            int ci = i * 256 + tid;
            int kr = ci >> 4, kch = (ci & 15);
            cp16(KsB + st * 4352 + kr * 68 + kch * 4,
                 Kb + (size_t)(kb + kr) * HIDD + kch * 8);
            int vr = ci >> 3, vch = (ci & 7);
            cp16(VTsB + st * 4608 + vr * 36 + vch * 4,
                 Vtb + (size_t)vr * S + kb + vch * 8);
        }
        if (tid < 16) cp16(msk + st * 64 + tid * 4, maskv + kb + tid * 4);
    };

    // prologue: Q (own group), then KV stage 0
    #pragma unroll
    for (int i = 0; i < 4; i++) {
        int ci = i * 256 + tid;
        int r = ci >> 4, ch = (ci & 15);
        cp16(Qs + r * 68 + ch * 4, Qb + (size_t)(qbase + r) * HIDD + ch * 8);
    }
    CP_COMMIT();
    fillKV(0, kstart);
    CP_COMMIT();
    asm volatile("cp.async.wait_group 1;\n" ::: "memory");   // Q done; KV0 may be in flight
    __syncthreads();

    // Q fragments -> registers (reused for all 16 KV tiles)
    uint32_t qf[8][4];
    {
        const int qrow = wm + l7 + 8 * lrow8;
        #pragma unroll
        for (int kt = 0; kt < 8; kt++)
            ldsm_x4(qf[kt][0], qf[kt][1], qf[kt][2], qf[kt][3],
                    saddr(&Qs[qrow * 68 + kt * 8 + lcol4]));
    }

    float o_acc[8][4] = {};
    const int row0 = wm + g, row1 = wm + g + 8;

    for (int t = 0; t < NT; t++) {
        const int st = t & 1;
        if (t + 1 < NT) fillKV(st ^ 1, kstart + (t + 1) * 64);
        CP_COMMIT();
        CP_WAIT1();
        __syncthreads();

        const uint32_t* Ks  = KsB + st * 4352;
        const uint32_t* VTs = VTsB + st * 4608;
        const float* mk = msk + st * 64;

        // --- scores = Q . K^T ---
        float s_acc[4][4] = {};
        #pragma unroll
        for (int kt = 0; kt < 8; kt++) {
            uint32_t b[4][2];
            ldsm_x4(b[0][0], b[0][1], b[1][0], b[1][1],
                    saddr(&Ks[(wns + brow + l7) * 68 + kt * 8 + bcol]));
            ldsm_x4(b[2][0], b[2][1], b[3][0], b[3][1],
                    saddr(&Ks[(wns + 16 + brow + l7) * 68 + kt * 8 + bcol]));
            #pragma unroll
            for (int nf = 0; nf < 4; nf++)
                mma_bf16(s_acc[nf], qf[kt][0], qf[kt][1], qf[kt][2], qf[kt][3],
                         b[nf][0], b[nf][1]);
        }

        // --- scale + mask, row max ---
        float rmax0 = -1e30f, rmax1 = -1e30f;
        #pragma unroll
        for (int nf = 0; nf < 4; nf++) {
            const int cc = wns + nf * 8 + 2 * tig;
            const float mk0 = mk[cc] * 0.015625f, mk1 = mk[cc + 1] * 0.015625f;
            s_acc[nf][0] *= mk0; s_acc[nf][1] *= mk1;
            s_acc[nf][2] *= mk0; s_acc[nf][3] *= mk1;
            rmax0 = fmaxf(rmax0, fmaxf(s_acc[nf][0], s_acc[nf][1]));
            rmax1 = fmaxf(rmax1, fmaxf(s_acc[nf][2], s_acc[nf][3]));
        }
        #pragma unroll
        for (int o = 1; o <= 2; o <<= 1) {
            rmax0 = fmaxf(rmax0, __shfl_xor_sync(0xffffffffu, rmax0, o));
            rmax1 = fmaxf(rmax1, __shfl_xor_sync(0xffffffffu, rmax1, o));
        }
        if (tig == 0) { maxb[wgrp * 64 + row0] = rmax0; maxb[wgrp * 64 + row1] = rmax1; }
        __syncthreads();

        // --- online softmax update ---
        const float mp0 = m_sm[row0], mp1 = m_sm[row1];
        const float mn0 = fmaxf(mp0, fmaxf(maxb[row0], maxb[64 + row0]));
        const float mn1 = fmaxf(mp1, fmaxf(maxb[row1], maxb[64 + row1]));
        const float c0f = __expf(mp0 - mn0), c1f = __expf(mp1 - mn1);

        float ps0 = 0.f, ps1 = 0.f;
        #pragma unroll
        for (int nf = 0; nf < 4; nf++) {
            const float p0 = __expf(s_acc[nf][0] - mn0);
            const float p1 = __expf(s_acc[nf][1] - mn0);
            const float p2 = __expf(s_acc[nf][2] - mn1);
            const float p3 = __expf(s_acc[nf][3] - mn1);
            ps0 += p0 + p1; ps1 += p2 + p3;
            const int pc = (wns >> 1) + nf * 4 + tig;
            Ps[row0 * 36 + pc] = pack_bf16(p0, p1);
            Ps[row1 * 36 + pc] = pack_bf16(p2, p3);
        }
        #pragma unroll
        for (int o = 1; o <= 2; o <<= 1) {
            ps0 += __shfl_xor_sync(0xffffffffu, ps0, o);
            ps1 += __shfl_xor_sync(0xffffffffu, ps1, o);
        }
        if (tig == 0) { sumb[wgrp * 64 + row0] = ps0; sumb[wgrp * 64 + row1] = ps1; }

        #pragma unroll
        for (int nf = 0; nf < 8; nf++) {
            o_acc[nf][0] *= c0f; o_acc[nf][1] *= c0f;
            o_acc[nf][2] *= c1f; o_acc[nf][3] *= c1f;
        }
        __syncthreads();

        if (w < 4 && tig == 0) {
            l_sm[row0] = l_sm[row0] * c0f + sumb[row0] + sumb[64 + row0];
            m_sm[row0] = mn0;
            l_sm[row1] = l_sm[row1] * c1f + sumb[row1] + sumb[64 + row1];
            m_sm[row1] = mn1;
        }

        // --- O += P . V ---
        const int prow = wm + l7 + 8 * lrow8;
        #pragma unroll
        for (int kt = 0; kt < 4; kt++) {
            uint32_t pa[4];
            ldsm_x4(pa[0], pa[1], pa[2], pa[3],
                    saddr(&Ps[prow * 36 + kt * 8 + lcol4]));
            #pragma unroll
            for (int np = 0; np < 4; np++) {
                uint32_t b0, b1, b2, b3;
                ldsm_x4(b0, b1, b2, b3,
                        saddr(&VTs[(wno + np * 16 + brow + l7) * 36 + kt * 8 + bcol]));
                mma_bf16(o_acc[2 * np],     pa[0], pa[1], pa[2], pa[3], b0, b1);
                mma_bf16(o_acc[2 * np + 1], pa[0], pa[1], pa[2], pa[3], b2, b3);
            }
        }
        __syncthreads();
    }

    // epilogue: unnormalized partials
    float* Ob = Opart + ((size_t)split * S + qbase) * HIDD;
    #pragma unroll
    for (int nf = 0; nf < 8; nf++) {
        const int cc = wno + nf * 8 + 2 * tig;
        *(float2*)&Ob[(size_t)row0 * HIDD + cc] = make_float2(o_acc[nf][0], o_acc[nf][1]);
        *(float2*)&Ob[(size_t)row1 * HIDD + cc] = make_float2(o_acc[nf][2], o_acc[nf][3]);
    }
    if (w < 4 && tig == 0) {
        mpart[split * S + qbase + row0] = m_sm[row0];
        lpart[split * S + qbase + row0] = l_sm[row0];
        mpart[split * S + qbase + row1] = m_sm[row1];
        lpart[split * S + qbase + row1] = l_sm[row1];
    }
}

// ---------------- combine the 4 KV-split partials -> bf16 av -----------------
__global__ void combine_kernel(const float* __restrict__ Opart,
                               const float* __restrict__ mpart,
                               const float* __restrict__ lpart,
                               __nv_bfloat16* __restrict__ avb) {
    const int row = blockIdx.x, col = threadIdx.x;
    float M = -1e30f;
    #pragma unroll
    for (int z = 0; z < 4; z++) M = fmaxf(M, mpart[z * S + row]);
    float denom = 0.f, v = 0.f;
    #pragma unroll
    for (int z = 0; z < 4; z++) {
        const float e = __expf(mpart[z * S + row] - M);
        denom += e * lpart[z * S + row];
        v     += e * Opart[((size_t)z * S + row) * HIDD + col];
    }
    avb[(size_t)row * HIDD + col] = __float2bfloat16(v / denom);
}

// ---------------- decoupling epilogue + per-row partial stats ----------------
__global__ void epilogue_kernel(float* __restrict__ att, const float* __restrict__ cidp,
                                double* __restrict__ psum, double* __restrict__ psq) {
    __shared__ float red[256], red2[256];
    int s = blockIdx.x;
    float* row = att + (size_t)s * CDIM;
    float dot = 0.f;
    for (int c = threadIdx.x; c < CDIM; c += 256) dot += row[c] * cidp[c];
    red[threadIdx.x] = dot; __syncthreads();
    for (int o = 128; o > 0; o >>= 1) {
        if (threadIdx.x < o) red[threadIdx.x] += red[threadIdx.x + o];
        __syncthreads();
    }
    float w = 1.f / (1.f + expf(-red[0]));
    __syncthreads();
    float ls = 0.f, lq = 0.f;
    for (int c = threadIdx.x; c < CDIM; c += 256) {
        float v = row[c] - w * cidp[c];
        row[c] = v;
        ls += v; lq += v * v;
    }
    red[threadIdx.x] = ls; red2[threadIdx.x] = lq; __syncthreads();
    for (int o = 128; o > 0; o >>= 1) {
        if (threadIdx.x < o) { red[threadIdx.x] += red[threadIdx.x + o]; red2[threadIdx.x] += red2[threadIdx.x + o]; }
        __syncthreads();
    }
    if (threadIdx.x == 0) { psum[s] = (double)red[0]; psq[s] = (double)red2[0]; }
}

// ---------------- global LN stats (deterministic, single block) --------------
__global__ void stats_kernel(const double* __restrict__ psum, const double* __restrict__ psq) {
    __shared__ double rs[1024], rq[1024];
    double s = 0.0, q = 0.0;
    for (int i = threadIdx.x; i < S; i += 1024) { s += psum[i]; q += psq[i]; }
    rs[threadIdx.x] = s; rq[threadIdx.x] = q; __syncthreads();
    for (int o = 512; o > 0; o >>= 1) {
        if (threadIdx.x < o) { rs[threadIdx.x] += rs[threadIdx.x + o]; rq[threadIdx.x] += rq[threadIdx.x + o]; }
        __syncthreads();
    }
    if (threadIdx.x == 0) {
        double n = (double)S * (double)CDIM;
        double mean = rs[0] / n;
        double var  = rq[0] / n - mean * mean;
        g_mean_f = (float)mean;
        g_rstd_f = (float)rsqrt(var + 1e-5);
    }
}

// ---------------- normalize + transpose back (S,C) -> (C,S) ------------------
__global__ void out_transpose_kernel(const float* __restrict__ af, float* __restrict__ out) {
    __shared__ float tile[32][33];
    float mean = g_mean_f, rstd = g_rstd_f;
    int c0 = blockIdx.x * 32, s0 = blockIdx.y * 32;
    #pragma unroll
    for (int i = threadIdx.y; i < 32; i += 8)
        tile[i][threadIdx.x] = af[(size_t)(s0 + i) * CDIM + c0 + threadIdx.x];
    __syncthreads();
    #pragma unroll
    for (int i = threadIdx.y; i < 32; i += 8)
        out[(size_t)(c0 + i) * S + s0 + threadIdx.x] = (tile[threadIdx.x][i] - mean) * rstd;
}

// ---------------- launch ------------------------------------------------------
extern "C" void kernel_launch(void* const* d_in, const int* in_sizes, int n_in,
                              void* d_out, int out_size) {
    const float* z      = (const float*)d_in[0];
    const float* cid    = (const float*)d_in[1];
    const float* mlp_w  = (const float*)d_in[2];
    const float* mlp_b  = (const float*)d_in[3];
    const float* proj_w = (const float*)d_in[4];
    const float* proj_b = (const float*)d_in[5];
    const float* wq_w   = (const float*)d_in[6];
    const float* wq_b   = (const float*)d_in[7];
    const float* wk_w   = (const float*)d_in[8];
    const float* wk_b   = (const float*)d_in[9];
    const float* wv_w   = (const float*)d_in[10];
    const float* wv_b   = (const float*)d_in[11];
    const float* wo_w   = (const float*)d_in[12];
    const float* wo_b   = (const float*)d_in[13];
    float* out = (float*)d_out;

    float *zt, *Kf, *iv, *cidp, *maskv, *qkvp, *Opart, *mpart, *lpart, *att;
    __nv_bfloat16 *ztb, *wqb, *wkb, *wvb, *wob, *Qb, *Kb, *Vb, *Vtb, *avb;
    double *psum, *psq;
    cudaGetSymbolAddress((void**)&zt,    g_zt);
    cudaGetSymbolAddress((void**)&ztb,   g_ztb);
    cudaGetSymbolAddress((void**)&wqb,   g_wqb);
    cudaGetSymbolAddress((void**)&wkb,   g_wkb);
    cudaGetSymbolAddress((void**)&wvb,   g_wvb);
    cudaGetSymbolAddress((void**)&wob,   g_wob);
    cudaGetSymbolAddress((void**)&Kf,    g_Km);
    cudaGetSymbolAddress((void**)&Qb,    g_Qb);
    cudaGetSymbolAddress((void**)&Kb,    g_Kb);
    cudaGetSymbolAddress((void**)&Vb,    g_Vb);
    cudaGetSymbolAddress((void**)&Vtb,   g_Vtb);
    cudaGetSymbolAddress((void**)&iv,    g_iv);
    cudaGetSymbolAddress((void**)&cidp,  g_cidp);
    cudaGetSymbolAddress((void**)&maskv, g_maskv);
    cudaGetSymbolAddress((void**)&qkvp,  g_qkvp);
    cudaGetSymbolAddress((void**)&Opart, g_Opart);
    cudaGetSymbolAddress((void**)&mpart, g_mpart);
    cudaGetSymbolAddress((void**)&lpart, g_lpart);
    cudaGetSymbolAddress((void**)&avb,   g_avb);
    cudaGetSymbolAddress((void**)&att,   g_att);
    cudaGetSymbolAddress((void**)&psum,  g_psum);
    cudaGetSymbolAddress((void**)&psq,   g_psq);

    static int s_attr_set = 0;
    if (!s_attr_set) {
        cudaFuncSetAttribute(flash_kernel, cudaFuncAttributeMaxDynamicSharedMemorySize,
                             FLASH_SMEM_BYTES);
        s_attr_set = 1;
    }

    dim3 t32x8(32, 8);

    transpose_zt_kernel<<<dim3(S / 32, CDIM / 32), t32x8>>>(z, zt);
    ln_rows_kernel<<<S, 256>>>(zt, ztb);
    convw_kernel<<<dim3(160, 4), 1024>>>(wq_w, wk_w, wv_w, wo_w, wqb, wkb, wvb, wob);
    dual_matvec_kernel<<<HIDD + CDIM, 128>>>(mlp_w, mlp_b, proj_w, proj_b, cid, iv, cidp);
    qkv_mma_kernel<<<dim3(1, S / 128, 12), 256>>>(ztb, wqb, wkb, wvb, qkvp);
    reduce_qkv_kernel<<<dim3(512, 3), 256>>>(qkvp, wq_b, wk_b, wv_b, Qb, Kb, Kf, Vb);
    vtrans_kernel<<<dim3(S / 32, HIDD / 32), t32x8>>>(Vb, Vtb);
    mask_kernel<<<S, 128>>>(Kf, iv, maskv);
    flash_kernel<<<dim3(S / 64, 4), 256, FLASH_SMEM_BYTES>>>(
        Qb, Kb, Vtb, maskv, Opart, mpart, lpart);
    combine_kernel<<<S, HIDD>>>(Opart, mpart, lpart, avb);
    wo_mma_kernel<<<dim3(CDIM / 128, S / 128), 256>>>(avb, wob, wo_b, att);
    epilogue_kernel<<<S, 256>>>(att, cidp, psum, psq);
    stats_kernel<<<1, 1024>>>(psum, psq);
    out_transpose_kernel<<<dim3(CDIM / 32, S / 32), t32x8>>>(att, out);
}